// round 1
// baseline (speedup 1.0000x reference)
#include <cuda_runtime.h>
#include <math_constants.h>

// Problem constants
#define BB 4
#define CC 256
#define NN 4096
#define NG 8
#define CPG 32            // channels per group
#define EPSV 1e-5f
#define ATTN_SCALE 0.0625f // 1/sqrt(256)

// ---------------- static scratch (allocation-free) ----------------
__device__ float g_h[BB * CC * NN];            // 16 MB  groupnorm output
__device__ float g_q[BB * CC * NN];            // 16 MB
__device__ float g_k[BB * CC * NN];            // 16 MB
__device__ float g_v[BB * CC * NN];            // 16 MB
__device__ float g_o[BB * CC * NN];            // 16 MB  attn @ V result
__device__ float g_S[(size_t)BB * NN * NN];    // 256 MB attention matrix

// ---------------- GroupNorm ----------------
// One block per (b, g). Elements of a group are contiguous: CPG*NN floats.
__global__ void gn_kernel(const float* __restrict__ x,
                          const float* __restrict__ sc,
                          const float* __restrict__ bi) {
    const int bg = blockIdx.x;
    const int b = bg >> 3, g = bg & 7;
    const size_t base = ((size_t)b * CC + (size_t)g * CPG) * (size_t)NN;
    const float* xp = x + base;
    const int M = CPG * NN; // 131072

    float s = 0.f, ss = 0.f;
    for (int i = threadIdx.x; i < M; i += blockDim.x) {
        float v = xp[i];
        s += v; ss += v * v;
    }
    __shared__ float rs[1024];
    __shared__ float rq[1024];
    rs[threadIdx.x] = s; rq[threadIdx.x] = ss;
    __syncthreads();
    for (int st = 512; st > 0; st >>= 1) {
        if (threadIdx.x < st) {
            rs[threadIdx.x] += rs[threadIdx.x + st];
            rq[threadIdx.x] += rq[threadIdx.x + st];
        }
        __syncthreads();
    }
    const float mean = rs[0] / (float)M;
    const float var  = rq[0] / (float)M - mean * mean;
    const float inv  = rsqrtf(var + EPSV);

    for (int i = threadIdx.x; i < M; i += blockDim.x) {
        const int c = g * CPG + (i >> 12);     // i / NN
        g_h[base + i] = (xp[i] - mean) * inv * sc[c] + bi[c];
    }
}

// ---------------- 1x1 conv projection: Out[b,o,n] = sum_c W[o,c] * Hin[b,c,n] + bias[o] (+res) ----------------
// grid: (NN/64, CC/64, BB), block: 256
__global__ void proj_kernel(const float* __restrict__ W,
                            const float* __restrict__ bias,
                            const float* __restrict__ Hin,
                            const float* __restrict__ res,
                            float* __restrict__ Out) {
    __shared__ float As[16][65]; // As[k][o]  from W (transposed store)
    __shared__ float Bs[16][65]; // Bs[k][n]  from H
    const int b  = blockIdx.z;
    const int n0 = blockIdx.x * 64;
    const int o0 = blockIdx.y * 64;
    const float* Hb = Hin + (size_t)b * CC * NN;
    const int tid = threadIdx.x;
    const int tx = tid & 15, ty = tid >> 4;

    float acc[4][4] = {};
    for (int c0 = 0; c0 < CC; c0 += 16) {
        #pragma unroll
        for (int l = 0; l < 4; l++) {
            int idx = tid + l * 256;
            int r = idx >> 4, kk = idx & 15;
            As[kk][r] = W[(o0 + r) * CC + c0 + kk];
        }
        #pragma unroll
        for (int l = 0; l < 4; l++) {
            int idx = tid + l * 256;
            int kk = idx >> 6, j = idx & 63;
            Bs[kk][j] = Hb[(size_t)(c0 + kk) * NN + n0 + j];
        }
        __syncthreads();
        #pragma unroll
        for (int kk = 0; kk < 16; kk++) {
            float a[4], bvv[4];
            #pragma unroll
            for (int i = 0; i < 4; i++) a[i] = As[kk][ty + i * 16];
            #pragma unroll
            for (int j = 0; j < 4; j++) bvv[j] = Bs[kk][tx + j * 16];
            #pragma unroll
            for (int i = 0; i < 4; i++)
                #pragma unroll
                for (int j = 0; j < 4; j++)
                    acc[i][j] += a[i] * bvv[j];
        }
        __syncthreads();
    }
    #pragma unroll
    for (int i = 0; i < 4; i++) {
        const int o = o0 + ty + i * 16;
        const float bo_ = bias[o];
        #pragma unroll
        for (int j = 0; j < 4; j++) {
            const int n = n0 + tx + j * 16;
            const size_t oi = (size_t)b * CC * NN + (size_t)o * NN + n;
            float v = acc[i][j] + bo_;
            if (res) v += res[oi];
            Out[oi] = v;
        }
    }
}

// ---------------- scores: S[b,n,m] = scale * sum_c q[b,c,n] * k[b,c,m] ----------------
// grid: (NN/64 (m), NN/64 (n), BB), block: 256
__global__ void scores_kernel() {
    __shared__ float As[16][65]; // As[k][n] from q
    __shared__ float Bs[16][65]; // Bs[k][m] from k
    const int b  = blockIdx.z;
    const int m0 = blockIdx.x * 64;
    const int n0 = blockIdx.y * 64;
    const float* qb = g_q + (size_t)b * CC * NN;
    const float* kb = g_k + (size_t)b * CC * NN;
    const int tid = threadIdx.x;
    const int tx = tid & 15, ty = tid >> 4;

    float acc[4][4] = {};
    for (int c0 = 0; c0 < CC; c0 += 16) {
        #pragma unroll
        for (int l = 0; l < 4; l++) {
            int idx = tid + l * 256;
            int kk = idx >> 6, j = idx & 63;
            As[kk][j] = qb[(size_t)(c0 + kk) * NN + n0 + j];
            Bs[kk][j] = kb[(size_t)(c0 + kk) * NN + m0 + j];
        }
        __syncthreads();
        #pragma unroll
        for (int kk = 0; kk < 16; kk++) {
            float a[4], bvv[4];
            #pragma unroll
            for (int i = 0; i < 4; i++) a[i] = As[kk][ty + i * 16];
            #pragma unroll
            for (int j = 0; j < 4; j++) bvv[j] = Bs[kk][tx + j * 16];
            #pragma unroll
            for (int i = 0; i < 4; i++)
                #pragma unroll
                for (int j = 0; j < 4; j++)
                    acc[i][j] += a[i] * bvv[j];
        }
        __syncthreads();
    }
    float* Sb = g_S + (size_t)b * NN * NN;
    #pragma unroll
    for (int i = 0; i < 4; i++) {
        const int n = n0 + ty + i * 16;
        #pragma unroll
        for (int j = 0; j < 4; j++) {
            const int m = m0 + tx + j * 16;
            Sb[(size_t)n * NN + m] = acc[i][j] * ATTN_SCALE;
        }
    }
}

// ---------------- row softmax over m (last axis). One block (256 thr) per row. ----------------
__global__ void softmax_kernel() {
    const size_t row = blockIdx.x; // b*NN + n
    float* p = g_S + row * (size_t)NN;
    const int tid = threadIdx.x;

    float v[16];
    float mx = -CUDART_INF_F;
    #pragma unroll
    for (int l = 0; l < 16; l++) {
        v[l] = p[tid + l * 256];
        mx = fmaxf(mx, v[l]);
    }
    __shared__ float red[256];
    red[tid] = mx; __syncthreads();
    for (int st = 128; st > 0; st >>= 1) {
        if (tid < st) red[tid] = fmaxf(red[tid], red[tid + st]);
        __syncthreads();
    }
    mx = red[0];
    __syncthreads();

    float sum = 0.f;
    #pragma unroll
    for (int l = 0; l < 16; l++) {
        v[l] = __expf(v[l] - mx);
        sum += v[l];
    }
    red[tid] = sum; __syncthreads();
    for (int st = 128; st > 0; st >>= 1) {
        if (tid < st) red[tid] += red[tid + st];
        __syncthreads();
    }
    const float inv = 1.f / red[0];
    #pragma unroll
    for (int l = 0; l < 16; l++)
        p[tid + l * 256] = v[l] * inv;
}

// ---------------- AV: o[b,c,n] = sum_m v[b,c,m] * P[b,n,m] ----------------
// grid: (NN/64 (n), CC/64 (c), BB), block: 256
__global__ void av_kernel() {
    __shared__ float As[16][65]; // As[m][c] from v (transposed store)
    __shared__ float Bs[16][65]; // Bs[m][n] from P (transposed store)
    const int b  = blockIdx.z;
    const int n0 = blockIdx.x * 64;
    const int c0 = blockIdx.y * 64;
    const float* vb = g_v + (size_t)b * CC * NN;
    const float* Pb = g_S + (size_t)b * NN * NN;
    const int tid = threadIdx.x;
    const int tx = tid & 15, ty = tid >> 4;

    float acc[4][4] = {};
    for (int m0 = 0; m0 < NN; m0 += 16) {
        #pragma unroll
        for (int l = 0; l < 4; l++) {
            int idx = tid + l * 256;
            int r = idx >> 4, kk = idx & 15;
            As[kk][r] = vb[(size_t)(c0 + r) * NN + m0 + kk];
            Bs[kk][r] = Pb[(size_t)(n0 + r) * NN + m0 + kk];
        }
        __syncthreads();
        #pragma unroll
        for (int kk = 0; kk < 16; kk++) {
            float a[4], bvv[4];
            #pragma unroll
            for (int i = 0; i < 4; i++) a[i] = As[kk][ty + i * 16];
            #pragma unroll
            for (int j = 0; j < 4; j++) bvv[j] = Bs[kk][tx + j * 16];
            #pragma unroll
            for (int i = 0; i < 4; i++)
                #pragma unroll
                for (int j = 0; j < 4; j++)
                    acc[i][j] += a[i] * bvv[j];
        }
        __syncthreads();
    }
    #pragma unroll
    for (int i = 0; i < 4; i++) {
        const int c = c0 + ty + i * 16;
        #pragma unroll
        for (int j = 0; j < 4; j++) {
            const int n = n0 + tx + j * 16;
            g_o[(size_t)b * CC * NN + (size_t)c * NN + n] = acc[i][j];
        }
    }
}

// ---------------- launch ----------------
extern "C" void kernel_launch(void* const* d_in, const int* in_sizes, int n_in,
                              void* d_out, int out_size) {
    const float* input = (const float*)d_in[0];
    const float* gns   = (const float*)d_in[1];
    const float* gnb   = (const float*)d_in[2];
    const float* Wq    = (const float*)d_in[3];
    const float* bq    = (const float*)d_in[4];
    const float* Wk    = (const float*)d_in[5];
    const float* bk    = (const float*)d_in[6];
    const float* Wv    = (const float*)d_in[7];
    const float* bv    = (const float*)d_in[8];
    const float* Wo    = (const float*)d_in[9];
    const float* bo    = (const float*)d_in[10];
    float* out = (float*)d_out;

    float *ph, *pq, *pk, *pv, *po;
    cudaGetSymbolAddress((void**)&ph, g_h);
    cudaGetSymbolAddress((void**)&pq, g_q);
    cudaGetSymbolAddress((void**)&pk, g_k);
    cudaGetSymbolAddress((void**)&pv, g_v);
    cudaGetSymbolAddress((void**)&po, g_o);

    // 1) GroupNorm
    gn_kernel<<<BB * NG, 1024>>>(input, gns, gnb);

    // 2) Q, K, V projections
    dim3 gproj(NN / 64, CC / 64, BB);
    proj_kernel<<<gproj, 256>>>(Wq, bq, ph, nullptr, pq);
    proj_kernel<<<gproj, 256>>>(Wk, bk, ph, nullptr, pk);
    proj_kernel<<<gproj, 256>>>(Wv, bv, ph, nullptr, pv);

    // 3) scores
    dim3 gsc(NN / 64, NN / 64, BB);
    scores_kernel<<<gsc, 256>>>();

    // 4) softmax over rows
    softmax_kernel<<<BB * NN, 256>>>();

    // 5) P @ V
    dim3 gav(NN / 64, CC / 64, BB);
    av_kernel<<<gav, 256>>>();

    // 6) output projection + residual
    proj_kernel<<<gproj, 256>>>(Wo, bo, po, input, out);
}

// round 3
// speedup vs baseline: 1.4180x; 1.4180x over previous
#include <cuda_runtime.h>
#include <math_constants.h>

// Problem constants
#define BB 4
#define CC 256
#define NN 4096
#define NG 8
#define CPG 32
#define EPSV 1e-5f
#define ATTN_SCALE 0.0625f  // 1/sqrt(256)

// GEMM tiling
#define TS 128      // output tile (M and N)
#define KT 16       // K tile
#define PAD 132     // padded smem row (132*4B = 528B, 16B-aligned rows)

// ---------------- static scratch (allocation-free) ----------------
__device__ float g_h[BB * CC * NN];            // 16 MB  groupnorm output
__device__ float g_q[BB * CC * NN];
__device__ float g_k[BB * CC * NN];
__device__ float g_v[BB * CC * NN];
__device__ float g_o[BB * CC * NN];
__device__ float g_S[(size_t)BB * NN * NN];    // 256 MB attention matrix

// ---------------- GroupNorm ----------------
__global__ void gn_kernel(const float* __restrict__ x,
                          const float* __restrict__ sc,
                          const float* __restrict__ bi) {
    const int bg = blockIdx.x;
    const int b = bg >> 3, g = bg & 7;
    const size_t base = ((size_t)b * CC + (size_t)g * CPG) * (size_t)NN;
    const float* xp = x + base;
    const int M4 = (CPG * NN) / 4;   // float4 count = 32768

    float s = 0.f, ss = 0.f;
    for (int i = threadIdx.x; i < M4; i += blockDim.x) {
        float4 v = ((const float4*)xp)[i];
        s += v.x + v.y + v.z + v.w;
        ss += v.x * v.x + v.y * v.y + v.z * v.z + v.w * v.w;
    }
    __shared__ float rs[1024];
    __shared__ float rq[1024];
    rs[threadIdx.x] = s; rq[threadIdx.x] = ss;
    __syncthreads();
    for (int st = 512; st > 0; st >>= 1) {
        if (threadIdx.x < st) {
            rs[threadIdx.x] += rs[threadIdx.x + st];
            rq[threadIdx.x] += rq[threadIdx.x + st];
        }
        __syncthreads();
    }
    const float Mf = (float)(CPG * NN);
    const float mean = rs[0] / Mf;
    const float var  = rq[0] / Mf - mean * mean;
    const float inv  = rsqrtf(var + EPSV);

    float4* outp = (float4*)(g_h + base);
    for (int i = threadIdx.x; i < M4; i += blockDim.x) {
        const int c = g * CPG + (i >> 10);    // (i*4)/NN
        const float a = inv * sc[c];
        const float d = bi[c] - mean * a;
        float4 v = ((const float4*)xp)[i];
        v.x = v.x * a + d; v.y = v.y * a + d; v.z = v.z * a + d; v.w = v.w * a + d;
        outp[i] = v;
    }
}

// ---------------- 1x1 conv projection ----------------
// Out[b,o,n] = sum_c W[o,c] * Hin[b,c,n] + bias[o] (+res)
// grid: (NN/128, CC/128, BB), block 256
__global__ __launch_bounds__(256, 2)
void proj_kernel(const float* __restrict__ W,
                 const float* __restrict__ bias,
                 const float* __restrict__ Hin,
                 const float* __restrict__ res,
                 float* __restrict__ Out) {
    __shared__ float As[KT][PAD];   // As[c][o]  (W transposed)
    __shared__ float Bs[KT][PAD];   // Bs[c][n]
    const int b  = blockIdx.z;
    const int n0 = blockIdx.x * TS;
    const int o0 = blockIdx.y * TS;
    const float* Hb = Hin + (size_t)b * CC * NN;
    const int tid = threadIdx.x;
    const int tx = tid & 15, ty = tid >> 4;

    float acc[8][8] = {};
    for (int c0 = 0; c0 < CC; c0 += KT) {
        #pragma unroll
        for (int l = 0; l < 2; l++) {
            int idx = tid + l * 256;
            // W: transpose load (k along c, contiguous)
            int r = idx >> 2, kq = (idx & 3) * 4;
            float4 t = *(const float4*)&W[(size_t)(o0 + r) * CC + c0 + kq];
            As[kq + 0][r] = t.x; As[kq + 1][r] = t.y;
            As[kq + 2][r] = t.z; As[kq + 3][r] = t.w;
            // H: direct load
            int kk = idx >> 5, n4 = (idx & 31) * 4;
            *(float4*)&Bs[kk][n4] = *(const float4*)&Hb[(size_t)(c0 + kk) * NN + n0 + n4];
        }
        __syncthreads();
        #pragma unroll
        for (int kk = 0; kk < KT; kk++) {
            float a[8], bb[8];
            *(float4*)(a)     = *(float4*)&As[kk][ty * 8];
            *(float4*)(a + 4) = *(float4*)&As[kk][ty * 8 + 4];
            *(float4*)(bb)     = *(float4*)&Bs[kk][tx * 8];
            *(float4*)(bb + 4) = *(float4*)&Bs[kk][tx * 8 + 4];
            #pragma unroll
            for (int i = 0; i < 8; i++)
                #pragma unroll
                for (int j = 0; j < 8; j++)
                    acc[i][j] += a[i] * bb[j];
        }
        __syncthreads();
    }
    #pragma unroll
    for (int i = 0; i < 8; i++) {
        const int o = o0 + ty * 8 + i;
        const float bo_ = bias[o];
        const size_t ro = (size_t)b * CC * NN + (size_t)o * NN + n0 + tx * 8;
        float4 v0, v1;
        v0.x = acc[i][0] + bo_; v0.y = acc[i][1] + bo_;
        v0.z = acc[i][2] + bo_; v0.w = acc[i][3] + bo_;
        v1.x = acc[i][4] + bo_; v1.y = acc[i][5] + bo_;
        v1.z = acc[i][6] + bo_; v1.w = acc[i][7] + bo_;
        if (res) {
            float4 r0 = *(const float4*)&res[ro];
            float4 r1 = *(const float4*)&res[ro + 4];
            v0.x += r0.x; v0.y += r0.y; v0.z += r0.z; v0.w += r0.w;
            v1.x += r1.x; v1.y += r1.y; v1.z += r1.z; v1.w += r1.w;
        }
        *(float4*)&Out[ro]     = v0;
        *(float4*)&Out[ro + 4] = v1;
    }
}

// ---------------- scores: S[b,n,m] = scale * sum_c q[b,c,n] k[b,c,m] ----------------
// grid: (NN/128 (m), NN/128 (n), BB), block 256
__global__ __launch_bounds__(256, 2)
void scores_kernel() {
    __shared__ float As[KT][PAD];   // As[c][n] from q
    __shared__ float Bs[KT][PAD];   // Bs[c][m] from k
    const int b  = blockIdx.z;
    const int m0 = blockIdx.x * TS;
    const int n0 = blockIdx.y * TS;
    const float* qb = g_q + (size_t)b * CC * NN;
    const float* kb = g_k + (size_t)b * CC * NN;
    const int tid = threadIdx.x;
    const int tx = tid & 15, ty = tid >> 4;

    float acc[8][8] = {};
    for (int c0 = 0; c0 < CC; c0 += KT) {
        #pragma unroll
        for (int l = 0; l < 2; l++) {
            int idx = tid + l * 256;
            int kk = idx >> 5, n4 = (idx & 31) * 4;
            *(float4*)&As[kk][n4] = *(const float4*)&qb[(size_t)(c0 + kk) * NN + n0 + n4];
            *(float4*)&Bs[kk][n4] = *(const float4*)&kb[(size_t)(c0 + kk) * NN + m0 + n4];
        }
        __syncthreads();
        #pragma unroll
        for (int kk = 0; kk < KT; kk++) {
            float a[8], bb[8];
            *(float4*)(a)     = *(float4*)&As[kk][ty * 8];
            *(float4*)(a + 4) = *(float4*)&As[kk][ty * 8 + 4];
            *(float4*)(bb)     = *(float4*)&Bs[kk][tx * 8];
            *(float4*)(bb + 4) = *(float4*)&Bs[kk][tx * 8 + 4];
            #pragma unroll
            for (int i = 0; i < 8; i++)
                #pragma unroll
                for (int j = 0; j < 8; j++)
                    acc[i][j] += a[i] * bb[j];
        }
        __syncthreads();
    }
    float* Sb = g_S + (size_t)b * NN * NN;
    #pragma unroll
    for (int i = 0; i < 8; i++) {
        const size_t ro = (size_t)(n0 + ty * 8 + i) * NN + m0 + tx * 8;
        float4 v0, v1;
        v0.x = acc[i][0] * ATTN_SCALE; v0.y = acc[i][1] * ATTN_SCALE;
        v0.z = acc[i][2] * ATTN_SCALE; v0.w = acc[i][3] * ATTN_SCALE;
        v1.x = acc[i][4] * ATTN_SCALE; v1.y = acc[i][5] * ATTN_SCALE;
        v1.z = acc[i][6] * ATTN_SCALE; v1.w = acc[i][7] * ATTN_SCALE;
        *(float4*)&Sb[ro]     = v0;
        *(float4*)&Sb[ro + 4] = v1;
    }
}

// ---------------- row softmax over m. One block (256 thr) per row. ----------------
__global__ void softmax_kernel() {
    const size_t row = blockIdx.x;  // b*NN + n
    float* p = g_S + row * (size_t)NN;
    const int tid = threadIdx.x;

    float4 v[4];
    float mx = -CUDART_INF_F;
    #pragma unroll
    for (int l = 0; l < 4; l++) {
        v[l] = ((const float4*)p)[tid + l * 256];
        mx = fmaxf(mx, fmaxf(fmaxf(v[l].x, v[l].y), fmaxf(v[l].z, v[l].w)));
    }
    __shared__ float red[256];
    red[tid] = mx; __syncthreads();
    for (int st = 128; st > 0; st >>= 1) {
        if (tid < st) red[tid] = fmaxf(red[tid], red[tid + st]);
        __syncthreads();
    }
    mx = red[0];
    __syncthreads();

    float sum = 0.f;
    #pragma unroll
    for (int l = 0; l < 4; l++) {
        v[l].x = __expf(v[l].x - mx); v[l].y = __expf(v[l].y - mx);
        v[l].z = __expf(v[l].z - mx); v[l].w = __expf(v[l].w - mx);
        sum += v[l].x + v[l].y + v[l].z + v[l].w;
    }
    red[tid] = sum; __syncthreads();
    for (int st = 128; st > 0; st >>= 1) {
        if (tid < st) red[tid] += red[tid + st];
        __syncthreads();
    }
    const float inv = 1.f / red[0];
    #pragma unroll
    for (int l = 0; l < 4; l++) {
        v[l].x *= inv; v[l].y *= inv; v[l].z *= inv; v[l].w *= inv;
        ((float4*)p)[tid + l * 256] = v[l];
    }
}

// ---------------- AV: o[b,c,n] = sum_m v[b,c,m] * P[b,n,m] ----------------
// grid: (NN/128 (n), CC/128 (c), BB), block 256
__global__ __launch_bounds__(256, 2)
void av_kernel() {
    __shared__ float As[KT][PAD];   // As[m][c] from v (transposed)
    __shared__ float Bs[KT][PAD];   // Bs[m][n] from P (transposed)
    const int b  = blockIdx.z;
    const int n0 = blockIdx.x * TS;
    const int c0 = blockIdx.y * TS;
    const float* vb = g_v + (size_t)b * CC * NN;
    const float* Pb = g_S + (size_t)b * NN * NN;
    const int tid = threadIdx.x;
    const int tx = tid & 15, ty = tid >> 4;

    float acc[8][8] = {};
    for (int m0 = 0; m0 < NN; m0 += KT) {
        #pragma unroll
        for (int l = 0; l < 2; l++) {
            int idx = tid + l * 256;
            int r = idx >> 2, kq = (idx & 3) * 4;
            float4 t = *(const float4*)&vb[(size_t)(c0 + r) * NN + m0 + kq];
            As[kq + 0][r] = t.x; As[kq + 1][r] = t.y;
            As[kq + 2][r] = t.z; As[kq + 3][r] = t.w;
            float4 u = *(const float4*)&Pb[(size_t)(n0 + r) * NN + m0 + kq];
            Bs[kq + 0][r] = u.x; Bs[kq + 1][r] = u.y;
            Bs[kq + 2][r] = u.z; Bs[kq + 3][r] = u.w;
        }
        __syncthreads();
        #pragma unroll
        for (int kk = 0; kk < KT; kk++) {
            float a[8], bb[8];
            *(float4*)(a)     = *(float4*)&As[kk][ty * 8];
            *(float4*)(a + 4) = *(float4*)&As[kk][ty * 8 + 4];
            *(float4*)(bb)     = *(float4*)&Bs[kk][tx * 8];
            *(float4*)(bb + 4) = *(float4*)&Bs[kk][tx * 8 + 4];
            #pragma unroll
            for (int i = 0; i < 8; i++)
                #pragma unroll
                for (int j = 0; j < 8; j++)
                    acc[i][j] += a[i] * bb[j];
        }
        __syncthreads();
    }
    #pragma unroll
    for (int i = 0; i < 8; i++) {
        const int c = c0 + ty * 8 + i;
        const size_t ro = (size_t)b * CC * NN + (size_t)c * NN + n0 + tx * 8;
        float4 v0, v1;
        v0.x = acc[i][0]; v0.y = acc[i][1]; v0.z = acc[i][2]; v0.w = acc[i][3];
        v1.x = acc[i][4]; v1.y = acc[i][5]; v1.z = acc[i][6]; v1.w = acc[i][7];
        *(float4*)&g_o[ro]     = v0;
        *(float4*)&g_o[ro + 4] = v1;
    }
}

// ---------------- launch ----------------
extern "C" void kernel_launch(void* const* d_in, const int* in_sizes, int n_in,
                              void* d_out, int out_size) {
    const float* input = (const float*)d_in[0];
    const float* gns   = (const float*)d_in[1];
    const float* gnb   = (const float*)d_in[2];
    const float* Wq    = (const float*)d_in[3];
    const float* bq    = (const float*)d_in[4];
    const float* Wk    = (const float*)d_in[5];
    const float* bk    = (const float*)d_in[6];
    const float* Wv    = (const float*)d_in[7];
    const float* bv    = (const float*)d_in[8];
    const float* Wo    = (const float*)d_in[9];
    const float* bo    = (const float*)d_in[10];
    float* out = (float*)d_out;

    float *ph, *pq, *pk, *pv, *po;
    cudaGetSymbolAddress((void**)&ph, g_h);
    cudaGetSymbolAddress((void**)&pq, g_q);
    cudaGetSymbolAddress((void**)&pk, g_k);
    cudaGetSymbolAddress((void**)&pv, g_v);
    cudaGetSymbolAddress((void**)&po, g_o);

    gn_kernel<<<BB * NG, 1024>>>(input, gns, gnb);

    dim3 gproj(NN / TS, CC / TS, BB);
    proj_kernel<<<gproj, 256>>>(Wq, bq, ph, nullptr, pq);
    proj_kernel<<<gproj, 256>>>(Wk, bk, ph, nullptr, pk);
    proj_kernel<<<gproj, 256>>>(Wv, bv, ph, nullptr, pv);

    dim3 gsc(NN / TS, NN / TS, BB);
    scores_kernel<<<gsc, 256>>>();

    softmax_kernel<<<BB * NN, 256>>>();

    dim3 gav(NN / TS, CC / TS, BB);
    av_kernel<<<gav, 256>>>();

    proj_kernel<<<gproj, 256>>>(Wo, bo, po, input, out);
}

// round 5
// speedup vs baseline: 2.9551x; 2.0840x over previous
#include <cuda_runtime.h>
#include <cuda_bf16.h>
#include <math_constants.h>
#include <cstdint>

// Problem constants
#define BB 4
#define CC 256
#define NN 4096
#define NG 8
#define CPG 32
#define EPSV 1e-5f
#define ATTN_SCALE 0.0625f  // 1/sqrt(256)

// SIMT GEMM tiling (projections)
#define TS 128
#define KT 16
#define PAD 132

// mma GEMM smem geometry
#define GROW 40                    // smem row stride in bf16 elements (80B)
#define MATB (128 * GROW * 2)      // bytes per matrix tile = 10240
#define BUFB (4 * MATB)            // per-stage buffer = 40960
#define GEMM_SMEM (2 * BUFB)       // double buffered = 81920

// ---------------- static scratch (allocation-free) ----------------
__device__ __align__(16) float g_h[BB * CC * NN];
__device__ __align__(16) float g_q[BB * CC * NN];
__device__ __align__(16) float g_k[BB * CC * NN];
__device__ __align__(16) float g_v[BB * CC * NN];
__device__ __align__(16) float g_ot[BB * NN * CC];           // AV result [b][n][c] fp32
__device__ __align__(16) float g_S[(size_t)BB * NN * NN];    // raw scores fp32
__device__ __align__(16) __nv_bfloat16 g_qt_hi[BB * NN * CC];  // [b][n][c]
__device__ __align__(16) __nv_bfloat16 g_qt_lo[BB * NN * CC];
__device__ __align__(16) __nv_bfloat16 g_kt_hi[BB * NN * CC];
__device__ __align__(16) __nv_bfloat16 g_kt_lo[BB * NN * CC];
__device__ __align__(16) __nv_bfloat16 g_v_hi[BB * CC * NN];   // [b][c][m]
__device__ __align__(16) __nv_bfloat16 g_v_lo[BB * CC * NN];
__device__ __align__(16) __nv_bfloat16 g_p_hi[(size_t)BB * NN * NN]; // [b][n][m]
__device__ __align__(16) __nv_bfloat16 g_p_lo[(size_t)BB * NN * NN];

// ================= PTX helpers (sm_100-safe: ldmatrix / mma.sync / cp.async) =================
__device__ __forceinline__ uint32_t smem_u32(const void* p) {
    uint32_t a;
    asm("{ .reg .u64 t; cvta.to.shared.u64 t, %1; cvt.u32.u64 %0, t; }" : "=r"(a) : "l"(p));
    return a;
}
__device__ __forceinline__ void ldm4(uint32_t r[4], uint32_t addr) {
    asm volatile("ldmatrix.sync.aligned.m8n8.x4.shared.b16 {%0,%1,%2,%3}, [%4];"
                 : "=r"(r[0]), "=r"(r[1]), "=r"(r[2]), "=r"(r[3]) : "r"(addr));
}
__device__ __forceinline__ void mma16816(float c[4], const uint32_t a[4],
                                         uint32_t b0, uint32_t b1) {
    asm volatile("mma.sync.aligned.m16n8k16.row.col.f32.bf16.bf16.f32 "
                 "{%0,%1,%2,%3}, {%4,%5,%6,%7}, {%8,%9}, {%0,%1,%2,%3};"
                 : "+f"(c[0]), "+f"(c[1]), "+f"(c[2]), "+f"(c[3])
                 : "r"(a[0]), "r"(a[1]), "r"(a[2]), "r"(a[3]), "r"(b0), "r"(b1));
}
__device__ __forceinline__ void cpa16(uint32_t dst, const void* src) {
    asm volatile("cp.async.cg.shared.global [%0], [%1], 16;" :: "r"(dst), "l"(src));
}
#define CPA_COMMIT() asm volatile("cp.async.commit_group;" ::: "memory")
#define CPA_WAIT1()  asm volatile("cp.async.wait_group 1;" ::: "memory")
#define CPA_WAIT0()  asm volatile("cp.async.wait_group 0;" ::: "memory")

// ---------------- GroupNorm ----------------
__global__ void gn_kernel(const float* __restrict__ x,
                          const float* __restrict__ sc,
                          const float* __restrict__ bi) {
    const int bg = blockIdx.x;
    const int b = bg >> 3, g = bg & 7;
    const size_t base = ((size_t)b * CC + (size_t)g * CPG) * (size_t)NN;
    const float* xp = x + base;
    const int M4 = (CPG * NN) / 4;

    float s = 0.f, ss = 0.f;
    for (int i = threadIdx.x; i < M4; i += blockDim.x) {
        float4 v = ((const float4*)xp)[i];
        s += v.x + v.y + v.z + v.w;
        ss += v.x * v.x + v.y * v.y + v.z * v.z + v.w * v.w;
    }
    __shared__ float rs[1024], rq[1024];
    rs[threadIdx.x] = s; rq[threadIdx.x] = ss;
    __syncthreads();
    for (int st = 512; st > 0; st >>= 1) {
        if (threadIdx.x < st) { rs[threadIdx.x] += rs[threadIdx.x + st]; rq[threadIdx.x] += rq[threadIdx.x + st]; }
        __syncthreads();
    }
    const float Mf = (float)(CPG * NN);
    const float mean = rs[0] / Mf;
    const float var = rq[0] / Mf - mean * mean;
    const float inv = rsqrtf(var + EPSV);

    float4* outp = (float4*)(g_h + base);
    for (int i = threadIdx.x; i < M4; i += blockDim.x) {
        const int c = g * CPG + (i >> 10);
        const float a = inv * sc[c];
        const float d = bi[c] - mean * a;
        float4 v = ((const float4*)xp)[i];
        v.x = v.x * a + d; v.y = v.y * a + d; v.z = v.z * a + d; v.w = v.w * a + d;
        outp[i] = v;
    }
}

// ---------------- SIMT projection: Out[b,o,n] = W @ Hin + bias ----------------
__global__ __launch_bounds__(256, 2)
void proj_kernel(const float* __restrict__ W, const float* __restrict__ bias,
                 const float* __restrict__ Hin, float* __restrict__ Out) {
    __shared__ float As[KT][PAD];
    __shared__ float Bs[KT][PAD];
    const int b = blockIdx.z;
    const int n0 = blockIdx.x * TS;
    const int o0 = blockIdx.y * TS;
    const float* Hb = Hin + (size_t)b * CC * NN;
    const int tid = threadIdx.x;
    const int tx = tid & 15, ty = tid >> 4;

    float acc[8][8] = {};
    for (int c0 = 0; c0 < CC; c0 += KT) {
        #pragma unroll
        for (int l = 0; l < 2; l++) {
            int idx = tid + l * 256;
            int r = idx >> 2, kq = (idx & 3) * 4;
            float4 t = *(const float4*)&W[(size_t)(o0 + r) * CC + c0 + kq];
            As[kq + 0][r] = t.x; As[kq + 1][r] = t.y; As[kq + 2][r] = t.z; As[kq + 3][r] = t.w;
            int kk = idx >> 5, n4 = (idx & 31) * 4;
            *(float4*)&Bs[kk][n4] = *(const float4*)&Hb[(size_t)(c0 + kk) * NN + n0 + n4];
        }
        __syncthreads();
        #pragma unroll
        for (int kk = 0; kk < KT; kk++) {
            float a[8], bb[8];
            *(float4*)(a)     = *(float4*)&As[kk][ty * 8];
            *(float4*)(a + 4) = *(float4*)&As[kk][ty * 8 + 4];
            *(float4*)(bb)     = *(float4*)&Bs[kk][tx * 8];
            *(float4*)(bb + 4) = *(float4*)&Bs[kk][tx * 8 + 4];
            #pragma unroll
            for (int i = 0; i < 8; i++)
                #pragma unroll
                for (int j = 0; j < 8; j++)
                    acc[i][j] += a[i] * bb[j];
        }
        __syncthreads();
    }
    #pragma unroll
    for (int i = 0; i < 8; i++) {
        const int o = o0 + ty * 8 + i;
        const float bo_ = bias[o];
        const size_t ro = (size_t)b * CC * NN + (size_t)o * NN + n0 + tx * 8;
        float4 v0, v1;
        v0.x = acc[i][0] + bo_; v0.y = acc[i][1] + bo_; v0.z = acc[i][2] + bo_; v0.w = acc[i][3] + bo_;
        v1.x = acc[i][4] + bo_; v1.y = acc[i][5] + bo_; v1.z = acc[i][6] + bo_; v1.w = acc[i][7] + bo_;
        *(float4*)&Out[ro] = v0;
        *(float4*)&Out[ro + 4] = v1;
    }
}

// ---------------- final projection: reads o_t[b][n][c], adds residual ----------------
__global__ __launch_bounds__(256, 2)
void projo_kernel(const float* __restrict__ W, const float* __restrict__ bias,
                  const float* __restrict__ Ot, const float* __restrict__ res,
                  float* __restrict__ Out) {
    __shared__ float As[KT][PAD];
    __shared__ float Bs[KT][PAD];
    const int b = blockIdx.z;
    const int n0 = blockIdx.x * TS;
    const int o0 = blockIdx.y * TS;
    const float* Ob = Ot + (size_t)b * NN * CC;
    const int tid = threadIdx.x;
    const int tx = tid & 15, ty = tid >> 4;

    float acc[8][8] = {};
    for (int c0 = 0; c0 < CC; c0 += KT) {
        #pragma unroll
        for (int l = 0; l < 2; l++) {
            int idx = tid + l * 256;
            int r = idx >> 2, kq = (idx & 3) * 4;
            float4 t = *(const float4*)&W[(size_t)(o0 + r) * CC + c0 + kq];
            As[kq + 0][r] = t.x; As[kq + 1][r] = t.y; As[kq + 2][r] = t.z; As[kq + 3][r] = t.w;
            float4 u = *(const float4*)&Ob[(size_t)(n0 + r) * CC + c0 + kq];
            Bs[kq + 0][r] = u.x; Bs[kq + 1][r] = u.y; Bs[kq + 2][r] = u.z; Bs[kq + 3][r] = u.w;
        }
        __syncthreads();
        #pragma unroll
        for (int kk = 0; kk < KT; kk++) {
            float a[8], bb[8];
            *(float4*)(a)     = *(float4*)&As[kk][ty * 8];
            *(float4*)(a + 4) = *(float4*)&As[kk][ty * 8 + 4];
            *(float4*)(bb)     = *(float4*)&Bs[kk][tx * 8];
            *(float4*)(bb + 4) = *(float4*)&Bs[kk][tx * 8 + 4];
            #pragma unroll
            for (int i = 0; i < 8; i++)
                #pragma unroll
                for (int j = 0; j < 8; j++)
                    acc[i][j] += a[i] * bb[j];
        }
        __syncthreads();
    }
    #pragma unroll
    for (int i = 0; i < 8; i++) {
        const int o = o0 + ty * 8 + i;
        const float bo_ = bias[o];
        const size_t ro = (size_t)b * CC * NN + (size_t)o * NN + n0 + tx * 8;
        float4 r0 = *(const float4*)&res[ro];
        float4 r1 = *(const float4*)&res[ro + 4];
        float4 v0, v1;
        v0.x = acc[i][0] + bo_ + r0.x; v0.y = acc[i][1] + bo_ + r0.y;
        v0.z = acc[i][2] + bo_ + r0.z; v0.w = acc[i][3] + bo_ + r0.w;
        v1.x = acc[i][4] + bo_ + r1.x; v1.y = acc[i][5] + bo_ + r1.y;
        v1.z = acc[i][6] + bo_ + r1.z; v1.w = acc[i][7] + bo_ + r1.w;
        *(float4*)&Out[ro] = v0;
        *(float4*)&Out[ro + 4] = v1;
    }
}

// ---------------- transpose + hi/lo split: src[b][c][n] fp32 -> dst[b][n][c] bf16 hi/lo ----------------
__global__ void tconv_kernel(const float* __restrict__ src,
                             __nv_bfloat16* __restrict__ dhi,
                             __nv_bfloat16* __restrict__ dlo) {
    __shared__ float t[32][33];
    const int b = blockIdx.z;
    const int n0 = blockIdx.x * 32;
    const int c0 = blockIdx.y * 32;
    const int tx = threadIdx.x, ty = threadIdx.y;  // (32, 8)
    const float* s = src + (size_t)b * CC * NN;
    #pragma unroll
    for (int k = 0; k < 4; k++)
        t[ty + 8 * k][tx] = s[(size_t)(c0 + ty + 8 * k) * NN + n0 + tx];
    __syncthreads();
    const size_t base = (size_t)b * NN * CC;
    #pragma unroll
    for (int k = 0; k < 4; k++) {
        const int n = n0 + ty + 8 * k;
        const float val = t[tx][ty + 8 * k];
        __nv_bfloat16 hi = __float2bfloat16(val);
        __nv_bfloat16 lo = __float2bfloat16(val - __bfloat162float(hi));
        dhi[base + (size_t)n * CC + c0 + tx] = hi;
        dlo[base + (size_t)n * CC + c0 + tx] = lo;
    }
}

// ---------------- elementwise hi/lo split (v) ----------------
__global__ void split_kernel(const float* __restrict__ src,
                             __nv_bfloat16* __restrict__ dhi,
                             __nv_bfloat16* __restrict__ dlo, int n) {
    for (int i = blockIdx.x * blockDim.x + threadIdx.x; i < n; i += gridDim.x * blockDim.x) {
        float val = src[i];
        __nv_bfloat16 hi = __float2bfloat16(val);
        dhi[i] = hi;
        dlo[i] = __float2bfloat16(val - __bfloat162float(hi));
    }
}

// ============================================================================
// Unified hi/lo bf16 GEMM via mma.sync:
//   Out[M0+i][N0+j] = scale * sum_k A[i][k] * B[j][k]
// A rows (M), B rows (N), both K-contiguous. 3-pass hi/lo split.
// Block: 128x128 tile, 256 thr, 8 warps (4 along M x 2 along N), warp = 32x64.
// cp.async double-buffered, K chunks of 32.
// ============================================================================
__global__ __launch_bounds__(256, 1)
void gemm_hilo_kernel(const __nv_bfloat16* __restrict__ Ah, const __nv_bfloat16* __restrict__ Al,
                      const __nv_bfloat16* __restrict__ Bh, const __nv_bfloat16* __restrict__ Bl,
                      size_t ldA, size_t ldB, size_t strA, size_t strB,
                      float* __restrict__ Out, size_t ldOut, size_t strOut,
                      int K, float scale) {
    extern __shared__ char smem[];
    const uint32_t sb = smem_u32(smem);
    const int tid = threadIdx.x;
    const int lane = tid & 31, wid = tid >> 5;
    const int warpM = wid & 3, warpN = wid >> 2;
    const int bz = blockIdx.z;
    const int N0 = blockIdx.x * 128;
    const int M0 = blockIdx.y * 128;

    const __nv_bfloat16* pA[2] = { Ah + (size_t)bz * strA + (size_t)M0 * ldA,
                                   Al + (size_t)bz * strA + (size_t)M0 * ldA };
    const __nv_bfloat16* pB[2] = { Bh + (size_t)bz * strB + (size_t)N0 * ldB,
                                   Bl + (size_t)bz * strB + (size_t)N0 * ldB };

    // lane-derived fragment offsets
    const int ga = lane >> 3;
    const int arow = ((ga & 1) << 3) + (lane & 7);
    const int akoff = (ga >> 1) << 3;
    const int brow = ((ga >> 1) << 3) + (lane & 7);
    const int bkoff = (ga & 1) << 3;

    float acc[2][8][4];
    #pragma unroll
    for (int i = 0; i < 2; i++)
        #pragma unroll
        for (int j = 0; j < 8; j++)
            #pragma unroll
            for (int k = 0; k < 4; k++) acc[i][j][k] = 0.f;

    const int nch = K >> 5;

    // copy helper (unrolled in-line twice)
    #define ISSUE_COPY(bufi, kc) do {                                              \
        _Pragma("unroll")                                                          \
        for (int i_ = 0; i_ < 8; i_++) {                                           \
            int idx_ = tid + i_ * 256;                                             \
            int mat_ = idx_ >> 9;                                                  \
            int r_ = (idx_ >> 2) & 127;                                            \
            int seg_ = idx_ & 3;                                                   \
            const __nv_bfloat16* src_;                                             \
            if (mat_ < 2) src_ = pA[mat_] + (size_t)r_ * ldA + (kc) + seg_ * 8;    \
            else          src_ = pB[mat_ - 2] + (size_t)r_ * ldB + (kc) + seg_ * 8;\
            uint32_t dst_ = sb + (bufi) * BUFB + mat_ * MATB + (r_ * GROW + seg_ * 8) * 2; \
            cpa16(dst_, src_);                                                     \
        }                                                                          \
        CPA_COMMIT();                                                              \
    } while (0)

    ISSUE_COPY(0, 0);

    for (int c = 0; c < nch; c++) {
        if (c + 1 < nch) {
            ISSUE_COPY((c + 1) & 1, (c + 1) << 5);
            CPA_WAIT1();
        } else {
            CPA_WAIT0();
        }
        __syncthreads();

        const uint32_t bufb = sb + (c & 1) * BUFB;
        #pragma unroll
        for (int ks = 0; ks < 32; ks += 16) {
            uint32_t ah[2][4], al[2][4];
            #pragma unroll
            for (int mt = 0; mt < 2; mt++) {
                uint32_t off = (uint32_t)(((warpM * 32 + mt * 16 + arow) * GROW + ks + akoff) * 2);
                ldm4(ah[mt], bufb + 0 * MATB + off);
                ldm4(al[mt], bufb + 1 * MATB + off);
            }
            uint32_t bh[4][4], bl[4][4];
            #pragma unroll
            for (int ng = 0; ng < 4; ng++) {
                uint32_t off = (uint32_t)(((warpN * 64 + ng * 16 + brow) * GROW + ks + bkoff) * 2);
                ldm4(bh[ng], bufb + 2 * MATB + off);
                ldm4(bl[ng], bufb + 3 * MATB + off);
            }
            #pragma unroll
            for (int mt = 0; mt < 2; mt++)
                #pragma unroll
                for (int ng = 0; ng < 4; ng++)
                    #pragma unroll
                    for (int h = 0; h < 2; h++) {
                        const int nt = ng * 2 + h;
                        mma16816(acc[mt][nt], ah[mt], bh[ng][h * 2], bh[ng][h * 2 + 1]);
                        mma16816(acc[mt][nt], ah[mt], bl[ng][h * 2], bl[ng][h * 2 + 1]);
                        mma16816(acc[mt][nt], al[mt], bh[ng][h * 2], bh[ng][h * 2 + 1]);
                    }
        }
        __syncthreads();
    }

    // epilogue
    float* Ob = Out + (size_t)bz * strOut;
    #pragma unroll
    for (int mt = 0; mt < 2; mt++)
        #pragma unroll
        for (int nt = 0; nt < 8; nt++) {
            const int row = M0 + warpM * 32 + mt * 16 + (lane >> 2);
            const int col = N0 + warpN * 64 + nt * 8 + ((lane & 3) << 1);
            float2 v0, v1;
            v0.x = acc[mt][nt][0] * scale; v0.y = acc[mt][nt][1] * scale;
            v1.x = acc[mt][nt][2] * scale; v1.y = acc[mt][nt][3] * scale;
            *(float2*)&Ob[(size_t)row * ldOut + col] = v0;
            *(float2*)&Ob[(size_t)(row + 8) * ldOut + col] = v1;
        }
}

// ---------------- softmax: fp32 in, bf16 hi/lo out ----------------
__global__ void softmax_kernel() {
    const size_t row = blockIdx.x;  // b*NN + n
    const float* p = g_S + row * (size_t)NN;
    __nv_bfloat16* ph = g_p_hi + row * (size_t)NN;
    __nv_bfloat16* pl = g_p_lo + row * (size_t)NN;
    const int tid = threadIdx.x;

    float4 v[4];
    float mx = -CUDART_INF_F;
    #pragma unroll
    for (int l = 0; l < 4; l++) {
        v[l] = ((const float4*)p)[tid + l * 256];
        mx = fmaxf(mx, fmaxf(fmaxf(v[l].x, v[l].y), fmaxf(v[l].z, v[l].w)));
    }
    __shared__ float red[256];
    red[tid] = mx; __syncthreads();
    for (int st = 128; st > 0; st >>= 1) {
        if (tid < st) red[tid] = fmaxf(red[tid], red[tid + st]);
        __syncthreads();
    }
    mx = red[0];
    __syncthreads();

    float sum = 0.f;
    #pragma unroll
    for (int l = 0; l < 4; l++) {
        v[l].x = __expf(v[l].x - mx); v[l].y = __expf(v[l].y - mx);
        v[l].z = __expf(v[l].z - mx); v[l].w = __expf(v[l].w - mx);
        sum += v[l].x + v[l].y + v[l].z + v[l].w;
    }
    red[tid] = sum; __syncthreads();
    for (int st = 128; st > 0; st >>= 1) {
        if (tid < st) red[tid] += red[tid + st];
        __syncthreads();
    }
    const float inv = 1.f / red[0];
    #pragma unroll
    for (int l = 0; l < 4; l++) {
        float w0 = v[l].x * inv, w1 = v[l].y * inv, w2 = v[l].z * inv, w3 = v[l].w * inv;
        __nv_bfloat16 h0 = __float2bfloat16(w0), h1 = __float2bfloat16(w1);
        __nv_bfloat16 h2 = __float2bfloat16(w2), h3 = __float2bfloat16(w3);
        __nv_bfloat16 l0 = __float2bfloat16(w0 - __bfloat162float(h0));
        __nv_bfloat16 l1 = __float2bfloat16(w1 - __bfloat162float(h1));
        __nv_bfloat16 l2 = __float2bfloat16(w2 - __bfloat162float(h2));
        __nv_bfloat16 l3 = __float2bfloat16(w3 - __bfloat162float(h3));
        const int i0 = (tid + l * 256) * 4;
        __nv_bfloat162 a, bpk;
        a.x = h0; a.y = h1; bpk.x = h2; bpk.y = h3;
        ((__nv_bfloat162*)(ph + i0))[0] = a;
        ((__nv_bfloat162*)(ph + i0))[1] = bpk;
        a.x = l0; a.y = l1; bpk.x = l2; bpk.y = l3;
        ((__nv_bfloat162*)(pl + i0))[0] = a;
        ((__nv_bfloat162*)(pl + i0))[1] = bpk;
    }
}

// ---------------- launch ----------------
extern "C" void kernel_launch(void* const* d_in, const int* in_sizes, int n_in,
                              void* d_out, int out_size) {
    const float* input = (const float*)d_in[0];
    const float* gns   = (const float*)d_in[1];
    const float* gnb   = (const float*)d_in[2];
    const float* Wq    = (const float*)d_in[3];
    const float* bq    = (const float*)d_in[4];
    const float* Wk    = (const float*)d_in[5];
    const float* bk    = (const float*)d_in[6];
    const float* Wv    = (const float*)d_in[7];
    const float* bv    = (const float*)d_in[8];
    const float* Wo    = (const float*)d_in[9];
    const float* bo    = (const float*)d_in[10];
    float* out = (float*)d_out;

    float *phf, *pqf, *pkf, *pvf, *pot, *pS;
    cudaGetSymbolAddress((void**)&phf, g_h);
    cudaGetSymbolAddress((void**)&pqf, g_q);
    cudaGetSymbolAddress((void**)&pkf, g_k);
    cudaGetSymbolAddress((void**)&pvf, g_v);
    cudaGetSymbolAddress((void**)&pot, g_ot);
    cudaGetSymbolAddress((void**)&pS, g_S);
    __nv_bfloat16 *qh, *ql, *kh, *kl, *vh, *vl, *ph, *pl;
    cudaGetSymbolAddress((void**)&qh, g_qt_hi);
    cudaGetSymbolAddress((void**)&ql, g_qt_lo);
    cudaGetSymbolAddress((void**)&kh, g_kt_hi);
    cudaGetSymbolAddress((void**)&kl, g_kt_lo);
    cudaGetSymbolAddress((void**)&vh, g_v_hi);
    cudaGetSymbolAddress((void**)&vl, g_v_lo);
    cudaGetSymbolAddress((void**)&ph, g_p_hi);
    cudaGetSymbolAddress((void**)&pl, g_p_lo);

    cudaFuncSetAttribute(gemm_hilo_kernel, cudaFuncAttributeMaxDynamicSharedMemorySize, GEMM_SMEM);

    // 1) GroupNorm
    gn_kernel<<<BB * NG, 1024>>>(input, gns, gnb);

    // 2) Q, K, V projections (fp32)
    dim3 gproj(NN / TS, CC / TS, BB);
    proj_kernel<<<gproj, 256>>>(Wq, bq, phf, pqf);
    proj_kernel<<<gproj, 256>>>(Wk, bk, phf, pkf);
    proj_kernel<<<gproj, 256>>>(Wv, bv, phf, pvf);

    // 3) operand prep
    dim3 gt(NN / 32, CC / 32, BB);
    dim3 bt(32, 8);
    tconv_kernel<<<gt, bt>>>(pqf, qh, ql);
    tconv_kernel<<<gt, bt>>>(pkf, kh, kl);
    split_kernel<<<4096, 256>>>(pvf, vh, vl, BB * CC * NN);

    // 4) scores: S[n][m] = scale * q[n]·k[m]   (A=qt, B=kt, K=256)
    dim3 gsc(NN / 128, NN / 128, BB);
    gemm_hilo_kernel<<<gsc, 256, GEMM_SMEM>>>(
        qh, ql, kh, kl,
        (size_t)CC, (size_t)CC, (size_t)NN * CC, (size_t)NN * CC,
        pS, (size_t)NN, (size_t)NN * NN,
        CC, ATTN_SCALE);

    // 5) softmax -> P hi/lo bf16
    softmax_kernel<<<BB * NN, 256>>>();

    // 6) AV: Ot[n][c] = P[n]·v[c]   (A=p, B=v, K=4096)
    dim3 gav(CC / 128, NN / 128, BB);
    gemm_hilo_kernel<<<gav, 256, GEMM_SMEM>>>(
        ph, pl, vh, vl,
        (size_t)NN, (size_t)NN, (size_t)NN * NN, (size_t)CC * NN,
        pot, (size_t)CC, (size_t)NN * CC,
        NN, 1.0f);

    // 7) output projection + residual
    projo_kernel<<<gproj, 256>>>(Wo, bo, pot, input, out);
}

// round 6
// speedup vs baseline: 3.3465x; 1.1325x over previous
#include <cuda_runtime.h>
#include <cuda_bf16.h>
#include <math_constants.h>
#include <cstdint>

// Problem constants
#define BB 4
#define CC 256
#define NN 4096
#define NG 8
#define CPG 32
#define EPSV 1e-5f
#define ATTN_SCALE 0.0625f  // 1/sqrt(256)

// mma GEMM smem geometry
#define GROW 40                    // smem row stride in bf16 elements (80B)
#define MATB (128 * GROW * 2)      // bytes per matrix tile = 10240
#define BUFB (4 * MATB)            // per-stage buffer = 40960
#define GEMM_SMEM (2 * BUFB)       // double buffered = 81920

// ---------------- static scratch (allocation-free) ----------------
__device__ __align__(16) float g_h[BB * CC * NN];              // groupnorm out fp32
__device__ __align__(16) float g_S[(size_t)BB * NN * NN];      // raw scores fp32
__device__ __align__(16) __nv_bfloat16 g_ht_hi[BB * NN * CC];  // h^T [b][n][c]
__device__ __align__(16) __nv_bfloat16 g_ht_lo[BB * NN * CC];
__device__ __align__(16) __nv_bfloat16 g_w_hi[4 * CC * CC];    // Wq,Wk,Wv,Wo
__device__ __align__(16) __nv_bfloat16 g_w_lo[4 * CC * CC];
__device__ __align__(16) __nv_bfloat16 g_qt_hi[BB * NN * CC];  // q^T [b][n][o]
__device__ __align__(16) __nv_bfloat16 g_qt_lo[BB * NN * CC];
__device__ __align__(16) __nv_bfloat16 g_kt_hi[BB * NN * CC];  // k^T [b][m][o]
__device__ __align__(16) __nv_bfloat16 g_kt_lo[BB * NN * CC];
__device__ __align__(16) __nv_bfloat16 g_v_hi[BB * CC * NN];   // v [b][o][m]
__device__ __align__(16) __nv_bfloat16 g_v_lo[BB * CC * NN];
__device__ __align__(16) __nv_bfloat16 g_p_hi[(size_t)BB * NN * NN]; // P [b][n][m]
__device__ __align__(16) __nv_bfloat16 g_p_lo[(size_t)BB * NN * NN];
__device__ __align__(16) __nv_bfloat16 g_ot_hi[BB * NN * CC];  // Ot [b][n][c]
__device__ __align__(16) __nv_bfloat16 g_ot_lo[BB * NN * CC];

// ================= PTX helpers (sm_100-safe) =================
__device__ __forceinline__ uint32_t smem_u32(const void* p) {
    uint32_t a;
    asm("{ .reg .u64 t; cvta.to.shared.u64 t, %1; cvt.u32.u64 %0, t; }" : "=r"(a) : "l"(p));
    return a;
}
__device__ __forceinline__ void ldm4(uint32_t r[4], uint32_t addr) {
    asm volatile("ldmatrix.sync.aligned.m8n8.x4.shared.b16 {%0,%1,%2,%3}, [%4];"
                 : "=r"(r[0]), "=r"(r[1]), "=r"(r[2]), "=r"(r[3]) : "r"(addr));
}
__device__ __forceinline__ void mma16816(float c[4], const uint32_t a[4],
                                         uint32_t b0, uint32_t b1) {
    asm volatile("mma.sync.aligned.m16n8k16.row.col.f32.bf16.bf16.f32 "
                 "{%0,%1,%2,%3}, {%4,%5,%6,%7}, {%8,%9}, {%0,%1,%2,%3};"
                 : "+f"(c[0]), "+f"(c[1]), "+f"(c[2]), "+f"(c[3])
                 : "r"(a[0]), "r"(a[1]), "r"(a[2]), "r"(a[3]), "r"(b0), "r"(b1));
}
__device__ __forceinline__ void cpa16(uint32_t dst, const void* src) {
    asm volatile("cp.async.cg.shared.global [%0], [%1], 16;" :: "r"(dst), "l"(src));
}
#define CPA_COMMIT() asm volatile("cp.async.commit_group;" ::: "memory")
#define CPA_WAIT1()  asm volatile("cp.async.wait_group 1;" ::: "memory")
#define CPA_WAIT0()  asm volatile("cp.async.wait_group 0;" ::: "memory")

// ---------------- GroupNorm ----------------
__global__ void gn_kernel(const float* __restrict__ x,
                          const float* __restrict__ sc,
                          const float* __restrict__ bi) {
    const int bg = blockIdx.x;
    const int b = bg >> 3, g = bg & 7;
    const size_t base = ((size_t)b * CC + (size_t)g * CPG) * (size_t)NN;
    const float* xp = x + base;
    const int M4 = (CPG * NN) / 4;

    float s = 0.f, ss = 0.f;
    for (int i = threadIdx.x; i < M4; i += blockDim.x) {
        float4 v = ((const float4*)xp)[i];
        s += v.x + v.y + v.z + v.w;
        ss += v.x * v.x + v.y * v.y + v.z * v.z + v.w * v.w;
    }
    __shared__ float rs[1024], rq[1024];
    rs[threadIdx.x] = s; rq[threadIdx.x] = ss;
    __syncthreads();
    for (int st = 512; st > 0; st >>= 1) {
        if (threadIdx.x < st) { rs[threadIdx.x] += rs[threadIdx.x + st]; rq[threadIdx.x] += rq[threadIdx.x + st]; }
        __syncthreads();
    }
    const float Mf = (float)(CPG * NN);
    const float mean = rs[0] / Mf;
    const float var = rq[0] / Mf - mean * mean;
    const float inv = rsqrtf(var + EPSV);

    float4* outp = (float4*)(g_h + base);
    for (int i = threadIdx.x; i < M4; i += blockDim.x) {
        const int c = g * CPG + (i >> 10);
        const float a = inv * sc[c];
        const float d = bi[c] - mean * a;
        float4 v = ((const float4*)xp)[i];
        v.x = v.x * a + d; v.y = v.y * a + d; v.z = v.z * a + d; v.w = v.w * a + d;
        outp[i] = v;
    }
}

// ---------------- transpose + hi/lo split: src[b][c][n] fp32 -> dst[b][n][c] bf16 hi/lo ----------------
__global__ void tconv_kernel(const float* __restrict__ src,
                             __nv_bfloat16* __restrict__ dhi,
                             __nv_bfloat16* __restrict__ dlo) {
    __shared__ float t[32][33];
    const int b = blockIdx.z;
    const int n0 = blockIdx.x * 32;
    const int c0 = blockIdx.y * 32;
    const int tx = threadIdx.x, ty = threadIdx.y;  // (32, 8)
    const float* s = src + (size_t)b * CC * NN;
    #pragma unroll
    for (int k = 0; k < 4; k++)
        t[ty + 8 * k][tx] = s[(size_t)(c0 + ty + 8 * k) * NN + n0 + tx];
    __syncthreads();
    const size_t base = (size_t)b * NN * CC;
    #pragma unroll
    for (int k = 0; k < 4; k++) {
        const int n = n0 + ty + 8 * k;
        const float val = t[tx][ty + 8 * k];
        __nv_bfloat16 hi = __float2bfloat16(val);
        __nv_bfloat16 lo = __float2bfloat16(val - __bfloat162float(hi));
        dhi[base + (size_t)n * CC + c0 + tx] = hi;
        dlo[base + (size_t)n * CC + c0 + tx] = lo;
    }
}

// ---------------- elementwise hi/lo split (weights) ----------------
__global__ void split_kernel(const float* __restrict__ src,
                             __nv_bfloat16* __restrict__ dhi,
                             __nv_bfloat16* __restrict__ dlo, int n) {
    for (int i = blockIdx.x * blockDim.x + threadIdx.x; i < n; i += gridDim.x * blockDim.x) {
        float val = src[i];
        __nv_bfloat16 hi = __float2bfloat16(val);
        dhi[i] = hi;
        dlo[i] = __float2bfloat16(val - __bfloat162float(hi));
    }
}

// ============================================================================
// Unified hi/lo bf16 GEMM (mma.sync):
//   Out[M0+i][N0+j] = scale * sum_k A[i][k]*B[j][k]  (+bias, +res)
// OUTMODE: 0 = fp32 to OutF; 1 = bf16 hi/lo split to Oh/Ol
// BIASMODE: 0 = none; 1 = bias[row]; 2 = bias[col]
// ============================================================================
template<int OUTMODE, int BIASMODE, bool DO_RES>
__global__ __launch_bounds__(256, 1)
void gemm_hilo_kernel(const __nv_bfloat16* __restrict__ Ah, const __nv_bfloat16* __restrict__ Al,
                      const __nv_bfloat16* __restrict__ Bh, const __nv_bfloat16* __restrict__ Bl,
                      size_t ldA, size_t ldB, size_t strA, size_t strB,
                      float* __restrict__ OutF,
                      __nv_bfloat16* __restrict__ Oh, __nv_bfloat16* __restrict__ Ol,
                      size_t ldOut, size_t strOut,
                      const float* __restrict__ bias, const float* __restrict__ res,
                      int K, float scale) {
    extern __shared__ char smem[];
    const uint32_t sb = smem_u32(smem);
    const int tid = threadIdx.x;
    const int lane = tid & 31, wid = tid >> 5;
    const int warpM = wid & 3, warpN = wid >> 2;
    const int bz = blockIdx.z;
    const int N0 = blockIdx.x * 128;
    const int M0 = blockIdx.y * 128;

    const __nv_bfloat16* pA[2] = { Ah + (size_t)bz * strA + (size_t)M0 * ldA,
                                   Al + (size_t)bz * strA + (size_t)M0 * ldA };
    const __nv_bfloat16* pB[2] = { Bh + (size_t)bz * strB + (size_t)N0 * ldB,
                                   Bl + (size_t)bz * strB + (size_t)N0 * ldB };

    const int ga = lane >> 3;
    const int arow = ((ga & 1) << 3) + (lane & 7);
    const int akoff = (ga >> 1) << 3;
    const int brow = ((ga >> 1) << 3) + (lane & 7);
    const int bkoff = (ga & 1) << 3;

    float acc[2][8][4];
    #pragma unroll
    for (int i = 0; i < 2; i++)
        #pragma unroll
        for (int j = 0; j < 8; j++)
            #pragma unroll
            for (int k = 0; k < 4; k++) acc[i][j][k] = 0.f;

    const int nch = K >> 5;

    #define ISSUE_COPY(bufi, kc) do {                                              \
        _Pragma("unroll")                                                          \
        for (int i_ = 0; i_ < 8; i_++) {                                           \
            int idx_ = tid + i_ * 256;                                             \
            int mat_ = idx_ >> 9;                                                  \
            int r_ = (idx_ >> 2) & 127;                                            \
            int seg_ = idx_ & 3;                                                   \
            const __nv_bfloat16* src_;                                             \
            if (mat_ < 2) src_ = pA[mat_] + (size_t)r_ * ldA + (kc) + seg_ * 8;    \
            else          src_ = pB[mat_ - 2] + (size_t)r_ * ldB + (kc) + seg_ * 8;\
            uint32_t dst_ = sb + (bufi) * BUFB + mat_ * MATB + (r_ * GROW + seg_ * 8) * 2; \
            cpa16(dst_, src_);                                                     \
        }                                                                          \
        CPA_COMMIT();                                                              \
    } while (0)

    ISSUE_COPY(0, 0);

    for (int c = 0; c < nch; c++) {
        if (c + 1 < nch) {
            ISSUE_COPY((c + 1) & 1, (c + 1) << 5);
            CPA_WAIT1();
        } else {
            CPA_WAIT0();
        }
        __syncthreads();

        const uint32_t bufb = sb + (c & 1) * BUFB;
        #pragma unroll
        for (int ks = 0; ks < 32; ks += 16) {
            uint32_t ah[2][4], al[2][4];
            #pragma unroll
            for (int mt = 0; mt < 2; mt++) {
                uint32_t off = (uint32_t)(((warpM * 32 + mt * 16 + arow) * GROW + ks + akoff) * 2);
                ldm4(ah[mt], bufb + 0 * MATB + off);
                ldm4(al[mt], bufb + 1 * MATB + off);
            }
            uint32_t bh[4][4], bl[4][4];
            #pragma unroll
            for (int ng = 0; ng < 4; ng++) {
                uint32_t off = (uint32_t)(((warpN * 64 + ng * 16 + brow) * GROW + ks + bkoff) * 2);
                ldm4(bh[ng], bufb + 2 * MATB + off);
                ldm4(bl[ng], bufb + 3 * MATB + off);
            }
            #pragma unroll
            for (int mt = 0; mt < 2; mt++)
                #pragma unroll
                for (int ng = 0; ng < 4; ng++)
                    #pragma unroll
                    for (int h = 0; h < 2; h++) {
                        const int nt = ng * 2 + h;
                        mma16816(acc[mt][nt], ah[mt], bh[ng][h * 2], bh[ng][h * 2 + 1]);
                        mma16816(acc[mt][nt], ah[mt], bl[ng][h * 2], bl[ng][h * 2 + 1]);
                        mma16816(acc[mt][nt], al[mt], bh[ng][h * 2], bh[ng][h * 2 + 1]);
                    }
        }
        __syncthreads();
    }

    // epilogue
    #pragma unroll
    for (int mt = 0; mt < 2; mt++)
        #pragma unroll
        for (int nt = 0; nt < 8; nt++) {
            const int row0 = M0 + warpM * 32 + mt * 16 + (lane >> 2);
            const int col = N0 + warpN * 64 + nt * 8 + ((lane & 3) << 1);
            #pragma unroll
            for (int rr = 0; rr < 2; rr++) {
                const int r = row0 + rr * 8;
                float v0 = acc[mt][nt][rr * 2 + 0] * scale;
                float v1 = acc[mt][nt][rr * 2 + 1] * scale;
                if (BIASMODE == 1) { const float bb = bias[r]; v0 += bb; v1 += bb; }
                if (BIASMODE == 2) { v0 += bias[col]; v1 += bias[col + 1]; }
                const size_t off = (size_t)bz * strOut + (size_t)r * ldOut + col;
                if (DO_RES) { v0 += res[off]; v1 += res[off + 1]; }
                if (OUTMODE == 0) {
                    float2 o; o.x = v0; o.y = v1;
                    *(float2*)&OutF[off] = o;
                } else {
                    __nv_bfloat162 hpk, lpk;
                    hpk.x = __float2bfloat16(v0);
                    hpk.y = __float2bfloat16(v1);
                    lpk.x = __float2bfloat16(v0 - __bfloat162float(hpk.x));
                    lpk.y = __float2bfloat16(v1 - __bfloat162float(hpk.y));
                    *(__nv_bfloat162*)&Oh[off] = hpk;
                    *(__nv_bfloat162*)&Ol[off] = lpk;
                }
            }
        }
}

// ---------------- softmax: fp32 in, bf16 hi/lo out ----------------
__global__ void softmax_kernel() {
    const size_t row = blockIdx.x;  // b*NN + n
    const float* p = g_S + row * (size_t)NN;
    __nv_bfloat16* ph = g_p_hi + row * (size_t)NN;
    __nv_bfloat16* pl = g_p_lo + row * (size_t)NN;
    const int tid = threadIdx.x;

    float4 v[4];
    float mx = -CUDART_INF_F;
    #pragma unroll
    for (int l = 0; l < 4; l++) {
        v[l] = ((const float4*)p)[tid + l * 256];
        mx = fmaxf(mx, fmaxf(fmaxf(v[l].x, v[l].y), fmaxf(v[l].z, v[l].w)));
    }
    __shared__ float red[256];
    red[tid] = mx; __syncthreads();
    for (int st = 128; st > 0; st >>= 1) {
        if (tid < st) red[tid] = fmaxf(red[tid], red[tid + st]);
        __syncthreads();
    }
    mx = red[0];
    __syncthreads();

    float sum = 0.f;
    #pragma unroll
    for (int l = 0; l < 4; l++) {
        v[l].x = __expf(v[l].x - mx); v[l].y = __expf(v[l].y - mx);
        v[l].z = __expf(v[l].z - mx); v[l].w = __expf(v[l].w - mx);
        sum += v[l].x + v[l].y + v[l].z + v[l].w;
    }
    red[tid] = sum; __syncthreads();
    for (int st = 128; st > 0; st >>= 1) {
        if (tid < st) red[tid] += red[tid + st];
        __syncthreads();
    }
    const float inv = 1.f / red[0];
    #pragma unroll
    for (int l = 0; l < 4; l++) {
        float w0 = v[l].x * inv, w1 = v[l].y * inv, w2 = v[l].z * inv, w3 = v[l].w * inv;
        __nv_bfloat16 h0 = __float2bfloat16(w0), h1 = __float2bfloat16(w1);
        __nv_bfloat16 h2 = __float2bfloat16(w2), h3 = __float2bfloat16(w3);
        __nv_bfloat16 l0 = __float2bfloat16(w0 - __bfloat162float(h0));
        __nv_bfloat16 l1 = __float2bfloat16(w1 - __bfloat162float(h1));
        __nv_bfloat16 l2 = __float2bfloat16(w2 - __bfloat162float(h2));
        __nv_bfloat16 l3 = __float2bfloat16(w3 - __bfloat162float(h3));
        const int i0 = (tid + l * 256) * 4;
        __nv_bfloat162 a, bpk;
        a.x = h0; a.y = h1; bpk.x = h2; bpk.y = h3;
        ((__nv_bfloat162*)(ph + i0))[0] = a;
        ((__nv_bfloat162*)(ph + i0))[1] = bpk;
        a.x = l0; a.y = l1; bpk.x = l2; bpk.y = l3;
        ((__nv_bfloat162*)(pl + i0))[0] = a;
        ((__nv_bfloat162*)(pl + i0))[1] = bpk;
    }
}

// ---------------- launch ----------------
extern "C" void kernel_launch(void* const* d_in, const int* in_sizes, int n_in,
                              void* d_out, int out_size) {
    const float* input = (const float*)d_in[0];
    const float* gns   = (const float*)d_in[1];
    const float* gnb   = (const float*)d_in[2];
    const float* Wq    = (const float*)d_in[3];
    const float* bq    = (const float*)d_in[4];
    const float* Wk    = (const float*)d_in[5];
    const float* bk    = (const float*)d_in[6];
    const float* Wv    = (const float*)d_in[7];
    const float* bv    = (const float*)d_in[8];
    const float* Wo    = (const float*)d_in[9];
    const float* bo    = (const float*)d_in[10];
    float* out = (float*)d_out;

    float *phf, *pS;
    cudaGetSymbolAddress((void**)&phf, g_h);
    cudaGetSymbolAddress((void**)&pS, g_S);
    __nv_bfloat16 *hth, *htl, *wh, *wl, *qh, *ql, *kh, *kl, *vh, *vl, *ph, *pl, *oth, *otl;
    cudaGetSymbolAddress((void**)&hth, g_ht_hi);
    cudaGetSymbolAddress((void**)&htl, g_ht_lo);
    cudaGetSymbolAddress((void**)&wh, g_w_hi);
    cudaGetSymbolAddress((void**)&wl, g_w_lo);
    cudaGetSymbolAddress((void**)&qh, g_qt_hi);
    cudaGetSymbolAddress((void**)&ql, g_qt_lo);
    cudaGetSymbolAddress((void**)&kh, g_kt_hi);
    cudaGetSymbolAddress((void**)&kl, g_kt_lo);
    cudaGetSymbolAddress((void**)&vh, g_v_hi);
    cudaGetSymbolAddress((void**)&vl, g_v_lo);
    cudaGetSymbolAddress((void**)&ph, g_p_hi);
    cudaGetSymbolAddress((void**)&pl, g_p_lo);
    cudaGetSymbolAddress((void**)&oth, g_ot_hi);
    cudaGetSymbolAddress((void**)&otl, g_ot_lo);

    cudaFuncSetAttribute(gemm_hilo_kernel<1, 2, false>, cudaFuncAttributeMaxDynamicSharedMemorySize, GEMM_SMEM);
    cudaFuncSetAttribute(gemm_hilo_kernel<1, 1, false>, cudaFuncAttributeMaxDynamicSharedMemorySize, GEMM_SMEM);
    cudaFuncSetAttribute(gemm_hilo_kernel<0, 0, false>, cudaFuncAttributeMaxDynamicSharedMemorySize, GEMM_SMEM);
    cudaFuncSetAttribute(gemm_hilo_kernel<1, 0, false>, cudaFuncAttributeMaxDynamicSharedMemorySize, GEMM_SMEM);
    cudaFuncSetAttribute(gemm_hilo_kernel<0, 1, true>, cudaFuncAttributeMaxDynamicSharedMemorySize, GEMM_SMEM);

    const size_t WSZ = (size_t)CC * CC;

    // 1) GroupNorm (fp32) + weight splits
    gn_kernel<<<BB * NG, 1024>>>(input, gns, gnb);
    split_kernel<<<64, 256>>>(Wq, wh + 0 * WSZ, wl + 0 * WSZ, CC * CC);
    split_kernel<<<64, 256>>>(Wk, wh + 1 * WSZ, wl + 1 * WSZ, CC * CC);
    split_kernel<<<64, 256>>>(Wv, wh + 2 * WSZ, wl + 2 * WSZ, CC * CC);
    split_kernel<<<64, 256>>>(Wo, wh + 3 * WSZ, wl + 3 * WSZ, CC * CC);

    // 2) h -> hT hi/lo
    dim3 gt(NN / 32, CC / 32, BB);
    tconv_kernel<<<gt, dim3(32, 8)>>>(phf, hth, htl);

    // 3) Q: qT[n][o] = hT . Wq^T  (bias on col=o), out hi/lo
    dim3 gq(CC / 128, NN / 128, BB);
    gemm_hilo_kernel<1, 2, false><<<gq, 256, GEMM_SMEM>>>(
        hth, htl, wh + 0 * WSZ, wl + 0 * WSZ,
        CC, CC, (size_t)NN * CC, 0,
        nullptr, qh, ql, CC, (size_t)NN * CC, bq, nullptr, CC, 1.0f);
    //    K: kT[m][o]
    gemm_hilo_kernel<1, 2, false><<<gq, 256, GEMM_SMEM>>>(
        hth, htl, wh + 1 * WSZ, wl + 1 * WSZ,
        CC, CC, (size_t)NN * CC, 0,
        nullptr, kh, kl, CC, (size_t)NN * CC, bk, nullptr, CC, 1.0f);
    //    V: v[o][m] = Wv . hT^T  (bias on row=o), out hi/lo
    dim3 gv(NN / 128, CC / 128, BB);
    gemm_hilo_kernel<1, 1, false><<<gv, 256, GEMM_SMEM>>>(
        wh + 2 * WSZ, wl + 2 * WSZ, hth, htl,
        CC, CC, 0, (size_t)NN * CC,
        nullptr, vh, vl, NN, (size_t)CC * NN, bv, nullptr, CC, 1.0f);

    // 4) scores: S[n][m] = (1/16) qT . kT^T  fp32
    dim3 gsc(NN / 128, NN / 128, BB);
    gemm_hilo_kernel<0, 0, false><<<gsc, 256, GEMM_SMEM>>>(
        qh, ql, kh, kl,
        CC, CC, (size_t)NN * CC, (size_t)NN * CC,
        pS, nullptr, nullptr, NN, (size_t)NN * NN, nullptr, nullptr, CC, ATTN_SCALE);

    // 5) softmax -> P hi/lo
    softmax_kernel<<<BB * NN, 256>>>();

    // 6) AV: Ot[n][c] = P . v^T  out hi/lo
    dim3 gav(CC / 128, NN / 128, BB);
    gemm_hilo_kernel<1, 0, false><<<gav, 256, GEMM_SMEM>>>(
        ph, pl, vh, vl,
        NN, NN, (size_t)NN * NN, (size_t)CC * NN,
        nullptr, oth, otl, CC, (size_t)NN * CC, nullptr, nullptr, NN, 1.0f);

    // 7) final: out[o][n] = Wo . Ot^T + bo + residual  fp32
    dim3 gf(NN / 128, CC / 128, BB);
    gemm_hilo_kernel<0, 1, true><<<gf, 256, GEMM_SMEM>>>(
        wh + 3 * WSZ, wl + 3 * WSZ, oth, otl,
        CC, CC, 0, (size_t)NN * CC,
        out, nullptr, nullptr, NN, (size_t)CC * NN, bo, input, CC, 1.0f);
}

// round 7
// speedup vs baseline: 3.4131x; 1.0199x over previous
#include <cuda_runtime.h>
#include <cuda_bf16.h>
#include <math_constants.h>
#include <cstdint>

// Problem constants
#define BB 4
#define CC 256
#define NN 4096
#define NG 8
#define CPG 32
#define EPSV 1e-5f
#define ATTN_SCALE 0.0625f  // 1/sqrt(256)

// mma GEMM smem geometry (projection GEMMs)
#define GROW 40
#define MATB (128 * GROW * 2)
#define BUFB (4 * MATB)
#define GEMM_SMEM (2 * BUFB)

// flash kernel smem geometry (bytes)
#define FQ_STRIDE 264               // Q/K smem row stride in bf16 elems (528B)
#define FV_STRIDE 40                // V smem row stride in bf16 elems (80B)
#define FQH 0
#define FQL (FQH + 128 * FQ_STRIDE * 2)     // 67584
#define FKH (FQL + 128 * FQ_STRIDE * 2)     // 135168
#define FKL (FKH + 32 * FQ_STRIDE * 2)      // +16896
#define FVH (FKL + 32 * FQ_STRIDE * 2)      // 168960
#define FVL (FVH + 256 * FV_STRIDE * 2)     // +20480
#define FLASH_SMEM (FVL + 256 * FV_STRIDE * 2)  // 209920

// ---------------- static scratch (allocation-free) ----------------
__device__ __align__(16) float g_h[BB * CC * NN];              // groupnorm out fp32
__device__ __align__(16) __nv_bfloat16 g_ht_hi[BB * NN * CC];  // h^T [b][n][c]
__device__ __align__(16) __nv_bfloat16 g_ht_lo[BB * NN * CC];
__device__ __align__(16) __nv_bfloat16 g_w_hi[4 * CC * CC];    // Wq,Wk,Wv,Wo
__device__ __align__(16) __nv_bfloat16 g_w_lo[4 * CC * CC];
__device__ __align__(16) __nv_bfloat16 g_qt_hi[BB * NN * CC];  // q^T [b][n][o]
__device__ __align__(16) __nv_bfloat16 g_qt_lo[BB * NN * CC];
__device__ __align__(16) __nv_bfloat16 g_kt_hi[BB * NN * CC];  // k^T [b][m][o]
__device__ __align__(16) __nv_bfloat16 g_kt_lo[BB * NN * CC];
__device__ __align__(16) __nv_bfloat16 g_v_hi[BB * CC * NN];   // v [b][o][m]
__device__ __align__(16) __nv_bfloat16 g_v_lo[BB * CC * NN];
__device__ __align__(16) __nv_bfloat16 g_ot_hi[BB * NN * CC];  // Ot [b][n][c]
__device__ __align__(16) __nv_bfloat16 g_ot_lo[BB * NN * CC];

// ================= PTX helpers (sm_100-safe) =================
__device__ __forceinline__ uint32_t smem_u32(const void* p) {
    uint32_t a;
    asm("{ .reg .u64 t; cvta.to.shared.u64 t, %1; cvt.u32.u64 %0, t; }" : "=r"(a) : "l"(p));
    return a;
}
__device__ __forceinline__ void ldm4(uint32_t r[4], uint32_t addr) {
    asm volatile("ldmatrix.sync.aligned.m8n8.x4.shared.b16 {%0,%1,%2,%3}, [%4];"
                 : "=r"(r[0]), "=r"(r[1]), "=r"(r[2]), "=r"(r[3]) : "r"(addr));
}
__device__ __forceinline__ void mma16816(float c[4], const uint32_t a[4],
                                         uint32_t b0, uint32_t b1) {
    asm volatile("mma.sync.aligned.m16n8k16.row.col.f32.bf16.bf16.f32 "
                 "{%0,%1,%2,%3}, {%4,%5,%6,%7}, {%8,%9}, {%0,%1,%2,%3};"
                 : "+f"(c[0]), "+f"(c[1]), "+f"(c[2]), "+f"(c[3])
                 : "r"(a[0]), "r"(a[1]), "r"(a[2]), "r"(a[3]), "r"(b0), "r"(b1));
}
__device__ __forceinline__ void cpa16(uint32_t dst, const void* src) {
    asm volatile("cp.async.cg.shared.global [%0], [%1], 16;" :: "r"(dst), "l"(src));
}
#define CPA_COMMIT() asm volatile("cp.async.commit_group;" ::: "memory")
#define CPA_WAIT1()  asm volatile("cp.async.wait_group 1;" ::: "memory")
#define CPA_WAIT0()  asm volatile("cp.async.wait_group 0;" ::: "memory")

__device__ __forceinline__ uint32_t pack_bf16(float a, float b) {
    __nv_bfloat162 h;
    h.x = __float2bfloat16(a);
    h.y = __float2bfloat16(b);
    return *(uint32_t*)&h;
}

// ---------------- GroupNorm ----------------
__global__ void gn_kernel(const float* __restrict__ x,
                          const float* __restrict__ sc,
                          const float* __restrict__ bi) {
    const int bg = blockIdx.x;
    const int b = bg >> 3, g = bg & 7;
    const size_t base = ((size_t)b * CC + (size_t)g * CPG) * (size_t)NN;
    const float* xp = x + base;
    const int M4 = (CPG * NN) / 4;

    float s = 0.f, ss = 0.f;
    for (int i = threadIdx.x; i < M4; i += blockDim.x) {
        float4 v = ((const float4*)xp)[i];
        s += v.x + v.y + v.z + v.w;
        ss += v.x * v.x + v.y * v.y + v.z * v.z + v.w * v.w;
    }
    __shared__ float rs[1024], rq[1024];
    rs[threadIdx.x] = s; rq[threadIdx.x] = ss;
    __syncthreads();
    for (int st = 512; st > 0; st >>= 1) {
        if (threadIdx.x < st) { rs[threadIdx.x] += rs[threadIdx.x + st]; rq[threadIdx.x] += rq[threadIdx.x + st]; }
        __syncthreads();
    }
    const float Mf = (float)(CPG * NN);
    const float mean = rs[0] / Mf;
    const float var = rq[0] / Mf - mean * mean;
    const float inv = rsqrtf(var + EPSV);

    float4* outp = (float4*)(g_h + base);
    for (int i = threadIdx.x; i < M4; i += blockDim.x) {
        const int c = g * CPG + (i >> 10);
        const float a = inv * sc[c];
        const float d = bi[c] - mean * a;
        float4 v = ((const float4*)xp)[i];
        v.x = v.x * a + d; v.y = v.y * a + d; v.z = v.z * a + d; v.w = v.w * a + d;
        outp[i] = v;
    }
}

// ---------------- transpose + hi/lo split ----------------
__global__ void tconv_kernel(const float* __restrict__ src,
                             __nv_bfloat16* __restrict__ dhi,
                             __nv_bfloat16* __restrict__ dlo) {
    __shared__ float t[32][33];
    const int b = blockIdx.z;
    const int n0 = blockIdx.x * 32;
    const int c0 = blockIdx.y * 32;
    const int tx = threadIdx.x, ty = threadIdx.y;  // (32, 8)
    const float* s = src + (size_t)b * CC * NN;
    #pragma unroll
    for (int k = 0; k < 4; k++)
        t[ty + 8 * k][tx] = s[(size_t)(c0 + ty + 8 * k) * NN + n0 + tx];
    __syncthreads();
    const size_t base = (size_t)b * NN * CC;
    #pragma unroll
    for (int k = 0; k < 4; k++) {
        const int n = n0 + ty + 8 * k;
        const float val = t[tx][ty + 8 * k];
        __nv_bfloat16 hi = __float2bfloat16(val);
        __nv_bfloat16 lo = __float2bfloat16(val - __bfloat162float(hi));
        dhi[base + (size_t)n * CC + c0 + tx] = hi;
        dlo[base + (size_t)n * CC + c0 + tx] = lo;
    }
}

// ---------------- elementwise hi/lo split (weights) ----------------
__global__ void split_kernel(const float* __restrict__ src,
                             __nv_bfloat16* __restrict__ dhi,
                             __nv_bfloat16* __restrict__ dlo, int n) {
    for (int i = blockIdx.x * blockDim.x + threadIdx.x; i < n; i += gridDim.x * blockDim.x) {
        float val = src[i];
        __nv_bfloat16 hi = __float2bfloat16(val);
        dhi[i] = hi;
        dlo[i] = __float2bfloat16(val - __bfloat162float(hi));
    }
}

// ============================================================================
// hi/lo bf16 GEMM (projections + final)
// ============================================================================
template<int OUTMODE, int BIASMODE, bool DO_RES>
__global__ __launch_bounds__(256, 1)
void gemm_hilo_kernel(const __nv_bfloat16* __restrict__ Ah, const __nv_bfloat16* __restrict__ Al,
                      const __nv_bfloat16* __restrict__ Bh, const __nv_bfloat16* __restrict__ Bl,
                      size_t ldA, size_t ldB, size_t strA, size_t strB,
                      float* __restrict__ OutF,
                      __nv_bfloat16* __restrict__ Oh, __nv_bfloat16* __restrict__ Ol,
                      size_t ldOut, size_t strOut,
                      const float* __restrict__ bias, const float* __restrict__ res,
                      int K, float scale) {
    extern __shared__ char smem[];
    const uint32_t sb = smem_u32(smem);
    const int tid = threadIdx.x;
    const int lane = tid & 31, wid = tid >> 5;
    const int warpM = wid & 3, warpN = wid >> 2;
    const int bz = blockIdx.z;
    const int N0 = blockIdx.x * 128;
    const int M0 = blockIdx.y * 128;

    const __nv_bfloat16* pA[2] = { Ah + (size_t)bz * strA + (size_t)M0 * ldA,
                                   Al + (size_t)bz * strA + (size_t)M0 * ldA };
    const __nv_bfloat16* pB[2] = { Bh + (size_t)bz * strB + (size_t)N0 * ldB,
                                   Bl + (size_t)bz * strB + (size_t)N0 * ldB };

    const int ga = lane >> 3;
    const int arow = ((ga & 1) << 3) + (lane & 7);
    const int akoff = (ga >> 1) << 3;
    const int brow = ((ga >> 1) << 3) + (lane & 7);
    const int bkoff = (ga & 1) << 3;

    float acc[2][8][4];
    #pragma unroll
    for (int i = 0; i < 2; i++)
        #pragma unroll
        for (int j = 0; j < 8; j++)
            #pragma unroll
            for (int k = 0; k < 4; k++) acc[i][j][k] = 0.f;

    const int nch = K >> 5;

    #define ISSUE_COPY(bufi, kc) do {                                              \
        _Pragma("unroll")                                                          \
        for (int i_ = 0; i_ < 8; i_++) {                                           \
            int idx_ = tid + i_ * 256;                                             \
            int mat_ = idx_ >> 9;                                                  \
            int r_ = (idx_ >> 2) & 127;                                            \
            int seg_ = idx_ & 3;                                                   \
            const __nv_bfloat16* src_;                                             \
            if (mat_ < 2) src_ = pA[mat_] + (size_t)r_ * ldA + (kc) + seg_ * 8;    \
            else          src_ = pB[mat_ - 2] + (size_t)r_ * ldB + (kc) + seg_ * 8;\
            uint32_t dst_ = sb + (bufi) * BUFB + mat_ * MATB + (r_ * GROW + seg_ * 8) * 2; \
            cpa16(dst_, src_);                                                     \
        }                                                                          \
        CPA_COMMIT();                                                              \
    } while (0)

    ISSUE_COPY(0, 0);

    for (int c = 0; c < nch; c++) {
        if (c + 1 < nch) {
            ISSUE_COPY((c + 1) & 1, (c + 1) << 5);
            CPA_WAIT1();
        } else {
            CPA_WAIT0();
        }
        __syncthreads();

        const uint32_t bufb = sb + (c & 1) * BUFB;
        #pragma unroll
        for (int ks = 0; ks < 32; ks += 16) {
            uint32_t ah[2][4], al[2][4];
            #pragma unroll
            for (int mt = 0; mt < 2; mt++) {
                uint32_t off = (uint32_t)(((warpM * 32 + mt * 16 + arow) * GROW + ks + akoff) * 2);
                ldm4(ah[mt], bufb + 0 * MATB + off);
                ldm4(al[mt], bufb + 1 * MATB + off);
            }
            uint32_t bh[4][4], bl[4][4];
            #pragma unroll
            for (int ng = 0; ng < 4; ng++) {
                uint32_t off = (uint32_t)(((warpN * 64 + ng * 16 + brow) * GROW + ks + bkoff) * 2);
                ldm4(bh[ng], bufb + 2 * MATB + off);
                ldm4(bl[ng], bufb + 3 * MATB + off);
            }
            #pragma unroll
            for (int mt = 0; mt < 2; mt++)
                #pragma unroll
                for (int ng = 0; ng < 4; ng++)
                    #pragma unroll
                    for (int h = 0; h < 2; h++) {
                        const int nt = ng * 2 + h;
                        mma16816(acc[mt][nt], ah[mt], bh[ng][h * 2], bh[ng][h * 2 + 1]);
                        mma16816(acc[mt][nt], ah[mt], bl[ng][h * 2], bl[ng][h * 2 + 1]);
                        mma16816(acc[mt][nt], al[mt], bh[ng][h * 2], bh[ng][h * 2 + 1]);
                    }
        }
        __syncthreads();
    }

    #pragma unroll
    for (int mt = 0; mt < 2; mt++)
        #pragma unroll
        for (int nt = 0; nt < 8; nt++) {
            const int row0 = M0 + warpM * 32 + mt * 16 + (lane >> 2);
            const int col = N0 + warpN * 64 + nt * 8 + ((lane & 3) << 1);
            #pragma unroll
            for (int rr = 0; rr < 2; rr++) {
                const int r = row0 + rr * 8;
                float v0 = acc[mt][nt][rr * 2 + 0] * scale;
                float v1 = acc[mt][nt][rr * 2 + 1] * scale;
                if (BIASMODE == 1) { const float bb = bias[r]; v0 += bb; v1 += bb; }
                if (BIASMODE == 2) { v0 += bias[col]; v1 += bias[col + 1]; }
                const size_t off = (size_t)bz * strOut + (size_t)r * ldOut + col;
                if (DO_RES) { v0 += res[off]; v1 += res[off + 1]; }
                if (OUTMODE == 0) {
                    float2 o; o.x = v0; o.y = v1;
                    *(float2*)&OutF[off] = o;
                } else {
                    __nv_bfloat162 hpk, lpk;
                    hpk.x = __float2bfloat16(v0);
                    hpk.y = __float2bfloat16(v1);
                    lpk.x = __float2bfloat16(v0 - __bfloat162float(hpk.x));
                    lpk.y = __float2bfloat16(v1 - __bfloat162float(hpk.y));
                    *(__nv_bfloat162*)&Oh[off] = hpk;
                    *(__nv_bfloat162*)&Ol[off] = lpk;
                }
            }
        }
}

// ============================================================================
// Flash attention: per block = (b, 128 query rows). 8 warps x 16 rows.
// Loops m tiles of 32 keys: S=qk (3-pass hi/lo mma), online softmax,
// P hi/lo re-split in registers, O += P.V (3-pass mma).
// Writes Ot[b][n][c] bf16 hi/lo.
// ============================================================================
__global__ __launch_bounds__(256, 1)
void flash_kernel(const __nv_bfloat16* __restrict__ Qh, const __nv_bfloat16* __restrict__ Ql,
                  const __nv_bfloat16* __restrict__ Kh, const __nv_bfloat16* __restrict__ Kl,
                  const __nv_bfloat16* __restrict__ Vh, const __nv_bfloat16* __restrict__ Vl,
                  __nv_bfloat16* __restrict__ Oth, __nv_bfloat16* __restrict__ Otl) {
    extern __shared__ char smem[];
    const uint32_t sb = smem_u32(smem);
    const int tid = threadIdx.x;
    const int lane = tid & 31, wid = tid >> 5;
    const int b = blockIdx.y;
    const int n0 = blockIdx.x * 128;

    const size_t boN = (size_t)b * NN * CC;
    const __nv_bfloat16* qh = Qh + boN;
    const __nv_bfloat16* ql = Ql + boN;
    const __nv_bfloat16* kh = Kh + boN;
    const __nv_bfloat16* kl = Kl + boN;
    const __nv_bfloat16* vh = Vh + (size_t)b * CC * NN;
    const __nv_bfloat16* vl = Vl + (size_t)b * CC * NN;

    // load Q (once): 128 rows x 32 segs of 16B, hi+lo
    for (int i = tid; i < 128 * 32; i += 256) {
        const int r = i >> 5, seg = i & 31;
        const uint32_t d = sb + r * (FQ_STRIDE * 2) + seg * 16;
        const size_t g = (size_t)(n0 + r) * CC + seg * 8;
        cpa16(d + FQH, qh + g);
        cpa16(d + FQL, ql + g);
    }
    CPA_COMMIT();

    const int ga = lane >> 3;
    const int arow = ((ga & 1) << 3) + (lane & 7);
    const int akoff = (ga >> 1) << 3;
    const int brow = ((ga >> 1) << 3) + (lane & 7);
    const int bkoff = (ga & 1) << 3;

    float o[32][4];
    #pragma unroll
    for (int i = 0; i < 32; i++)
        #pragma unroll
        for (int j = 0; j < 4; j++) o[i][j] = 0.f;
    float mi0 = -CUDART_INF_F, mi1 = -CUDART_INF_F;
    float li0 = 0.f, li1 = 0.f;

    const uint32_t qbase = sb + FQH + (uint32_t)((wid * 16 + arow) * FQ_STRIDE + akoff) * 2;
    const uint32_t qlobase = qbase + (FQL - FQH);

    for (int m0 = 0; m0 < NN; m0 += 32) {
        // load K tile (32 rows x 256c) and V tile (256 rows x 32m), hi+lo
        for (int i = tid; i < 1024; i += 256) {
            const int r = i >> 5, seg = i & 31;
            const uint32_t d = sb + FKH + r * (FQ_STRIDE * 2) + seg * 16;
            const size_t g = (size_t)(m0 + r) * CC + seg * 8;
            cpa16(d, kh + g);
            cpa16(d + (FKL - FKH), kl + g);
        }
        for (int i = tid; i < 1024; i += 256) {
            const int r = i >> 2, seg = i & 3;
            const uint32_t d = sb + FVH + r * (FV_STRIDE * 2) + seg * 16;
            const size_t g = (size_t)r * NN + m0 + seg * 8;
            cpa16(d, vh + g);
            cpa16(d + (FVL - FVH), vl + g);
        }
        CPA_COMMIT();
        CPA_WAIT0();
        __syncthreads();

        // ---- S = Q . K^T  (16 rows x 32 m per warp) ----
        float s[4][4];
        #pragma unroll
        for (int t = 0; t < 4; t++)
            #pragma unroll
            for (int e = 0; e < 4; e++) s[t][e] = 0.f;

        #pragma unroll
        for (int ks = 0; ks < 256; ks += 16) {
            uint32_t qhf[4], qlf[4];
            ldm4(qhf, qbase + ks * 2);
            ldm4(qlf, qlobase + ks * 2);
            uint32_t khf[2][4], klf[2][4];
            #pragma unroll
            for (int g = 0; g < 2; g++) {
                const uint32_t off = sb + FKH + (uint32_t)((g * 16 + brow) * FQ_STRIDE + ks + bkoff) * 2;
                ldm4(khf[g], off);
                ldm4(klf[g], off + (FKL - FKH));
            }
            #pragma unroll
            for (int g = 0; g < 2; g++)
                #pragma unroll
                for (int h = 0; h < 2; h++) {
                    const int t = g * 2 + h;
                    mma16816(s[t], qhf, khf[g][h * 2], khf[g][h * 2 + 1]);
                    mma16816(s[t], qhf, klf[g][h * 2], klf[g][h * 2 + 1]);
                    mma16816(s[t], qlf, khf[g][h * 2], khf[g][h * 2 + 1]);
                }
        }

        // scale
        #pragma unroll
        for (int t = 0; t < 4; t++)
            #pragma unroll
            for (int e = 0; e < 4; e++) s[t][e] *= ATTN_SCALE;

        // ---- online softmax ----
        float mn0 = -CUDART_INF_F, mn1 = -CUDART_INF_F;
        #pragma unroll
        for (int t = 0; t < 4; t++) {
            mn0 = fmaxf(mn0, fmaxf(s[t][0], s[t][1]));
            mn1 = fmaxf(mn1, fmaxf(s[t][2], s[t][3]));
        }
        mn0 = fmaxf(mn0, __shfl_xor_sync(0xffffffffu, mn0, 1));
        mn0 = fmaxf(mn0, __shfl_xor_sync(0xffffffffu, mn0, 2));
        mn1 = fmaxf(mn1, __shfl_xor_sync(0xffffffffu, mn1, 1));
        mn1 = fmaxf(mn1, __shfl_xor_sync(0xffffffffu, mn1, 2));
        const float mnew0 = fmaxf(mi0, mn0);
        const float mnew1 = fmaxf(mi1, mn1);
        const float sc0 = __expf(mi0 - mnew0);
        const float sc1 = __expf(mi1 - mnew1);
        mi0 = mnew0; mi1 = mnew1;
        li0 *= sc0; li1 *= sc1;
        if (sc0 < 1.f) {
            #pragma unroll
            for (int ct = 0; ct < 32; ct++) { o[ct][0] *= sc0; o[ct][1] *= sc0; }
        }
        if (sc1 < 1.f) {
            #pragma unroll
            for (int ct = 0; ct < 32; ct++) { o[ct][2] *= sc1; o[ct][3] *= sc1; }
        }
        #pragma unroll
        for (int t = 0; t < 4; t++) {
            s[t][0] = __expf(s[t][0] - mi0);
            s[t][1] = __expf(s[t][1] - mi0);
            s[t][2] = __expf(s[t][2] - mi1);
            s[t][3] = __expf(s[t][3] - mi1);
            li0 += s[t][0] + s[t][1];
            li1 += s[t][2] + s[t][3];
        }

        // ---- P -> A fragments (hi/lo) ----
        // ktile kt covers m cols 16kt..16kt+15 from S tiles t0=2kt, t1=2kt+1.
        uint32_t pah[2][4], pal[2][4];
        #pragma unroll
        for (int kt = 0; kt < 2; kt++) {
            const int t0 = kt * 2, t1 = t0 + 1;
            float hv[4][2];
            const float* src4[4] = { s[t0], s[t0] + 2, s[t1], s[t1] + 2 };
            #pragma unroll
            for (int q = 0; q < 4; q++) {
                float a = src4[q][0], bq_ = src4[q][1];
                __nv_bfloat162 hp;
                hp.x = __float2bfloat16(a);
                hp.y = __float2bfloat16(bq_);
                pah[kt][q] = *(uint32_t*)&hp;
                hv[q][0] = a - __bfloat162float(hp.x);
                hv[q][1] = bq_ - __bfloat162float(hp.y);
            }
            #pragma unroll
            for (int q = 0; q < 4; q++)
                pal[kt][q] = pack_bf16(hv[q][0], hv[q][1]);
        }

        // ---- O += P . V ----
        #pragma unroll
        for (int cg = 0; cg < 16; cg++) {
            const uint32_t vb = sb + FVH + (uint32_t)((cg * 16 + brow) * FV_STRIDE + bkoff) * 2;
            #pragma unroll
            for (int kt = 0; kt < 2; kt++) {
                uint32_t vfh[4], vfl[4];
                ldm4(vfh, vb + kt * 32);
                ldm4(vfl, vb + kt * 32 + (FVL - FVH));
                #pragma unroll
                for (int h = 0; h < 2; h++) {
                    float* oc = o[cg * 2 + h];
                    mma16816(oc, pah[kt], vfh[h * 2], vfh[h * 2 + 1]);
                    mma16816(oc, pah[kt], vfl[h * 2], vfl[h * 2 + 1]);
                    mma16816(oc, pal[kt], vfh[h * 2], vfh[h * 2 + 1]);
                }
            }
        }
        __syncthreads();
    }

    // final normalize + write
    li0 += __shfl_xor_sync(0xffffffffu, li0, 1);
    li0 += __shfl_xor_sync(0xffffffffu, li0, 2);
    li1 += __shfl_xor_sync(0xffffffffu, li1, 1);
    li1 += __shfl_xor_sync(0xffffffffu, li1, 2);
    const float inv0 = 1.f / li0;
    const float inv1 = 1.f / li1;

    const int r0 = n0 + wid * 16 + (lane >> 2);
    #pragma unroll
    for (int ct = 0; ct < 32; ct++) {
        const int col = ct * 8 + ((lane & 3) << 1);
        float v0 = o[ct][0] * inv0, v1 = o[ct][1] * inv0;
        float v2 = o[ct][2] * inv1, v3 = o[ct][3] * inv1;
        __nv_bfloat162 h0, l0, h1, l1;
        h0.x = __float2bfloat16(v0); h0.y = __float2bfloat16(v1);
        l0.x = __float2bfloat16(v0 - __bfloat162float(h0.x));
        l0.y = __float2bfloat16(v1 - __bfloat162float(h0.y));
        h1.x = __float2bfloat16(v2); h1.y = __float2bfloat16(v3);
        l1.x = __float2bfloat16(v2 - __bfloat162float(h1.x));
        l1.y = __float2bfloat16(v3 - __bfloat162float(h1.y));
        const size_t off0 = boN + (size_t)r0 * CC + col;
        const size_t off1 = boN + (size_t)(r0 + 8) * CC + col;
        *(__nv_bfloat162*)&Oth[off0] = h0;
        *(__nv_bfloat162*)&Otl[off0] = l0;
        *(__nv_bfloat162*)&Oth[off1] = h1;
        *(__nv_bfloat162*)&Otl[off1] = l1;
    }
}

// ---------------- launch ----------------
extern "C" void kernel_launch(void* const* d_in, const int* in_sizes, int n_in,
                              void* d_out, int out_size) {
    const float* input = (const float*)d_in[0];
    const float* gns   = (const float*)d_in[1];
    const float* gnb   = (const float*)d_in[2];
    const float* Wq    = (const float*)d_in[3];
    const float* bq    = (const float*)d_in[4];
    const float* Wk    = (const float*)d_in[5];
    const float* bk    = (const float*)d_in[6];
    const float* Wv    = (const float*)d_in[7];
    const float* bv    = (const float*)d_in[8];
    const float* Wo    = (const float*)d_in[9];
    const float* bo    = (const float*)d_in[10];
    float* out = (float*)d_out;

    float* phf;
    cudaGetSymbolAddress((void**)&phf, g_h);
    __nv_bfloat16 *hth, *htl, *wh, *wl, *qh, *ql, *kh, *kl, *vh, *vl, *oth, *otl;
    cudaGetSymbolAddress((void**)&hth, g_ht_hi);
    cudaGetSymbolAddress((void**)&htl, g_ht_lo);
    cudaGetSymbolAddress((void**)&wh, g_w_hi);
    cudaGetSymbolAddress((void**)&wl, g_w_lo);
    cudaGetSymbolAddress((void**)&qh, g_qt_hi);
    cudaGetSymbolAddress((void**)&ql, g_qt_lo);
    cudaGetSymbolAddress((void**)&kh, g_kt_hi);
    cudaGetSymbolAddress((void**)&kl, g_kt_lo);
    cudaGetSymbolAddress((void**)&vh, g_v_hi);
    cudaGetSymbolAddress((void**)&vl, g_v_lo);
    cudaGetSymbolAddress((void**)&oth, g_ot_hi);
    cudaGetSymbolAddress((void**)&otl, g_ot_lo);

    cudaFuncSetAttribute(gemm_hilo_kernel<1, 2, false>, cudaFuncAttributeMaxDynamicSharedMemorySize, GEMM_SMEM);
    cudaFuncSetAttribute(gemm_hilo_kernel<1, 1, false>, cudaFuncAttributeMaxDynamicSharedMemorySize, GEMM_SMEM);
    cudaFuncSetAttribute(gemm_hilo_kernel<0, 1, true>, cudaFuncAttributeMaxDynamicSharedMemorySize, GEMM_SMEM);
    cudaFuncSetAttribute(flash_kernel, cudaFuncAttributeMaxDynamicSharedMemorySize, FLASH_SMEM);

    const size_t WSZ = (size_t)CC * CC;

    // 1) GroupNorm + weight splits
    gn_kernel<<<BB * NG, 1024>>>(input, gns, gnb);
    split_kernel<<<64, 256>>>(Wq, wh + 0 * WSZ, wl + 0 * WSZ, CC * CC);
    split_kernel<<<64, 256>>>(Wk, wh + 1 * WSZ, wl + 1 * WSZ, CC * CC);
    split_kernel<<<64, 256>>>(Wv, wh + 2 * WSZ, wl + 2 * WSZ, CC * CC);
    split_kernel<<<64, 256>>>(Wo, wh + 3 * WSZ, wl + 3 * WSZ, CC * CC);

    // 2) h -> hT hi/lo
    dim3 gt(NN / 32, CC / 32, BB);
    tconv_kernel<<<gt, dim3(32, 8)>>>(phf, hth, htl);

    // 3) projections (tensor cores)
    dim3 gq(CC / 128, NN / 128, BB);
    gemm_hilo_kernel<1, 2, false><<<gq, 256, GEMM_SMEM>>>(
        hth, htl, wh + 0 * WSZ, wl + 0 * WSZ,
        CC, CC, (size_t)NN * CC, 0,
        nullptr, qh, ql, CC, (size_t)NN * CC, bq, nullptr, CC, 1.0f);
    gemm_hilo_kernel<1, 2, false><<<gq, 256, GEMM_SMEM>>>(
        hth, htl, wh + 1 * WSZ, wl + 1 * WSZ,
        CC, CC, (size_t)NN * CC, 0,
        nullptr, kh, kl, CC, (size_t)NN * CC, bk, nullptr, CC, 1.0f);
    dim3 gv(NN / 128, CC / 128, BB);
    gemm_hilo_kernel<1, 1, false><<<gv, 256, GEMM_SMEM>>>(
        wh + 2 * WSZ, wl + 2 * WSZ, hth, htl,
        CC, CC, 0, (size_t)NN * CC,
        nullptr, vh, vl, NN, (size_t)CC * NN, bv, nullptr, CC, 1.0f);

    // 4) fused flash attention -> Ot hi/lo
    dim3 gfl(NN / 128, BB);
    flash_kernel<<<gfl, 256, FLASH_SMEM>>>(qh, ql, kh, kl, vh, vl, oth, otl);

    // 5) final: out = Wo . Ot^T + bo + residual
    dim3 gf(NN / 128, CC / 128, BB);
    gemm_hilo_kernel<0, 1, true><<<gf, 256, GEMM_SMEM>>>(
        wh + 3 * WSZ, wl + 3 * WSZ, oth, otl,
        CC, CC, 0, (size_t)NN * CC,
        out, nullptr, nullptr, NN, (size_t)CC * NN, bo, input, CC, 1.0f);
}

// round 8
// speedup vs baseline: 4.9307x; 1.4446x over previous
#include <cuda_runtime.h>
#include <cuda_bf16.h>
#include <cuda_fp16.h>
#include <math_constants.h>
#include <cstdint>

// Problem constants
#define BB 4
#define CC 256
#define NN 4096
#define NG 8
#define CPG 32
#define EPSV 1e-5f
#define ATTN_SCALE 0.0625f  // 1/sqrt(256)

// mma GEMM smem geometry (projection GEMMs)
#define GROW 40
#define MATB (128 * GROW * 2)
#define BUFB (4 * MATB)
#define GEMM_SMEM (2 * BUFB)

// flash kernel smem geometry (bytes)
#define FQ_STRIDE 264               // Q/K smem row stride in fp16 elems (528B)
#define FV_STRIDE 40                // V smem row stride in fp16 elems (80B)
#define FQH 0
#define FQL (FQH + 128 * FQ_STRIDE * 2)       // 67584
#define FK0 (FQL + 128 * FQ_STRIDE * 2)       // 135168
#define FK1 (FK0 + 32 * FQ_STRIDE * 2)        // 152064
#define FV0 (FK1 + 32 * FQ_STRIDE * 2)        // 168960
#define FV1 (FV0 + 256 * FV_STRIDE * 2)       // 189440
#define FLASH_SMEM (FV1 + 256 * FV_STRIDE * 2)  // 209920

// ---------------- static scratch (allocation-free) ----------------
__device__ __align__(16) float g_h[BB * CC * NN];              // groupnorm out fp32
__device__ __align__(16) __nv_bfloat16 g_ht_hi[BB * NN * CC];  // h^T [b][n][c]
__device__ __align__(16) __nv_bfloat16 g_ht_lo[BB * NN * CC];
__device__ __align__(16) __nv_bfloat16 g_w_hi[4 * CC * CC];    // Wq,Wk,Wv,Wo
__device__ __align__(16) __nv_bfloat16 g_w_lo[4 * CC * CC];
__device__ __align__(16) __half g_q16h[BB * NN * CC];          // q^T [b][n][o] fp16 hi
__device__ __align__(16) __half g_q16l[BB * NN * CC];          // fp16 lo
__device__ __align__(16) __half g_k16[BB * NN * CC];           // k^T [b][m][o] fp16
__device__ __align__(16) __half g_v16[BB * CC * NN];           // v [b][o][m] fp16
__device__ __align__(16) __nv_bfloat16 g_ot_hi[BB * NN * CC];  // Ot [b][n][c]
__device__ __align__(16) __nv_bfloat16 g_ot_lo[BB * NN * CC];

// ================= PTX helpers (sm_100-safe) =================
__device__ __forceinline__ uint32_t smem_u32(const void* p) {
    uint32_t a;
    asm("{ .reg .u64 t; cvta.to.shared.u64 t, %1; cvt.u32.u64 %0, t; }" : "=r"(a) : "l"(p));
    return a;
}
__device__ __forceinline__ void ldm4(uint32_t r[4], uint32_t addr) {
    asm volatile("ldmatrix.sync.aligned.m8n8.x4.shared.b16 {%0,%1,%2,%3}, [%4];"
                 : "=r"(r[0]), "=r"(r[1]), "=r"(r[2]), "=r"(r[3]) : "r"(addr));
}
__device__ __forceinline__ void mma16816(float c[4], const uint32_t a[4],
                                         uint32_t b0, uint32_t b1) {
    asm volatile("mma.sync.aligned.m16n8k16.row.col.f32.bf16.bf16.f32 "
                 "{%0,%1,%2,%3}, {%4,%5,%6,%7}, {%8,%9}, {%0,%1,%2,%3};"
                 : "+f"(c[0]), "+f"(c[1]), "+f"(c[2]), "+f"(c[3])
                 : "r"(a[0]), "r"(a[1]), "r"(a[2]), "r"(a[3]), "r"(b0), "r"(b1));
}
__device__ __forceinline__ void mma16816h(float c[4], const uint32_t a[4],
                                          uint32_t b0, uint32_t b1) {
    asm volatile("mma.sync.aligned.m16n8k16.row.col.f32.f16.f16.f32 "
                 "{%0,%1,%2,%3}, {%4,%5,%6,%7}, {%8,%9}, {%0,%1,%2,%3};"
                 : "+f"(c[0]), "+f"(c[1]), "+f"(c[2]), "+f"(c[3])
                 : "r"(a[0]), "r"(a[1]), "r"(a[2]), "r"(a[3]), "r"(b0), "r"(b1));
}
__device__ __forceinline__ void cpa16(uint32_t dst, const void* src) {
    asm volatile("cp.async.cg.shared.global [%0], [%1], 16;" :: "r"(dst), "l"(src));
}
#define CPA_COMMIT() asm volatile("cp.async.commit_group;" ::: "memory")
#define CPA_WAIT1()  asm volatile("cp.async.wait_group 1;" ::: "memory")
#define CPA_WAIT0()  asm volatile("cp.async.wait_group 0;" ::: "memory")

__device__ __forceinline__ uint32_t pack_h2(float a, float b) {
    __half2 h;
    h.x = __float2half_rn(a);
    h.y = __float2half_rn(b);
    return *(uint32_t*)&h;
}

// ---------------- GroupNorm ----------------
__global__ void gn_kernel(const float* __restrict__ x,
                          const float* __restrict__ sc,
                          const float* __restrict__ bi) {
    const int bg = blockIdx.x;
    const int b = bg >> 3, g = bg & 7;
    const size_t base = ((size_t)b * CC + (size_t)g * CPG) * (size_t)NN;
    const float* xp = x + base;
    const int M4 = (CPG * NN) / 4;

    float s = 0.f, ss = 0.f;
    for (int i = threadIdx.x; i < M4; i += blockDim.x) {
        float4 v = ((const float4*)xp)[i];
        s += v.x + v.y + v.z + v.w;
        ss += v.x * v.x + v.y * v.y + v.z * v.z + v.w * v.w;
    }
    __shared__ float rs[1024], rq[1024];
    rs[threadIdx.x] = s; rq[threadIdx.x] = ss;
    __syncthreads();
    for (int st = 512; st > 0; st >>= 1) {
        if (threadIdx.x < st) { rs[threadIdx.x] += rs[threadIdx.x + st]; rq[threadIdx.x] += rq[threadIdx.x + st]; }
        __syncthreads();
    }
    const float Mf = (float)(CPG * NN);
    const float mean = rs[0] / Mf;
    const float var = rq[0] / Mf - mean * mean;
    const float inv = rsqrtf(var + EPSV);

    float4* outp = (float4*)(g_h + base);
    for (int i = threadIdx.x; i < M4; i += blockDim.x) {
        const int c = g * CPG + (i >> 10);
        const float a = inv * sc[c];
        const float d = bi[c] - mean * a;
        float4 v = ((const float4*)xp)[i];
        v.x = v.x * a + d; v.y = v.y * a + d; v.z = v.z * a + d; v.w = v.w * a + d;
        outp[i] = v;
    }
}

// ---------------- transpose + hi/lo split (h) ----------------
__global__ void tconv_kernel(const float* __restrict__ src,
                             __nv_bfloat16* __restrict__ dhi,
                             __nv_bfloat16* __restrict__ dlo) {
    __shared__ float t[32][33];
    const int b = blockIdx.z;
    const int n0 = blockIdx.x * 32;
    const int c0 = blockIdx.y * 32;
    const int tx = threadIdx.x, ty = threadIdx.y;  // (32, 8)
    const float* s = src + (size_t)b * CC * NN;
    #pragma unroll
    for (int k = 0; k < 4; k++)
        t[ty + 8 * k][tx] = s[(size_t)(c0 + ty + 8 * k) * NN + n0 + tx];
    __syncthreads();
    const size_t base = (size_t)b * NN * CC;
    #pragma unroll
    for (int k = 0; k < 4; k++) {
        const int n = n0 + ty + 8 * k;
        const float val = t[tx][ty + 8 * k];
        __nv_bfloat16 hi = __float2bfloat16(val);
        __nv_bfloat16 lo = __float2bfloat16(val - __bfloat162float(hi));
        dhi[base + (size_t)n * CC + c0 + tx] = hi;
        dlo[base + (size_t)n * CC + c0 + tx] = lo;
    }
}

// ---------------- elementwise hi/lo split (weights) ----------------
__global__ void split_kernel(const float* __restrict__ src,
                             __nv_bfloat16* __restrict__ dhi,
                             __nv_bfloat16* __restrict__ dlo, int n) {
    for (int i = blockIdx.x * blockDim.x + threadIdx.x; i < n; i += gridDim.x * blockDim.x) {
        float val = src[i];
        __nv_bfloat16 hi = __float2bfloat16(val);
        dhi[i] = hi;
        dlo[i] = __float2bfloat16(val - __bfloat162float(hi));
    }
}

// ============================================================================
// hi/lo bf16 GEMM (projections + final)
// OUTMODE: 0 = fp32; 1 = bf16 hi/lo; 2 = fp16 hi/lo; 3 = fp16 hi only
// BIASMODE: 0 none; 1 bias[row]; 2 bias[col]
// ============================================================================
template<int OUTMODE, int BIASMODE, bool DO_RES>
__global__ __launch_bounds__(256, 1)
void gemm_hilo_kernel(const __nv_bfloat16* __restrict__ Ah, const __nv_bfloat16* __restrict__ Al,
                      const __nv_bfloat16* __restrict__ Bh, const __nv_bfloat16* __restrict__ Bl,
                      size_t ldA, size_t ldB, size_t strA, size_t strB,
                      float* __restrict__ OutF,
                      void* __restrict__ Oh, void* __restrict__ Ol,
                      size_t ldOut, size_t strOut,
                      const float* __restrict__ bias, const float* __restrict__ res,
                      int K, float scale) {
    extern __shared__ char smem[];
    const uint32_t sb = smem_u32(smem);
    const int tid = threadIdx.x;
    const int lane = tid & 31, wid = tid >> 5;
    const int warpM = wid & 3, warpN = wid >> 2;
    const int bz = blockIdx.z;
    const int N0 = blockIdx.x * 128;
    const int M0 = blockIdx.y * 128;

    const __nv_bfloat16* pA[2] = { Ah + (size_t)bz * strA + (size_t)M0 * ldA,
                                   Al + (size_t)bz * strA + (size_t)M0 * ldA };
    const __nv_bfloat16* pB[2] = { Bh + (size_t)bz * strB + (size_t)N0 * ldB,
                                   Bl + (size_t)bz * strB + (size_t)N0 * ldB };

    const int ga = lane >> 3;
    const int arow = ((ga & 1) << 3) + (lane & 7);
    const int akoff = (ga >> 1) << 3;
    const int brow = ((ga >> 1) << 3) + (lane & 7);
    const int bkoff = (ga & 1) << 3;

    float acc[2][8][4];
    #pragma unroll
    for (int i = 0; i < 2; i++)
        #pragma unroll
        for (int j = 0; j < 8; j++)
            #pragma unroll
            for (int k = 0; k < 4; k++) acc[i][j][k] = 0.f;

    const int nch = K >> 5;

    #define ISSUE_COPY(bufi, kc) do {                                              \
        _Pragma("unroll")                                                          \
        for (int i_ = 0; i_ < 8; i_++) {                                           \
            int idx_ = tid + i_ * 256;                                             \
            int mat_ = idx_ >> 9;                                                  \
            int r_ = (idx_ >> 2) & 127;                                            \
            int seg_ = idx_ & 3;                                                   \
            const __nv_bfloat16* src_;                                             \
            if (mat_ < 2) src_ = pA[mat_] + (size_t)r_ * ldA + (kc) + seg_ * 8;    \
            else          src_ = pB[mat_ - 2] + (size_t)r_ * ldB + (kc) + seg_ * 8;\
            uint32_t dst_ = sb + (bufi) * BUFB + mat_ * MATB + (r_ * GROW + seg_ * 8) * 2; \
            cpa16(dst_, src_);                                                     \
        }                                                                          \
        CPA_COMMIT();                                                              \
    } while (0)

    ISSUE_COPY(0, 0);

    for (int c = 0; c < nch; c++) {
        if (c + 1 < nch) {
            ISSUE_COPY((c + 1) & 1, (c + 1) << 5);
            CPA_WAIT1();
        } else {
            CPA_WAIT0();
        }
        __syncthreads();

        const uint32_t bufb = sb + (c & 1) * BUFB;
        #pragma unroll
        for (int ks = 0; ks < 32; ks += 16) {
            uint32_t ah[2][4], al[2][4];
            #pragma unroll
            for (int mt = 0; mt < 2; mt++) {
                uint32_t off = (uint32_t)(((warpM * 32 + mt * 16 + arow) * GROW + ks + akoff) * 2);
                ldm4(ah[mt], bufb + 0 * MATB + off);
                ldm4(al[mt], bufb + 1 * MATB + off);
            }
            uint32_t bh[4][4], bl[4][4];
            #pragma unroll
            for (int ng = 0; ng < 4; ng++) {
                uint32_t off = (uint32_t)(((warpN * 64 + ng * 16 + brow) * GROW + ks + bkoff) * 2);
                ldm4(bh[ng], bufb + 2 * MATB + off);
                ldm4(bl[ng], bufb + 3 * MATB + off);
            }
            #pragma unroll
            for (int mt = 0; mt < 2; mt++)
                #pragma unroll
                for (int ng = 0; ng < 4; ng++)
                    #pragma unroll
                    for (int h = 0; h < 2; h++) {
                        const int nt = ng * 2 + h;
                        mma16816(acc[mt][nt], ah[mt], bh[ng][h * 2], bh[ng][h * 2 + 1]);
                        mma16816(acc[mt][nt], ah[mt], bl[ng][h * 2], bl[ng][h * 2 + 1]);
                        mma16816(acc[mt][nt], al[mt], bh[ng][h * 2], bh[ng][h * 2 + 1]);
                    }
        }
        __syncthreads();
    }

    #pragma unroll
    for (int mt = 0; mt < 2; mt++)
        #pragma unroll
        for (int nt = 0; nt < 8; nt++) {
            const int row0 = M0 + warpM * 32 + mt * 16 + (lane >> 2);
            const int col = N0 + warpN * 64 + nt * 8 + ((lane & 3) << 1);
            #pragma unroll
            for (int rr = 0; rr < 2; rr++) {
                const int r = row0 + rr * 8;
                float v0 = acc[mt][nt][rr * 2 + 0] * scale;
                float v1 = acc[mt][nt][rr * 2 + 1] * scale;
                if (BIASMODE == 1) { const float bb = bias[r]; v0 += bb; v1 += bb; }
                if (BIASMODE == 2) { v0 += bias[col]; v1 += bias[col + 1]; }
                const size_t off = (size_t)bz * strOut + (size_t)r * ldOut + col;
                if (DO_RES) { v0 += res[off]; v1 += res[off + 1]; }
                if (OUTMODE == 0) {
                    float2 o; o.x = v0; o.y = v1;
                    *(float2*)&OutF[off] = o;
                } else if (OUTMODE == 1) {
                    __nv_bfloat162 hpk, lpk;
                    hpk.x = __float2bfloat16(v0);
                    hpk.y = __float2bfloat16(v1);
                    lpk.x = __float2bfloat16(v0 - __bfloat162float(hpk.x));
                    lpk.y = __float2bfloat16(v1 - __bfloat162float(hpk.y));
                    *(__nv_bfloat162*)((__nv_bfloat16*)Oh + off) = hpk;
                    *(__nv_bfloat162*)((__nv_bfloat16*)Ol + off) = lpk;
                } else if (OUTMODE == 2) {
                    __half2 hpk, lpk;
                    hpk.x = __float2half_rn(v0);
                    hpk.y = __float2half_rn(v1);
                    lpk.x = __float2half_rn(v0 - __half2float(hpk.x));
                    lpk.y = __float2half_rn(v1 - __half2float(hpk.y));
                    *(__half2*)((__half*)Oh + off) = hpk;
                    *(__half2*)((__half*)Ol + off) = lpk;
                } else {
                    __half2 hpk;
                    hpk.x = __float2half_rn(v0);
                    hpk.y = __float2half_rn(v1);
                    *(__half2*)((__half*)Oh + off) = hpk;
                }
            }
        }
}

// ============================================================================
// Flash attention, 2-pass fp16:
//   S = (Qhi + Qlo) . Khi^T ;  O += (Phi + Plo) . Vhi
// K/V single fp16 tiles, double-buffered cp.async pipeline.
// ============================================================================
__global__ __launch_bounds__(256, 1)
void flash_kernel(const __half* __restrict__ Qh, const __half* __restrict__ Ql,
                  const __half* __restrict__ Kh, const __half* __restrict__ Vh,
                  __nv_bfloat16* __restrict__ Oth, __nv_bfloat16* __restrict__ Otl) {
    extern __shared__ char smem[];
    const uint32_t sb = smem_u32(smem);
    const int tid = threadIdx.x;
    const int lane = tid & 31, wid = tid >> 5;
    const int b = blockIdx.y;
    const int n0 = blockIdx.x * 128;

    const size_t boN = (size_t)b * NN * CC;
    const __half* qh = Qh + boN;
    const __half* ql = Ql + boN;
    const __half* kh = Kh + boN;
    const __half* vh = Vh + (size_t)b * CC * NN;

    // Q (hi+lo) load, once  [group 0]
    for (int i = tid; i < 128 * 32; i += 256) {
        const int r = i >> 5, seg = i & 31;
        const uint32_t d = sb + r * (FQ_STRIDE * 2) + seg * 16;
        const size_t g = (size_t)(n0 + r) * CC + seg * 8;
        cpa16(d + FQH, qh + g);
        cpa16(d + FQL, ql + g);
    }
    CPA_COMMIT();

    const uint32_t fkb[2] = { sb + FK0, sb + FK1 };
    const uint32_t fvb[2] = { sb + FV0, sb + FV1 };

    // K/V tile loader: 32 keys x 256c (K), 256c x 32m (V)
    #define LOAD_KV(bufi, mm0) do {                                                \
        for (int i = tid; i < 1024; i += 256) {                                    \
            const int r_ = i >> 5, seg_ = i & 31;                                  \
            cpa16(fkb[bufi] + r_ * (FQ_STRIDE * 2) + seg_ * 16,                    \
                  kh + (size_t)((mm0) + r_) * CC + seg_ * 8);                      \
        }                                                                          \
        for (int i = tid; i < 1024; i += 256) {                                    \
            const int r_ = i >> 2, seg_ = i & 3;                                   \
            cpa16(fvb[bufi] + r_ * (FV_STRIDE * 2) + seg_ * 16,                    \
                  vh + (size_t)r_ * NN + (mm0) + seg_ * 8);                        \
        }                                                                          \
        CPA_COMMIT();                                                              \
    } while (0)

    LOAD_KV(0, 0);

    const int ga = lane >> 3;
    const int arow = ((ga & 1) << 3) + (lane & 7);
    const int akoff = (ga >> 1) << 3;
    const int brow = ((ga >> 1) << 3) + (lane & 7);
    const int bkoff = (ga & 1) << 3;

    float o[32][4];
    #pragma unroll
    for (int i = 0; i < 32; i++)
        #pragma unroll
        for (int j = 0; j < 4; j++) o[i][j] = 0.f;
    float mi0 = -CUDART_INF_F, mi1 = -CUDART_INF_F;
    float li0 = 0.f, li1 = 0.f;

    const uint32_t qbase = sb + FQH + (uint32_t)((wid * 16 + arow) * FQ_STRIDE + akoff) * 2;
    const uint32_t qlobase = qbase + (FQL - FQH);

    for (int it = 0; it < 128; it++) {
        const int buf = it & 1;
        if (it + 1 < 128) {
            LOAD_KV((it + 1) & 1, (it + 1) * 32);
            CPA_WAIT1();
        } else {
            CPA_WAIT0();
        }
        __syncthreads();

        // ---- S = (Qhi+Qlo) . Khi^T ----
        float s[4][4];
        #pragma unroll
        for (int t = 0; t < 4; t++)
            #pragma unroll
            for (int e = 0; e < 4; e++) s[t][e] = 0.f;

        #pragma unroll
        for (int ks = 0; ks < 256; ks += 16) {
            uint32_t qhf[4], qlf[4];
            ldm4(qhf, qbase + ks * 2);
            ldm4(qlf, qlobase + ks * 2);
            uint32_t khf[2][4];
            #pragma unroll
            for (int g = 0; g < 2; g++)
                ldm4(khf[g], fkb[buf] + (uint32_t)((g * 16 + brow) * FQ_STRIDE + ks + bkoff) * 2);
            #pragma unroll
            for (int g = 0; g < 2; g++)
                #pragma unroll
                for (int h = 0; h < 2; h++) {
                    const int t = g * 2 + h;
                    mma16816h(s[t], qhf, khf[g][h * 2], khf[g][h * 2 + 1]);
                    mma16816h(s[t], qlf, khf[g][h * 2], khf[g][h * 2 + 1]);
                }
        }

        #pragma unroll
        for (int t = 0; t < 4; t++)
            #pragma unroll
            for (int e = 0; e < 4; e++) s[t][e] *= ATTN_SCALE;

        // ---- online softmax ----
        float mn0 = -CUDART_INF_F, mn1 = -CUDART_INF_F;
        #pragma unroll
        for (int t = 0; t < 4; t++) {
            mn0 = fmaxf(mn0, fmaxf(s[t][0], s[t][1]));
            mn1 = fmaxf(mn1, fmaxf(s[t][2], s[t][3]));
        }
        mn0 = fmaxf(mn0, __shfl_xor_sync(0xffffffffu, mn0, 1));
        mn0 = fmaxf(mn0, __shfl_xor_sync(0xffffffffu, mn0, 2));
        mn1 = fmaxf(mn1, __shfl_xor_sync(0xffffffffu, mn1, 1));
        mn1 = fmaxf(mn1, __shfl_xor_sync(0xffffffffu, mn1, 2));
        const float mnew0 = fmaxf(mi0, mn0);
        const float mnew1 = fmaxf(mi1, mn1);
        const float sc0 = __expf(mi0 - mnew0);
        const float sc1 = __expf(mi1 - mnew1);
        mi0 = mnew0; mi1 = mnew1;
        li0 *= sc0; li1 *= sc1;
        if (sc0 < 1.f) {
            #pragma unroll
            for (int ct = 0; ct < 32; ct++) { o[ct][0] *= sc0; o[ct][1] *= sc0; }
        }
        if (sc1 < 1.f) {
            #pragma unroll
            for (int ct = 0; ct < 32; ct++) { o[ct][2] *= sc1; o[ct][3] *= sc1; }
        }
        #pragma unroll
        for (int t = 0; t < 4; t++) {
            s[t][0] = __expf(s[t][0] - mi0);
            s[t][1] = __expf(s[t][1] - mi0);
            s[t][2] = __expf(s[t][2] - mi1);
            s[t][3] = __expf(s[t][3] - mi1);
            li0 += s[t][0] + s[t][1];
            li1 += s[t][2] + s[t][3];
        }

        // ---- P -> A fragments (fp16 hi/lo) ----
        uint32_t pah[2][4], pal[2][4];
        #pragma unroll
        for (int kt = 0; kt < 2; kt++) {
            const int t0 = kt * 2, t1 = t0 + 1;
            const float* src4[4] = { s[t0], s[t0] + 2, s[t1], s[t1] + 2 };
            #pragma unroll
            for (int q = 0; q < 4; q++) {
                const float a = src4[q][0], bb = src4[q][1];
                __half2 hp;
                hp.x = __float2half_rn(a);
                hp.y = __float2half_rn(bb);
                pah[kt][q] = *(uint32_t*)&hp;
                pal[kt][q] = pack_h2(a - __half2float(hp.x), bb - __half2float(hp.y));
            }
        }

        // ---- O += (Phi+Plo) . Vhi ----
        #pragma unroll
        for (int cg = 0; cg < 16; cg++) {
            const uint32_t vb = fvb[buf] + (uint32_t)((cg * 16 + brow) * FV_STRIDE + bkoff) * 2;
            #pragma unroll
            for (int kt = 0; kt < 2; kt++) {
                uint32_t vfh[4];
                ldm4(vfh, vb + kt * 32);
                #pragma unroll
                for (int h = 0; h < 2; h++) {
                    float* oc = o[cg * 2 + h];
                    mma16816h(oc, pah[kt], vfh[h * 2], vfh[h * 2 + 1]);
                    mma16816h(oc, pal[kt], vfh[h * 2], vfh[h * 2 + 1]);
                }
            }
        }
        __syncthreads();
    }

    // final normalize + write
    li0 += __shfl_xor_sync(0xffffffffu, li0, 1);
    li0 += __shfl_xor_sync(0xffffffffu, li0, 2);
    li1 += __shfl_xor_sync(0xffffffffu, li1, 1);
    li1 += __shfl_xor_sync(0xffffffffu, li1, 2);
    const float inv0 = 1.f / li0;
    const float inv1 = 1.f / li1;

    const int r0 = n0 + wid * 16 + (lane >> 2);
    #pragma unroll
    for (int ct = 0; ct < 32; ct++) {
        const int col = ct * 8 + ((lane & 3) << 1);
        float v0 = o[ct][0] * inv0, v1 = o[ct][1] * inv0;
        float v2 = o[ct][2] * inv1, v3 = o[ct][3] * inv1;
        __nv_bfloat162 h0, l0, h1, l1;
        h0.x = __float2bfloat16(v0); h0.y = __float2bfloat16(v1);
        l0.x = __float2bfloat16(v0 - __bfloat162float(h0.x));
        l0.y = __float2bfloat16(v1 - __bfloat162float(h0.y));
        h1.x = __float2bfloat16(v2); h1.y = __float2bfloat16(v3);
        l1.x = __float2bfloat16(v2 - __bfloat162float(h1.x));
        l1.y = __float2bfloat16(v3 - __bfloat162float(h1.y));
        const size_t off0 = boN + (size_t)r0 * CC + col;
        const size_t off1 = boN + (size_t)(r0 + 8) * CC + col;
        *(__nv_bfloat162*)&Oth[off0] = h0;
        *(__nv_bfloat162*)&Otl[off0] = l0;
        *(__nv_bfloat162*)&Oth[off1] = h1;
        *(__nv_bfloat162*)&Otl[off1] = l1;
    }
}

// ---------------- launch ----------------
extern "C" void kernel_launch(void* const* d_in, const int* in_sizes, int n_in,
                              void* d_out, int out_size) {
    const float* input = (const float*)d_in[0];
    const float* gns   = (const float*)d_in[1];
    const float* gnb   = (const float*)d_in[2];
    const float* Wq    = (const float*)d_in[3];
    const float* bq    = (const float*)d_in[4];
    const float* Wk    = (const float*)d_in[5];
    const float* bk    = (const float*)d_in[6];
    const float* Wv    = (const float*)d_in[7];
    const float* bv    = (const float*)d_in[8];
    const float* Wo    = (const float*)d_in[9];
    const float* bo    = (const float*)d_in[10];
    float* out = (float*)d_out;

    float* phf;
    cudaGetSymbolAddress((void**)&phf, g_h);
    __nv_bfloat16 *hth, *htl, *wh, *wl, *oth, *otl;
    __half *q16h, *q16l, *k16, *v16;
    cudaGetSymbolAddress((void**)&hth, g_ht_hi);
    cudaGetSymbolAddress((void**)&htl, g_ht_lo);
    cudaGetSymbolAddress((void**)&wh, g_w_hi);
    cudaGetSymbolAddress((void**)&wl, g_w_lo);
    cudaGetSymbolAddress((void**)&q16h, g_q16h);
    cudaGetSymbolAddress((void**)&q16l, g_q16l);
    cudaGetSymbolAddress((void**)&k16, g_k16);
    cudaGetSymbolAddress((void**)&v16, g_v16);
    cudaGetSymbolAddress((void**)&oth, g_ot_hi);
    cudaGetSymbolAddress((void**)&otl, g_ot_lo);

    cudaFuncSetAttribute(gemm_hilo_kernel<2, 2, false>, cudaFuncAttributeMaxDynamicSharedMemorySize, GEMM_SMEM);
    cudaFuncSetAttribute(gemm_hilo_kernel<3, 2, false>, cudaFuncAttributeMaxDynamicSharedMemorySize, GEMM_SMEM);
    cudaFuncSetAttribute(gemm_hilo_kernel<3, 1, false>, cudaFuncAttributeMaxDynamicSharedMemorySize, GEMM_SMEM);
    cudaFuncSetAttribute(gemm_hilo_kernel<0, 1, true>, cudaFuncAttributeMaxDynamicSharedMemorySize, GEMM_SMEM);
    cudaFuncSetAttribute(flash_kernel, cudaFuncAttributeMaxDynamicSharedMemorySize, FLASH_SMEM);

    const size_t WSZ = (size_t)CC * CC;

    // 1) GroupNorm + weight splits
    gn_kernel<<<BB * NG, 1024>>>(input, gns, gnb);
    split_kernel<<<64, 256>>>(Wq, wh + 0 * WSZ, wl + 0 * WSZ, CC * CC);
    split_kernel<<<64, 256>>>(Wk, wh + 1 * WSZ, wl + 1 * WSZ, CC * CC);
    split_kernel<<<64, 256>>>(Wv, wh + 2 * WSZ, wl + 2 * WSZ, CC * CC);
    split_kernel<<<64, 256>>>(Wo, wh + 3 * WSZ, wl + 3 * WSZ, CC * CC);

    // 2) h -> hT hi/lo
    dim3 gt(NN / 32, CC / 32, BB);
    tconv_kernel<<<gt, dim3(32, 8)>>>(phf, hth, htl);

    // 3) projections (3-pass bf16 -> fp16 outputs)
    dim3 gq(CC / 128, NN / 128, BB);
    gemm_hilo_kernel<2, 2, false><<<gq, 256, GEMM_SMEM>>>(
        hth, htl, wh + 0 * WSZ, wl + 0 * WSZ,
        CC, CC, (size_t)NN * CC, 0,
        nullptr, q16h, q16l, CC, (size_t)NN * CC, bq, nullptr, CC, 1.0f);
    gemm_hilo_kernel<3, 2, false><<<gq, 256, GEMM_SMEM>>>(
        hth, htl, wh + 1 * WSZ, wl + 1 * WSZ,
        CC, CC, (size_t)NN * CC, 0,
        nullptr, k16, nullptr, CC, (size_t)NN * CC, bk, nullptr, CC, 1.0f);
    dim3 gv(NN / 128, CC / 128, BB);
    gemm_hilo_kernel<3, 1, false><<<gv, 256, GEMM_SMEM>>>(
        wh + 2 * WSZ, wl + 2 * WSZ, hth, htl,
        CC, CC, 0, (size_t)NN * CC,
        nullptr, v16, nullptr, NN, (size_t)CC * NN, bv, nullptr, CC, 1.0f);

    // 4) fused flash attention (2-pass fp16) -> Ot bf16 hi/lo
    dim3 gfl(NN / 128, BB);
    flash_kernel<<<gfl, 256, FLASH_SMEM>>>(q16h, q16l, k16, v16, oth, otl);

    // 5) final: out = Wo . Ot^T + bo + residual (3-pass bf16)
    dim3 gf(NN / 128, CC / 128, BB);
    gemm_hilo_kernel<0, 1, true><<<gf, 256, GEMM_SMEM>>>(
        wh + 3 * WSZ, wl + 3 * WSZ, oth, otl,
        CC, CC, 0, (size_t)NN * CC,
        out, nullptr, nullptr, NN, (size_t)CC * NN, bo, input, CC, 1.0f);
}

// round 9
// speedup vs baseline: 6.4345x; 1.3050x over previous
#include <cuda_runtime.h>
#include <cuda_bf16.h>
#include <cuda_fp16.h>
#include <math_constants.h>
#include <cstdint>

// Problem constants
#define BB 4
#define CC 256
#define NN 4096
#define NG 8
#define CPG 32
#define EPSV 1e-5f
#define ATTN_SCALE 0.0625f  // 1/sqrt(256)

// gemm2h smem geometry (3 tiles, double buffered)
#define GROW 40
#define MATB (128 * GROW * 2)     // 10240
#define BUF3 (3 * MATB)           // 30720
#define GEMM_SMEM (2 * BUF3)      // 61440

// flash smem geometry
#define FQ_STRIDE 264             // 528B rows (256 fp16 + pad)
#define FV_STRIDE 72              // 144B rows (64 fp16 + pad)
#define FQ0 0
#define FK0 67584                 // 128*528
#define FK1 (FK0 + 33792)         // 64*528
#define FV0 (FK1 + 33792)         // 135168
#define FV1 (FV0 + 36864)         // 256*144
#define FLASH_SMEM (FV1 + 36864)  // 208896

// ---------------- static scratch ----------------
__device__ __align__(16) float g_part[512 * 2];               // GN partial sums
__device__ float g_mean[BB * NG];
__device__ float g_inv[BB * NG];
__device__ __align__(16) __half g_ht_hi[BB * NN * CC];        // h^T [b][n][c] fp16 hi
__device__ __align__(16) __half g_ht_lo[BB * NN * CC];        // fp16 lo
__device__ __align__(16) __half g_w_hi[4 * CC * CC];          // Wq,Wk,Wv,Wo fp16 hi
__device__ __align__(16) __half g_w_lo[4 * CC * CC];          // fp16 lo
__device__ __align__(16) __half g_q16[BB * NN * CC];          // q^T [b][n][o]
__device__ __align__(16) __half g_k16[BB * NN * CC];          // k^T [b][m][o]
__device__ __align__(16) __half g_v16[BB * CC * NN];          // v [b][o][m]
__device__ __align__(16) __half g_ot16[BB * NN * CC];         // Ot [b][n][c]

// ================= PTX helpers =================
__device__ __forceinline__ uint32_t smem_u32(const void* p) {
    uint32_t a;
    asm("{ .reg .u64 t; cvta.to.shared.u64 t, %1; cvt.u32.u64 %0, t; }" : "=r"(a) : "l"(p));
    return a;
}
__device__ __forceinline__ void ldm4(uint32_t r[4], uint32_t addr) {
    asm volatile("ldmatrix.sync.aligned.m8n8.x4.shared.b16 {%0,%1,%2,%3}, [%4];"
                 : "=r"(r[0]), "=r"(r[1]), "=r"(r[2]), "=r"(r[3]) : "r"(addr));
}
__device__ __forceinline__ void mma16816h(float c[4], const uint32_t a[4],
                                          uint32_t b0, uint32_t b1) {
    asm volatile("mma.sync.aligned.m16n8k16.row.col.f32.f16.f16.f32 "
                 "{%0,%1,%2,%3}, {%4,%5,%6,%7}, {%8,%9}, {%0,%1,%2,%3};"
                 : "+f"(c[0]), "+f"(c[1]), "+f"(c[2]), "+f"(c[3])
                 : "r"(a[0]), "r"(a[1]), "r"(a[2]), "r"(a[3]), "r"(b0), "r"(b1));
}
__device__ __forceinline__ void cpa16(uint32_t dst, const void* src) {
    asm volatile("cp.async.cg.shared.global [%0], [%1], 16;" :: "r"(dst), "l"(src));
}
#define CPA_COMMIT() asm volatile("cp.async.commit_group;" ::: "memory")
#define CPA_WAIT1()  asm volatile("cp.async.wait_group 1;" ::: "memory")
#define CPA_WAIT0()  asm volatile("cp.async.wait_group 0;" ::: "memory")

__device__ __forceinline__ uint32_t pack_h2(float a, float b) {
    __half2 h;
    h.x = __float2half_rn(a);
    h.y = __float2half_rn(b);
    return *(uint32_t*)&h;
}

// ---------------- GroupNorm stage 1: partial sums ----------------
__global__ void gnstat1_kernel(const float* __restrict__ x) {
    const int bg = blockIdx.y;      // 0..31
    const int chunk = blockIdx.x;   // 0..15
    const float* xp = x + (size_t)bg * (CPG * NN) + chunk * 8192;
    float s = 0.f, ss = 0.f;
    for (int i = threadIdx.x; i < 2048; i += 256) {
        float4 v = ((const float4*)xp)[i];
        s += v.x + v.y + v.z + v.w;
        ss += v.x * v.x + v.y * v.y + v.z * v.z + v.w * v.w;
    }
    __shared__ float rs[256], rq[256];
    rs[threadIdx.x] = s; rq[threadIdx.x] = ss;
    __syncthreads();
    for (int st = 128; st > 0; st >>= 1) {
        if (threadIdx.x < st) { rs[threadIdx.x] += rs[threadIdx.x + st]; rq[threadIdx.x] += rq[threadIdx.x + st]; }
        __syncthreads();
    }
    if (threadIdx.x == 0) {
        g_part[(bg * 16 + chunk) * 2 + 0] = rs[0];
        g_part[(bg * 16 + chunk) * 2 + 1] = rq[0];
    }
}

// ---------------- GroupNorm stage 2: finalize stats ----------------
__global__ void gnstat2_kernel() {
    const int i = threadIdx.x;  // 0..31 = bg
    float s = 0.f, ss = 0.f;
    #pragma unroll
    for (int j = 0; j < 16; j++) {
        s += g_part[(i * 16 + j) * 2 + 0];
        ss += g_part[(i * 16 + j) * 2 + 1];
    }
    const float Mf = (float)(CPG * NN);
    const float mean = s / Mf;
    const float var = ss / Mf - mean * mean;
    g_mean[i] = mean;
    g_inv[i] = rsqrtf(var + EPSV);
}

// ---------------- fused GN-apply + transpose + fp16 hi/lo split ----------------
// input [b][c][n] fp32 -> hT [b][n][c] fp16 hi/lo
__global__ void tconv_kernel(const float* __restrict__ x,
                             const float* __restrict__ sc,
                             const float* __restrict__ bi,
                             __half* __restrict__ dhi,
                             __half* __restrict__ dlo) {
    __shared__ float t[32][33];
    const int b = blockIdx.z;
    const int n0 = blockIdx.x * 32;
    const int c0 = blockIdx.y * 32;  // group-aligned (32 = CPG)
    const int tx = threadIdx.x, ty = threadIdx.y;  // (32, 8)
    const int bg = b * NG + blockIdx.y;
    const float mean = g_mean[bg];
    const float inv = g_inv[bg];
    const float* s = x + (size_t)b * CC * NN;
    #pragma unroll
    for (int k = 0; k < 4; k++)
        t[ty + 8 * k][tx] = s[(size_t)(c0 + ty + 8 * k) * NN + n0 + tx];
    __syncthreads();
    const int c = c0 + tx;
    const float a = inv * sc[c];
    const float d = bi[c] - mean * a;
    const size_t base = (size_t)b * NN * CC;
    #pragma unroll
    for (int k = 0; k < 4; k++) {
        const int n = n0 + ty + 8 * k;
        const float val = t[tx][ty + 8 * k] * a + d;
        __half hi = __float2half_rn(val);
        __half lo = __float2half_rn(val - __half2float(hi));
        dhi[base + (size_t)n * CC + c] = hi;
        dlo[base + (size_t)n * CC + c] = lo;
    }
}

// ---------------- weight hi/lo split (fp16) ----------------
__global__ void wsplit_kernel(const float* __restrict__ src,
                              __half* __restrict__ dhi,
                              __half* __restrict__ dlo, int n) {
    for (int i = blockIdx.x * blockDim.x + threadIdx.x; i < n; i += gridDim.x * blockDim.x) {
        float val = src[i];
        __half hi = __float2half_rn(val);
        dhi[i] = hi;
        dlo[i] = __float2half_rn(val - __half2float(hi));
    }
}

// ============================================================================
// 2-pass fp16 GEMM: Out[i][j] = scale * sum_k (Ah+Al)[i][k] * Bh[j][k]
// OUTMODE: 0 = fp32; 1 = fp16 single
// BIASMODE: 0 none; 1 bias[row]; 2 bias[col]
// ============================================================================
template<int OUTMODE, int BIASMODE, bool DO_RES>
__global__ __launch_bounds__(256, 1)
void gemm2h_kernel(const __half* __restrict__ Ah, const __half* __restrict__ Al,
                   const __half* __restrict__ Bh,
                   size_t ldA, size_t ldB, size_t strA, size_t strB,
                   float* __restrict__ OutF, __half* __restrict__ Oh,
                   size_t ldOut, size_t strOut,
                   const float* __restrict__ bias, const float* __restrict__ res,
                   int K, float scale) {
    extern __shared__ char smem[];
    const uint32_t sb = smem_u32(smem);
    const int tid = threadIdx.x;
    const int lane = tid & 31, wid = tid >> 5;
    const int warpM = wid & 3, warpN = wid >> 2;
    const int bz = blockIdx.z;
    const int N0 = blockIdx.x * 128;
    const int M0 = blockIdx.y * 128;

    const __half* pA[2] = { Ah + (size_t)bz * strA + (size_t)M0 * ldA,
                            Al + (size_t)bz * strA + (size_t)M0 * ldA };
    const __half* pB = Bh + (size_t)bz * strB + (size_t)N0 * ldB;

    const int ga = lane >> 3;
    const int arow = ((ga & 1) << 3) + (lane & 7);
    const int akoff = (ga >> 1) << 3;
    const int brow = ((ga >> 1) << 3) + (lane & 7);
    const int bkoff = (ga & 1) << 3;

    float acc[2][8][4];
    #pragma unroll
    for (int i = 0; i < 2; i++)
        #pragma unroll
        for (int j = 0; j < 8; j++)
            #pragma unroll
            for (int k = 0; k < 4; k++) acc[i][j][k] = 0.f;

    const int nch = K >> 5;

    #define ISSUE_COPY3(bufi, kc) do {                                             \
        _Pragma("unroll")                                                          \
        for (int i_ = 0; i_ < 6; i_++) {                                           \
            int idx_ = tid + i_ * 256;                                             \
            int mat_ = idx_ >> 9;                                                  \
            int r_ = (idx_ >> 2) & 127;                                            \
            int seg_ = idx_ & 3;                                                   \
            const __half* src_;                                                    \
            if (mat_ < 2) src_ = pA[mat_] + (size_t)r_ * ldA + (kc) + seg_ * 8;    \
            else          src_ = pB + (size_t)r_ * ldB + (kc) + seg_ * 8;          \
            uint32_t dst_ = sb + (bufi) * BUF3 + mat_ * MATB + (r_ * GROW + seg_ * 8) * 2; \
            cpa16(dst_, src_);                                                     \
        }                                                                          \
        CPA_COMMIT();                                                              \
    } while (0)

    ISSUE_COPY3(0, 0);

    for (int c = 0; c < nch; c++) {
        if (c + 1 < nch) {
            ISSUE_COPY3((c + 1) & 1, (c + 1) << 5);
            CPA_WAIT1();
        } else {
            CPA_WAIT0();
        }
        __syncthreads();

        const uint32_t bufb = sb + (c & 1) * BUF3;
        #pragma unroll
        for (int ks = 0; ks < 32; ks += 16) {
            uint32_t ah[2][4], al[2][4];
            #pragma unroll
            for (int mt = 0; mt < 2; mt++) {
                uint32_t off = (uint32_t)(((warpM * 32 + mt * 16 + arow) * GROW + ks + akoff) * 2);
                ldm4(ah[mt], bufb + 0 * MATB + off);
                ldm4(al[mt], bufb + 1 * MATB + off);
            }
            uint32_t bh[4][4];
            #pragma unroll
            for (int ng = 0; ng < 4; ng++) {
                uint32_t off = (uint32_t)(((warpN * 64 + ng * 16 + brow) * GROW + ks + bkoff) * 2);
                ldm4(bh[ng], bufb + 2 * MATB + off);
            }
            #pragma unroll
            for (int mt = 0; mt < 2; mt++)
                #pragma unroll
                for (int ng = 0; ng < 4; ng++)
                    #pragma unroll
                    for (int h = 0; h < 2; h++) {
                        const int nt = ng * 2 + h;
                        mma16816h(acc[mt][nt], ah[mt], bh[ng][h * 2], bh[ng][h * 2 + 1]);
                        mma16816h(acc[mt][nt], al[mt], bh[ng][h * 2], bh[ng][h * 2 + 1]);
                    }
        }
        __syncthreads();
    }

    #pragma unroll
    for (int mt = 0; mt < 2; mt++)
        #pragma unroll
        for (int nt = 0; nt < 8; nt++) {
            const int row0 = M0 + warpM * 32 + mt * 16 + (lane >> 2);
            const int col = N0 + warpN * 64 + nt * 8 + ((lane & 3) << 1);
            #pragma unroll
            for (int rr = 0; rr < 2; rr++) {
                const int r = row0 + rr * 8;
                float v0 = acc[mt][nt][rr * 2 + 0] * scale;
                float v1 = acc[mt][nt][rr * 2 + 1] * scale;
                if (BIASMODE == 1) { const float bb = bias[r]; v0 += bb; v1 += bb; }
                if (BIASMODE == 2) { v0 += bias[col]; v1 += bias[col + 1]; }
                const size_t off = (size_t)bz * strOut + (size_t)r * ldOut + col;
                if (DO_RES) { v0 += res[off]; v1 += res[off + 1]; }
                if (OUTMODE == 0) {
                    float2 o; o.x = v0; o.y = v1;
                    *(float2*)&OutF[off] = o;
                } else {
                    __half2 hp;
                    hp.x = __float2half_rn(v0);
                    hp.y = __float2half_rn(v1);
                    *(__half2*)&Oh[off] = hp;
                }
            }
        }
}

// ============================================================================
// Flash attention: 128 queries x 64-key tiles.
//   S = Qhi . Khi^T (1-pass); online softmax; O += (Phi+Plo) . Vhi (2-pass)
// ============================================================================
__global__ __launch_bounds__(256, 1)
void flash_kernel(const __half* __restrict__ Qh, const __half* __restrict__ Kh,
                  const __half* __restrict__ Vh, __half* __restrict__ Ot) {
    extern __shared__ char smem[];
    const uint32_t sb = smem_u32(smem);
    const int tid = threadIdx.x;
    const int lane = tid & 31, wid = tid >> 5;
    const int b = blockIdx.y;
    const int n0 = blockIdx.x * 128;

    const size_t boN = (size_t)b * NN * CC;
    const __half* qh = Qh + boN;
    const __half* kh = Kh + boN;
    const __half* vh = Vh + (size_t)b * CC * NN;

    // Q load (once)
    for (int i = tid; i < 128 * 32; i += 256) {
        const int r = i >> 5, seg = i & 31;
        cpa16(sb + FQ0 + r * 528 + seg * 16, qh + (size_t)(n0 + r) * CC + seg * 8);
    }
    CPA_COMMIT();

    const uint32_t fkb[2] = { sb + FK0, sb + FK1 };
    const uint32_t fvb[2] = { sb + FV0, sb + FV1 };

    #define LOAD_KV64(bufi, mm0) do {                                              \
        for (int i = tid; i < 2048; i += 256) {                                    \
            const int r_ = i >> 5, seg_ = i & 31;                                  \
            cpa16(fkb[bufi] + r_ * 528 + seg_ * 16,                                \
                  kh + (size_t)((mm0) + r_) * CC + seg_ * 8);                      \
        }                                                                          \
        for (int i = tid; i < 2048; i += 256) {                                    \
            const int r_ = i >> 3, seg_ = i & 7;                                   \
            cpa16(fvb[bufi] + r_ * 144 + seg_ * 16,                                \
                  vh + (size_t)r_ * NN + (mm0) + seg_ * 8);                        \
        }                                                                          \
        CPA_COMMIT();                                                              \
    } while (0)

    LOAD_KV64(0, 0);

    const int ga = lane >> 3;
    const int arow = ((ga & 1) << 3) + (lane & 7);
    const int akoff = (ga >> 1) << 3;
    const int brow = ((ga >> 1) << 3) + (lane & 7);
    const int bkoff = (ga & 1) << 3;

    float o[32][4];
    #pragma unroll
    for (int i = 0; i < 32; i++)
        #pragma unroll
        for (int j = 0; j < 4; j++) o[i][j] = 0.f;
    float mi0 = -CUDART_INF_F, mi1 = -CUDART_INF_F;
    float li0 = 0.f, li1 = 0.f;

    const uint32_t qbase = sb + FQ0 + (uint32_t)((wid * 16 + arow) * FQ_STRIDE + akoff) * 2;

    for (int it = 0; it < 64; it++) {
        const int buf = it & 1;
        if (it + 1 < 64) {
            LOAD_KV64((it + 1) & 1, (it + 1) * 64);
            CPA_WAIT1();
        } else {
            CPA_WAIT0();
        }
        __syncthreads();

        // ---- S = Qhi . Khi^T : 16 rows x 64 keys per warp ----
        float s[8][4];
        #pragma unroll
        for (int t = 0; t < 8; t++)
            #pragma unroll
            for (int e = 0; e < 4; e++) s[t][e] = 0.f;

        #pragma unroll
        for (int ks = 0; ks < 256; ks += 16) {
            uint32_t qf[4];
            ldm4(qf, qbase + ks * 2);
            uint32_t kf[4][4];
            #pragma unroll
            for (int g = 0; g < 4; g++)
                ldm4(kf[g], fkb[buf] + (uint32_t)((g * 16 + brow) * FQ_STRIDE + ks + bkoff) * 2);
            #pragma unroll
            for (int g = 0; g < 4; g++)
                #pragma unroll
                for (int h = 0; h < 2; h++)
                    mma16816h(s[g * 2 + h], qf, kf[g][h * 2], kf[g][h * 2 + 1]);
        }

        #pragma unroll
        for (int t = 0; t < 8; t++)
            #pragma unroll
            for (int e = 0; e < 4; e++) s[t][e] *= ATTN_SCALE;

        // ---- online softmax ----
        float mn0 = -CUDART_INF_F, mn1 = -CUDART_INF_F;
        #pragma unroll
        for (int t = 0; t < 8; t++) {
            mn0 = fmaxf(mn0, fmaxf(s[t][0], s[t][1]));
            mn1 = fmaxf(mn1, fmaxf(s[t][2], s[t][3]));
        }
        mn0 = fmaxf(mn0, __shfl_xor_sync(0xffffffffu, mn0, 1));
        mn0 = fmaxf(mn0, __shfl_xor_sync(0xffffffffu, mn0, 2));
        mn1 = fmaxf(mn1, __shfl_xor_sync(0xffffffffu, mn1, 1));
        mn1 = fmaxf(mn1, __shfl_xor_sync(0xffffffffu, mn1, 2));
        const float mnew0 = fmaxf(mi0, mn0);
        const float mnew1 = fmaxf(mi1, mn1);
        const float sc0 = __expf(mi0 - mnew0);
        const float sc1 = __expf(mi1 - mnew1);
        mi0 = mnew0; mi1 = mnew1;
        li0 *= sc0; li1 *= sc1;
        if (sc0 < 1.f) {
            #pragma unroll
            for (int ct = 0; ct < 32; ct++) { o[ct][0] *= sc0; o[ct][1] *= sc0; }
        }
        if (sc1 < 1.f) {
            #pragma unroll
            for (int ct = 0; ct < 32; ct++) { o[ct][2] *= sc1; o[ct][3] *= sc1; }
        }
        #pragma unroll
        for (int t = 0; t < 8; t++) {
            s[t][0] = __expf(s[t][0] - mi0);
            s[t][1] = __expf(s[t][1] - mi0);
            s[t][2] = __expf(s[t][2] - mi1);
            s[t][3] = __expf(s[t][3] - mi1);
            li0 += s[t][0] + s[t][1];
            li1 += s[t][2] + s[t][3];
        }

        // ---- per 16-key chunk: build P fragments, accumulate O += P.V ----
        #pragma unroll
        for (int kt = 0; kt < 4; kt++) {
            const int t0 = kt * 2, t1 = t0 + 1;
            const float* src4[4] = { s[t0], s[t0] + 2, s[t1], s[t1] + 2 };
            uint32_t pah[4], pal[4];
            #pragma unroll
            for (int q = 0; q < 4; q++) {
                const float a = src4[q][0], bb = src4[q][1];
                __half2 hp;
                hp.x = __float2half_rn(a);
                hp.y = __float2half_rn(bb);
                pah[q] = *(uint32_t*)&hp;
                pal[q] = pack_h2(a - __half2float(hp.x), bb - __half2float(hp.y));
            }
            #pragma unroll
            for (int cg = 0; cg < 16; cg++) {
                uint32_t vf[4];
                ldm4(vf, fvb[buf] + (uint32_t)((cg * 16 + brow) * FV_STRIDE + bkoff) * 2 + kt * 32);
                #pragma unroll
                for (int h = 0; h < 2; h++) {
                    float* oc = o[cg * 2 + h];
                    mma16816h(oc, pah, vf[h * 2], vf[h * 2 + 1]);
                    mma16816h(oc, pal, vf[h * 2], vf[h * 2 + 1]);
                }
            }
        }
        __syncthreads();
    }

    // final normalize + fp16 write
    li0 += __shfl_xor_sync(0xffffffffu, li0, 1);
    li0 += __shfl_xor_sync(0xffffffffu, li0, 2);
    li1 += __shfl_xor_sync(0xffffffffu, li1, 1);
    li1 += __shfl_xor_sync(0xffffffffu, li1, 2);
    const float inv0 = 1.f / li0;
    const float inv1 = 1.f / li1;

    const int r0 = n0 + wid * 16 + (lane >> 2);
    #pragma unroll
    for (int ct = 0; ct < 32; ct++) {
        const int col = ct * 8 + ((lane & 3) << 1);
        __half2 a0, a1;
        a0.x = __float2half_rn(o[ct][0] * inv0);
        a0.y = __float2half_rn(o[ct][1] * inv0);
        a1.x = __float2half_rn(o[ct][2] * inv1);
        a1.y = __float2half_rn(o[ct][3] * inv1);
        *(__half2*)&Ot[boN + (size_t)r0 * CC + col] = a0;
        *(__half2*)&Ot[boN + (size_t)(r0 + 8) * CC + col] = a1;
    }
}

// ---------------- launch ----------------
extern "C" void kernel_launch(void* const* d_in, const int* in_sizes, int n_in,
                              void* d_out, int out_size) {
    const float* input = (const float*)d_in[0];
    const float* gns   = (const float*)d_in[1];
    const float* gnb   = (const float*)d_in[2];
    const float* Wq    = (const float*)d_in[3];
    const float* bq    = (const float*)d_in[4];
    const float* Wk    = (const float*)d_in[5];
    const float* bk    = (const float*)d_in[6];
    const float* Wv    = (const float*)d_in[7];
    const float* bv    = (const float*)d_in[8];
    const float* Wo    = (const float*)d_in[9];
    const float* bo    = (const float*)d_in[10];
    float* out = (float*)d_out;

    __half *hth, *htl, *wh, *wl, *q16, *k16, *v16, *ot16;
    cudaGetSymbolAddress((void**)&hth, g_ht_hi);
    cudaGetSymbolAddress((void**)&htl, g_ht_lo);
    cudaGetSymbolAddress((void**)&wh, g_w_hi);
    cudaGetSymbolAddress((void**)&wl, g_w_lo);
    cudaGetSymbolAddress((void**)&q16, g_q16);
    cudaGetSymbolAddress((void**)&k16, g_k16);
    cudaGetSymbolAddress((void**)&v16, g_v16);
    cudaGetSymbolAddress((void**)&ot16, g_ot16);

    cudaFuncSetAttribute(gemm2h_kernel<1, 2, false>, cudaFuncAttributeMaxDynamicSharedMemorySize, GEMM_SMEM);
    cudaFuncSetAttribute(gemm2h_kernel<1, 1, false>, cudaFuncAttributeMaxDynamicSharedMemorySize, GEMM_SMEM);
    cudaFuncSetAttribute(gemm2h_kernel<0, 1, true>, cudaFuncAttributeMaxDynamicSharedMemorySize, GEMM_SMEM);
    cudaFuncSetAttribute(flash_kernel, cudaFuncAttributeMaxDynamicSharedMemorySize, FLASH_SMEM);

    const size_t WSZ = (size_t)CC * CC;

    // 1) GroupNorm stats + weight splits
    gnstat1_kernel<<<dim3(16, 32), 256>>>(input);
    wsplit_kernel<<<64, 256>>>(Wq, wh + 0 * WSZ, wl + 0 * WSZ, CC * CC);
    wsplit_kernel<<<64, 256>>>(Wk, wh + 1 * WSZ, wl + 1 * WSZ, CC * CC);
    wsplit_kernel<<<64, 256>>>(Wv, wh + 2 * WSZ, wl + 2 * WSZ, CC * CC);
    wsplit_kernel<<<64, 256>>>(Wo, wh + 3 * WSZ, wl + 3 * WSZ, CC * CC);
    gnstat2_kernel<<<1, 32>>>();

    // 2) fused GN-apply + transpose + split
    dim3 gt(NN / 32, CC / 32, BB);
    tconv_kernel<<<gt, dim3(32, 8)>>>(input, gns, gnb, hth, htl);

    // 3) projections (2-pass fp16)
    dim3 gq(CC / 128, NN / 128, BB);
    gemm2h_kernel<1, 2, false><<<gq, 256, GEMM_SMEM>>>(
        hth, htl, wh + 0 * WSZ,
        CC, CC, (size_t)NN * CC, 0,
        nullptr, q16, CC, (size_t)NN * CC, bq, nullptr, CC, 1.0f);
    gemm2h_kernel<1, 2, false><<<gq, 256, GEMM_SMEM>>>(
        hth, htl, wh + 1 * WSZ,
        CC, CC, (size_t)NN * CC, 0,
        nullptr, k16, CC, (size_t)NN * CC, bk, nullptr, CC, 1.0f);
    dim3 gv(NN / 128, CC / 128, BB);
    gemm2h_kernel<1, 1, false><<<gv, 256, GEMM_SMEM>>>(
        wh + 2 * WSZ, wl + 2 * WSZ, hth,
        CC, CC, 0, (size_t)NN * CC,
        nullptr, v16, NN, (size_t)CC * NN, bv, nullptr, CC, 1.0f);

    // 4) flash attention -> Ot fp16
    dim3 gfl(NN / 128, BB);
    flash_kernel<<<gfl, 256, FLASH_SMEM>>>(q16, k16, v16, ot16);

    // 5) final: out = (Wo_hi+Wo_lo) . Ot^T + bo + residual (fp32 out)
    dim3 gf(NN / 128, CC / 128, BB);
    gemm2h_kernel<0, 1, true><<<gf, 256, GEMM_SMEM>>>(
        wh + 3 * WSZ, wl + 3 * WSZ, ot16,
        CC, CC, 0, (size_t)NN * CC,
        out, nullptr, NN, (size_t)CC * NN, bo, input, CC, 1.0f);
}

// round 10
// speedup vs baseline: 8.0892x; 1.2572x over previous
#include <cuda_runtime.h>
#include <cuda_fp16.h>
#include <math_constants.h>
#include <cstdint>

// Problem constants
#define BB 4
#define CC 256
#define NN 4096
#define NG 8
#define CPG 32
#define EPSV 1e-5f
#define ATTN_SCALE 0.0625f  // 1/sqrt(256)

// gemm2h smem geometry (3 tiles, double buffered)
#define GROW 40
#define MATB (128 * GROW * 2)     // 10240
#define BUF3 (3 * MATB)           // 30720
#define GEMM_SMEM (2 * BUF3)      // 61440

// flash smem geometry
#define FQ_STRIDE 264             // 528B rows (256 fp16 + pad)
#define FV_STRIDE 72              // 144B rows (64 fp16 + pad)
#define FQ0 0
#define FK0 67584                 // 128*528
#define FK1 (FK0 + 33792)         // 64*528
#define FV0 (FK1 + 33792)         // 135168
#define FV1 (FV0 + 36864)         // 256*144
#define FLASH_SMEM (FV1 + 36864)  // 208896

// ---------------- static scratch ----------------
__device__ __align__(16) float g_part[512 * 2];               // GN partial sums
__device__ float g_mean[BB * NG];
__device__ float g_inv[BB * NG];
__device__ __align__(16) __half g_ht_hi[BB * NN * CC];        // h^T [b][n][c] fp16 hi
__device__ __align__(16) __half g_ht_lo[BB * NN * CC];        // fp16 lo
__device__ __align__(16) __half g_wqk[2 * CC * CC];           // concat(Wq,Wk) hi
__device__ __align__(16) __half g_wv_hi[CC * CC];
__device__ __align__(16) __half g_wv_lo[CC * CC];
__device__ __align__(16) __half g_wo_hi[CC * CC];
__device__ __align__(16) __half g_wo_lo[CC * CC];
__device__ __align__(16) float g_bqk[2 * CC];                 // concat(bq,bk)
__device__ __align__(16) __half g_qk16[BB * NN * 2 * CC];     // qk^T [b][n][512]
__device__ __align__(16) __half g_v16[BB * CC * NN];          // v [b][o][m]
__device__ __align__(16) __half g_ot16[BB * NN * CC];         // Ot [b][n][c]

// ================= PTX helpers =================
__device__ __forceinline__ uint32_t smem_u32(const void* p) {
    uint32_t a;
    asm("{ .reg .u64 t; cvta.to.shared.u64 t, %1; cvt.u32.u64 %0, t; }" : "=r"(a) : "l"(p));
    return a;
}
__device__ __forceinline__ void ldm4(uint32_t r[4], uint32_t addr) {
    asm volatile("ldmatrix.sync.aligned.m8n8.x4.shared.b16 {%0,%1,%2,%3}, [%4];"
                 : "=r"(r[0]), "=r"(r[1]), "=r"(r[2]), "=r"(r[3]) : "r"(addr));
}
__device__ __forceinline__ void mma16816h(float c[4], const uint32_t a[4],
                                          uint32_t b0, uint32_t b1) {
    asm volatile("mma.sync.aligned.m16n8k16.row.col.f32.f16.f16.f32 "
                 "{%0,%1,%2,%3}, {%4,%5,%6,%7}, {%8,%9}, {%0,%1,%2,%3};"
                 : "+f"(c[0]), "+f"(c[1]), "+f"(c[2]), "+f"(c[3])
                 : "r"(a[0]), "r"(a[1]), "r"(a[2]), "r"(a[3]), "r"(b0), "r"(b1));
}
__device__ __forceinline__ void cpa16(uint32_t dst, const void* src) {
    asm volatile("cp.async.cg.shared.global [%0], [%1], 16;" :: "r"(dst), "l"(src));
}
#define CPA_COMMIT() asm volatile("cp.async.commit_group;" ::: "memory")
#define CPA_WAIT1()  asm volatile("cp.async.wait_group 1;" ::: "memory")
#define CPA_WAIT0()  asm volatile("cp.async.wait_group 0;" ::: "memory")

// ---------------- GroupNorm stage 1: partial sums ----------------
__global__ void gnstat1_kernel(const float* __restrict__ x) {
    const int bg = blockIdx.y;      // 0..31
    const int chunk = blockIdx.x;   // 0..15
    const float* xp = x + (size_t)bg * (CPG * NN) + chunk * 8192;
    float s = 0.f, ss = 0.f;
    for (int i = threadIdx.x; i < 2048; i += 256) {
        float4 v = ((const float4*)xp)[i];
        s += v.x + v.y + v.z + v.w;
        ss += v.x * v.x + v.y * v.y + v.z * v.z + v.w * v.w;
    }
    __shared__ float rs[256], rq[256];
    rs[threadIdx.x] = s; rq[threadIdx.x] = ss;
    __syncthreads();
    for (int st = 128; st > 0; st >>= 1) {
        if (threadIdx.x < st) { rs[threadIdx.x] += rs[threadIdx.x + st]; rq[threadIdx.x] += rq[threadIdx.x + st]; }
        __syncthreads();
    }
    if (threadIdx.x == 0) {
        g_part[(bg * 16 + chunk) * 2 + 0] = rs[0];
        g_part[(bg * 16 + chunk) * 2 + 1] = rq[0];
    }
}

// ---------------- GroupNorm stage 2: finalize stats ----------------
__global__ void gnstat2_kernel() {
    const int i = threadIdx.x;  // 0..31 = bg
    float s = 0.f, ss = 0.f;
    #pragma unroll
    for (int j = 0; j < 16; j++) {
        s += g_part[(i * 16 + j) * 2 + 0];
        ss += g_part[(i * 16 + j) * 2 + 1];
    }
    const float Mf = (float)(CPG * NN);
    const float mean = s / Mf;
    const float var = ss / Mf - mean * mean;
    g_mean[i] = mean;
    g_inv[i] = rsqrtf(var + EPSV);
}

// ---------------- all weight splits + bias concat, ONE kernel ----------------
__global__ void wsplitall_kernel(const float* __restrict__ Wq, const float* __restrict__ Wk,
                                 const float* __restrict__ Wv, const float* __restrict__ Wo,
                                 const float* __restrict__ bq, const float* __restrict__ bk) {
    const int i = blockIdx.x * blockDim.x + threadIdx.x;  // 0..65535
    if (i < CC * CC) {
        g_wqk[i] = __float2half_rn(Wq[i]);
        g_wqk[CC * CC + i] = __float2half_rn(Wk[i]);
        {
            float v = Wv[i];
            __half hi = __float2half_rn(v);
            g_wv_hi[i] = hi;
            g_wv_lo[i] = __float2half_rn(v - __half2float(hi));
        }
        {
            float v = Wo[i];
            __half hi = __float2half_rn(v);
            g_wo_hi[i] = hi;
            g_wo_lo[i] = __float2half_rn(v - __half2float(hi));
        }
        if (i < CC) g_bqk[i] = bq[i];
        else if (i < 2 * CC) g_bqk[i] = bk[i - CC];
    }
}

// ---------------- fused GN-apply + transpose + fp16 hi/lo split ----------------
__global__ void tconv_kernel(const float* __restrict__ x,
                             const float* __restrict__ sc,
                             const float* __restrict__ bi,
                             __half* __restrict__ dhi,
                             __half* __restrict__ dlo) {
    __shared__ float t[32][33];
    const int b = blockIdx.z;
    const int n0 = blockIdx.x * 32;
    const int c0 = blockIdx.y * 32;
    const int tx = threadIdx.x, ty = threadIdx.y;  // (32, 8)
    const int bg = b * NG + blockIdx.y;
    const float mean = g_mean[bg];
    const float inv = g_inv[bg];
    const float* s = x + (size_t)b * CC * NN;
    #pragma unroll
    for (int k = 0; k < 4; k++)
        t[ty + 8 * k][tx] = s[(size_t)(c0 + ty + 8 * k) * NN + n0 + tx];
    __syncthreads();
    const int c = c0 + tx;
    const float a = inv * sc[c];
    const float d = bi[c] - mean * a;
    const size_t base = (size_t)b * NN * CC;
    #pragma unroll
    for (int k = 0; k < 4; k++) {
        const int n = n0 + ty + 8 * k;
        const float val = t[tx][ty + 8 * k] * a + d;
        __half hi = __float2half_rn(val);
        __half lo = __float2half_rn(val - __half2float(hi));
        dhi[base + (size_t)n * CC + c] = hi;
        dlo[base + (size_t)n * CC + c] = lo;
    }
}

// ============================================================================
// 2-pass fp16 GEMM: Out[i][j] = scale * sum_k (Ah+Al)[i][k] * Bh[j][k]
// OUTMODE: 0 = fp32; 1 = fp16 single
// BIASMODE: 0 none; 1 bias[row]; 2 bias[col]
// ============================================================================
template<int OUTMODE, int BIASMODE, bool DO_RES>
__global__ __launch_bounds__(256, 1)
void gemm2h_kernel(const __half* __restrict__ Ah, const __half* __restrict__ Al,
                   const __half* __restrict__ Bh,
                   size_t ldA, size_t ldB, size_t strA, size_t strB,
                   float* __restrict__ OutF, __half* __restrict__ Oh,
                   size_t ldOut, size_t strOut,
                   const float* __restrict__ bias, const float* __restrict__ res,
                   int K, float scale) {
    extern __shared__ char smem[];
    const uint32_t sb = smem_u32(smem);
    const int tid = threadIdx.x;
    const int lane = tid & 31, wid = tid >> 5;
    const int warpM = wid & 3, warpN = wid >> 2;
    const int bz = blockIdx.z;
    const int N0 = blockIdx.x * 128;
    const int M0 = blockIdx.y * 128;

    const __half* pA[2] = { Ah + (size_t)bz * strA + (size_t)M0 * ldA,
                            Al + (size_t)bz * strA + (size_t)M0 * ldA };
    const __half* pB = Bh + (size_t)bz * strB + (size_t)N0 * ldB;

    const int ga = lane >> 3;
    const int arow = ((ga & 1) << 3) + (lane & 7);
    const int akoff = (ga >> 1) << 3;
    const int brow = ((ga >> 1) << 3) + (lane & 7);
    const int bkoff = (ga & 1) << 3;

    float acc[2][8][4];
    #pragma unroll
    for (int i = 0; i < 2; i++)
        #pragma unroll
        for (int j = 0; j < 8; j++)
            #pragma unroll
            for (int k = 0; k < 4; k++) acc[i][j][k] = 0.f;

    const int nch = K >> 5;

    #define ISSUE_COPY3(bufi, kc) do {                                             \
        _Pragma("unroll")                                                          \
        for (int i_ = 0; i_ < 6; i_++) {                                           \
            int idx_ = tid + i_ * 256;                                             \
            int mat_ = idx_ >> 9;                                                  \
            int r_ = (idx_ >> 2) & 127;                                            \
            int seg_ = idx_ & 3;                                                   \
            const __half* src_;                                                    \
            if (mat_ < 2) src_ = pA[mat_] + (size_t)r_ * ldA + (kc) + seg_ * 8;    \
            else          src_ = pB + (size_t)r_ * ldB + (kc) + seg_ * 8;          \
            uint32_t dst_ = sb + (bufi) * BUF3 + mat_ * MATB + (r_ * GROW + seg_ * 8) * 2; \
            cpa16(dst_, src_);                                                     \
        }                                                                          \
        CPA_COMMIT();                                                              \
    } while (0)

    ISSUE_COPY3(0, 0);

    for (int c = 0; c < nch; c++) {
        if (c + 1 < nch) {
            ISSUE_COPY3((c + 1) & 1, (c + 1) << 5);
            CPA_WAIT1();
        } else {
            CPA_WAIT0();
        }
        __syncthreads();

        const uint32_t bufb = sb + (c & 1) * BUF3;
        #pragma unroll
        for (int ks = 0; ks < 32; ks += 16) {
            uint32_t ah[2][4], al[2][4];
            #pragma unroll
            for (int mt = 0; mt < 2; mt++) {
                uint32_t off = (uint32_t)(((warpM * 32 + mt * 16 + arow) * GROW + ks + akoff) * 2);
                ldm4(ah[mt], bufb + 0 * MATB + off);
                ldm4(al[mt], bufb + 1 * MATB + off);
            }
            uint32_t bh[4][4];
            #pragma unroll
            for (int ng = 0; ng < 4; ng++) {
                uint32_t off = (uint32_t)(((warpN * 64 + ng * 16 + brow) * GROW + ks + bkoff) * 2);
                ldm4(bh[ng], bufb + 2 * MATB + off);
            }
            #pragma unroll
            for (int mt = 0; mt < 2; mt++)
                #pragma unroll
                for (int ng = 0; ng < 4; ng++)
                    #pragma unroll
                    for (int h = 0; h < 2; h++) {
                        const int nt = ng * 2 + h;
                        mma16816h(acc[mt][nt], ah[mt], bh[ng][h * 2], bh[ng][h * 2 + 1]);
                        mma16816h(acc[mt][nt], al[mt], bh[ng][h * 2], bh[ng][h * 2 + 1]);
                    }
        }
        __syncthreads();
    }

    #pragma unroll
    for (int mt = 0; mt < 2; mt++)
        #pragma unroll
        for (int nt = 0; nt < 8; nt++) {
            const int row0 = M0 + warpM * 32 + mt * 16 + (lane >> 2);
            const int col = N0 + warpN * 64 + nt * 8 + ((lane & 3) << 1);
            #pragma unroll
            for (int rr = 0; rr < 2; rr++) {
                const int r = row0 + rr * 8;
                float v0 = acc[mt][nt][rr * 2 + 0] * scale;
                float v1 = acc[mt][nt][rr * 2 + 1] * scale;
                if (BIASMODE == 1) { const float bb = bias[r]; v0 += bb; v1 += bb; }
                if (BIASMODE == 2) { v0 += bias[col]; v1 += bias[col + 1]; }
                const size_t off = (size_t)bz * strOut + (size_t)r * ldOut + col;
                if (DO_RES) { v0 += res[off]; v1 += res[off + 1]; }
                if (OUTMODE == 0) {
                    float2 o; o.x = v0; o.y = v1;
                    *(float2*)&OutF[off] = o;
                } else {
                    __half2 hp;
                    hp.x = __float2half_rn(v0);
                    hp.y = __float2half_rn(v1);
                    *(__half2*)&Oh[off] = hp;
                }
            }
        }
}

// ============================================================================
// Flash attention: 128 queries x 64-key tiles.
//   S = Q . K^T (1-pass); online softmax; O += P . V (1-pass)
// Q,K interleaved in qk[b][n][512] (Q cols 0..255, K cols 256..511).
// ============================================================================
__global__ __launch_bounds__(256, 1)
void flash_kernel(const __half* __restrict__ QK, const __half* __restrict__ Vh,
                  __half* __restrict__ Ot) {
    extern __shared__ char smem[];
    const uint32_t sb = smem_u32(smem);
    const int tid = threadIdx.x;
    const int lane = tid & 31, wid = tid >> 5;
    const int b = blockIdx.y;
    const int n0 = blockIdx.x * 128;

    const __half* qh = QK + (size_t)b * NN * 512;
    const __half* kh = qh + 256;
    const __half* vh = Vh + (size_t)b * CC * NN;
    const size_t boN = (size_t)b * NN * CC;

    // Q load (once): rows have stride 512 in gmem
    for (int i = tid; i < 128 * 32; i += 256) {
        const int r = i >> 5, seg = i & 31;
        cpa16(sb + FQ0 + r * 528 + seg * 16, qh + (size_t)(n0 + r) * 512 + seg * 8);
    }
    CPA_COMMIT();

    const uint32_t fkb[2] = { sb + FK0, sb + FK1 };
    const uint32_t fvb[2] = { sb + FV0, sb + FV1 };

    #define LOAD_KV64(bufi, mm0) do {                                              \
        for (int i = tid; i < 2048; i += 256) {                                    \
            const int r_ = i >> 5, seg_ = i & 31;                                  \
            cpa16(fkb[bufi] + r_ * 528 + seg_ * 16,                                \
                  kh + (size_t)((mm0) + r_) * 512 + seg_ * 8);                     \
        }                                                                          \
        for (int i = tid; i < 2048; i += 256) {                                    \
            const int r_ = i >> 3, seg_ = i & 7;                                   \
            cpa16(fvb[bufi] + r_ * 144 + seg_ * 16,                                \
                  vh + (size_t)r_ * NN + (mm0) + seg_ * 8);                        \
        }                                                                          \
        CPA_COMMIT();                                                              \
    } while (0)

    LOAD_KV64(0, 0);

    const int ga = lane >> 3;
    const int arow = ((ga & 1) << 3) + (lane & 7);
    const int akoff = (ga >> 1) << 3;
    const int brow = ((ga >> 1) << 3) + (lane & 7);
    const int bkoff = (ga & 1) << 3;

    float o[32][4];
    #pragma unroll
    for (int i = 0; i < 32; i++)
        #pragma unroll
        for (int j = 0; j < 4; j++) o[i][j] = 0.f;
    float mi0 = -CUDART_INF_F, mi1 = -CUDART_INF_F;
    float li0 = 0.f, li1 = 0.f;

    const uint32_t qbase = sb + FQ0 + (uint32_t)((wid * 16 + arow) * FQ_STRIDE + akoff) * 2;

    for (int it = 0; it < 64; it++) {
        const int buf = it & 1;
        if (it + 1 < 64) {
            LOAD_KV64((it + 1) & 1, (it + 1) * 64);
            CPA_WAIT1();
        } else {
            CPA_WAIT0();
        }
        __syncthreads();

        // ---- S = Q . K^T : 16 rows x 64 keys per warp ----
        float s[8][4];
        #pragma unroll
        for (int t = 0; t < 8; t++)
            #pragma unroll
            for (int e = 0; e < 4; e++) s[t][e] = 0.f;

        #pragma unroll
        for (int ks = 0; ks < 256; ks += 16) {
            uint32_t qf[4];
            ldm4(qf, qbase + ks * 2);
            uint32_t kf[4][4];
            #pragma unroll
            for (int g = 0; g < 4; g++)
                ldm4(kf[g], fkb[buf] + (uint32_t)((g * 16 + brow) * FQ_STRIDE + ks + bkoff) * 2);
            #pragma unroll
            for (int g = 0; g < 4; g++)
                #pragma unroll
                for (int h = 0; h < 2; h++)
                    mma16816h(s[g * 2 + h], qf, kf[g][h * 2], kf[g][h * 2 + 1]);
        }

        #pragma unroll
        for (int t = 0; t < 8; t++)
            #pragma unroll
            for (int e = 0; e < 4; e++) s[t][e] *= ATTN_SCALE;

        // ---- online softmax ----
        float mn0 = -CUDART_INF_F, mn1 = -CUDART_INF_F;
        #pragma unroll
        for (int t = 0; t < 8; t++) {
            mn0 = fmaxf(mn0, fmaxf(s[t][0], s[t][1]));
            mn1 = fmaxf(mn1, fmaxf(s[t][2], s[t][3]));
        }
        mn0 = fmaxf(mn0, __shfl_xor_sync(0xffffffffu, mn0, 1));
        mn0 = fmaxf(mn0, __shfl_xor_sync(0xffffffffu, mn0, 2));
        mn1 = fmaxf(mn1, __shfl_xor_sync(0xffffffffu, mn1, 1));
        mn1 = fmaxf(mn1, __shfl_xor_sync(0xffffffffu, mn1, 2));
        const float mnew0 = fmaxf(mi0, mn0);
        const float mnew1 = fmaxf(mi1, mn1);
        const float sc0 = __expf(mi0 - mnew0);
        const float sc1 = __expf(mi1 - mnew1);
        mi0 = mnew0; mi1 = mnew1;
        li0 *= sc0; li1 *= sc1;
        if (sc0 < 1.f) {
            #pragma unroll
            for (int ct = 0; ct < 32; ct++) { o[ct][0] *= sc0; o[ct][1] *= sc0; }
        }
        if (sc1 < 1.f) {
            #pragma unroll
            for (int ct = 0; ct < 32; ct++) { o[ct][2] *= sc1; o[ct][3] *= sc1; }
        }
        #pragma unroll
        for (int t = 0; t < 8; t++) {
            s[t][0] = __expf(s[t][0] - mi0);
            s[t][1] = __expf(s[t][1] - mi0);
            s[t][2] = __expf(s[t][2] - mi1);
            s[t][3] = __expf(s[t][3] - mi1);
            li0 += s[t][0] + s[t][1];
            li1 += s[t][2] + s[t][3];
        }

        // ---- per 16-key chunk: build P fragments (fp16 single), O += P.V ----
        #pragma unroll
        for (int kt = 0; kt < 4; kt++) {
            const int t0 = kt * 2, t1 = t0 + 1;
            const float* src4[4] = { s[t0], s[t0] + 2, s[t1], s[t1] + 2 };
            uint32_t pah[4];
            #pragma unroll
            for (int q = 0; q < 4; q++) {
                __half2 hp;
                hp.x = __float2half_rn(src4[q][0]);
                hp.y = __float2half_rn(src4[q][1]);
                pah[q] = *(uint32_t*)&hp;
            }
            #pragma unroll
            for (int cg = 0; cg < 16; cg++) {
                uint32_t vf[4];
                ldm4(vf, fvb[buf] + (uint32_t)((cg * 16 + brow) * FV_STRIDE + bkoff) * 2 + kt * 32);
                #pragma unroll
                for (int h = 0; h < 2; h++)
                    mma16816h(o[cg * 2 + h], pah, vf[h * 2], vf[h * 2 + 1]);
            }
        }
        __syncthreads();
    }

    // final normalize + fp16 write
    li0 += __shfl_xor_sync(0xffffffffu, li0, 1);
    li0 += __shfl_xor_sync(0xffffffffu, li0, 2);
    li1 += __shfl_xor_sync(0xffffffffu, li1, 1);
    li1 += __shfl_xor_sync(0xffffffffu, li1, 2);
    const float inv0 = 1.f / li0;
    const float inv1 = 1.f / li1;

    const int r0 = n0 + wid * 16 + (lane >> 2);
    #pragma unroll
    for (int ct = 0; ct < 32; ct++) {
        const int col = ct * 8 + ((lane & 3) << 1);
        __half2 a0, a1;
        a0.x = __float2half_rn(o[ct][0] * inv0);
        a0.y = __float2half_rn(o[ct][1] * inv0);
        a1.x = __float2half_rn(o[ct][2] * inv1);
        a1.y = __float2half_rn(o[ct][3] * inv1);
        *(__half2*)&Ot[boN + (size_t)r0 * CC + col] = a0;
        *(__half2*)&Ot[boN + (size_t)(r0 + 8) * CC + col] = a1;
    }
}

// ---------------- launch ----------------
extern "C" void kernel_launch(void* const* d_in, const int* in_sizes, int n_in,
                              void* d_out, int out_size) {
    const float* input = (const float*)d_in[0];
    const float* gns   = (const float*)d_in[1];
    const float* gnb   = (const float*)d_in[2];
    const float* Wq    = (const float*)d_in[3];
    const float* bq    = (const float*)d_in[4];
    const float* Wk    = (const float*)d_in[5];
    const float* bk    = (const float*)d_in[6];
    const float* Wv    = (const float*)d_in[7];
    const float* bv    = (const float*)d_in[8];
    const float* Wo    = (const float*)d_in[9];
    const float* bo    = (const float*)d_in[10];
    float* out = (float*)d_out;

    __half *hth, *htl, *wqk, *wvh, *wvl, *woh, *wol, *qk16, *v16, *ot16;
    float* bqk;
    cudaGetSymbolAddress((void**)&hth, g_ht_hi);
    cudaGetSymbolAddress((void**)&htl, g_ht_lo);
    cudaGetSymbolAddress((void**)&wqk, g_wqk);
    cudaGetSymbolAddress((void**)&wvh, g_wv_hi);
    cudaGetSymbolAddress((void**)&wvl, g_wv_lo);
    cudaGetSymbolAddress((void**)&woh, g_wo_hi);
    cudaGetSymbolAddress((void**)&wol, g_wo_lo);
    cudaGetSymbolAddress((void**)&bqk, g_bqk);
    cudaGetSymbolAddress((void**)&qk16, g_qk16);
    cudaGetSymbolAddress((void**)&v16, g_v16);
    cudaGetSymbolAddress((void**)&ot16, g_ot16);

    cudaFuncSetAttribute(gemm2h_kernel<1, 2, false>, cudaFuncAttributeMaxDynamicSharedMemorySize, GEMM_SMEM);
    cudaFuncSetAttribute(gemm2h_kernel<1, 1, false>, cudaFuncAttributeMaxDynamicSharedMemorySize, GEMM_SMEM);
    cudaFuncSetAttribute(gemm2h_kernel<0, 1, true>, cudaFuncAttributeMaxDynamicSharedMemorySize, GEMM_SMEM);
    cudaFuncSetAttribute(flash_kernel, cudaFuncAttributeMaxDynamicSharedMemorySize, FLASH_SMEM);

    // 1) GroupNorm stats + all weight splits (one kernel)
    gnstat1_kernel<<<dim3(16, 32), 256>>>(input);
    wsplitall_kernel<<<256, 256>>>(Wq, Wk, Wv, Wo, bq, bk);
    gnstat2_kernel<<<1, 32>>>();

    // 2) fused GN-apply + transpose + split
    dim3 gt(NN / 32, CC / 32, BB);
    tconv_kernel<<<gt, dim3(32, 8)>>>(input, gns, gnb, hth, htl);

    // 3) QK merged projection: qk[b][n][512] = hT . [Wq;Wk]^T + [bq;bk]
    dim3 gqk(2 * CC / 128, NN / 128, BB);
    gemm2h_kernel<1, 2, false><<<gqk, 256, GEMM_SMEM>>>(
        hth, htl, wqk,
        CC, CC, (size_t)NN * CC, 0,
        nullptr, qk16, 2 * CC, (size_t)NN * 2 * CC, bqk, nullptr, CC, 1.0f);
    //    V projection: v[b][o][m]
    dim3 gv(NN / 128, CC / 128, BB);
    gemm2h_kernel<1, 1, false><<<gv, 256, GEMM_SMEM>>>(
        wvh, wvl, hth,
        CC, CC, 0, (size_t)NN * CC,
        nullptr, v16, NN, (size_t)CC * NN, bv, nullptr, CC, 1.0f);

    // 4) flash attention (1-pass S, 1-pass PV) -> Ot fp16
    dim3 gfl(NN / 128, BB);
    flash_kernel<<<gfl, 256, FLASH_SMEM>>>(qk16, v16, ot16);

    // 5) final: out = (Wo_hi+Wo_lo) . Ot^T + bo + residual (fp32 out)
    dim3 gf(NN / 128, CC / 128, BB);
    gemm2h_kernel<0, 1, true><<<gf, 256, GEMM_SMEM>>>(
        woh, wol, ot16,
        CC, CC, 0, (size_t)NN * CC,
        out, nullptr, NN, (size_t)CC * NN, bo, input, CC, 1.0f);
}

// round 11
// speedup vs baseline: 8.5270x; 1.0541x over previous
#include <cuda_runtime.h>
#include <cuda_fp16.h>
#include <math_constants.h>
#include <cstdint>

// Problem constants
#define BB 4
#define CC 256
#define NN 4096
#define NG 8
#define CPG 32
#define EPSV 1e-5f
#define ATTN_SCALE 0.0625f  // 1/sqrt(256)

// 1-pass gemm smem geometry (2 tiles, double buffered)
#define GROW 40
#define MATB (128 * GROW * 2)     // 10240
#define BUF2 (2 * MATB)           // 20480
#define GEMM_SMEM (2 * BUF2)      // 40960

// flash smem geometry
#define FQ_STRIDE 264             // 528B rows (256 fp16 + pad)
#define FV_STRIDE 72              // 144B rows (64 fp16 + pad)
#define FQ0 0
#define FK0 67584                 // 128*528
#define FK1 (FK0 + 33792)         // 64*528
#define FV0 (FK1 + 33792)         // 135168
#define FV1 (FV0 + 36864)         // 256*144
#define FLASH_SMEM (FV1 + 36864)  // 208896

// ---------------- static scratch ----------------
__device__ __align__(16) float g_part[512 * 2];              // GN partial sums
__device__ float g_mean[BB * NG];
__device__ float g_inv[BB * NG];
__device__ __align__(16) __half g_ht[BB * NN * CC];          // h^T [b][n][c] fp16
__device__ __align__(16) __half g_wqk[2 * CC * CC];          // concat(Wq,Wk)
__device__ __align__(16) __half g_wv[CC * CC];
__device__ __align__(16) __half g_wo[CC * CC];
__device__ __align__(16) float g_bqk[2 * CC];                // concat(bq,bk)
__device__ __align__(16) __half g_qk16[BB * NN * 2 * CC];    // qk^T [b][n][512]
__device__ __align__(16) __half g_v16[BB * CC * NN];         // v [b][o][m]
__device__ __align__(16) float g_opart[2 * BB * NN * CC];    // split-K partial O fp32
__device__ __align__(16) float g_lpart[2 * BB * NN];         // split-K partial l
__device__ __align__(16) __half g_ot16[BB * NN * CC];        // Ot [b][n][c]

// ================= PTX helpers =================
__device__ __forceinline__ uint32_t smem_u32(const void* p) {
    uint32_t a;
    asm("{ .reg .u64 t; cvta.to.shared.u64 t, %1; cvt.u32.u64 %0, t; }" : "=r"(a) : "l"(p));
    return a;
}
__device__ __forceinline__ void ldm4(uint32_t r[4], uint32_t addr) {
    asm volatile("ldmatrix.sync.aligned.m8n8.x4.shared.b16 {%0,%1,%2,%3}, [%4];"
                 : "=r"(r[0]), "=r"(r[1]), "=r"(r[2]), "=r"(r[3]) : "r"(addr));
}
__device__ __forceinline__ void mma16816h(float c[4], const uint32_t a[4],
                                          uint32_t b0, uint32_t b1) {
    asm volatile("mma.sync.aligned.m16n8k16.row.col.f32.f16.f16.f32 "
                 "{%0,%1,%2,%3}, {%4,%5,%6,%7}, {%8,%9}, {%0,%1,%2,%3};"
                 : "+f"(c[0]), "+f"(c[1]), "+f"(c[2]), "+f"(c[3])
                 : "r"(a[0]), "r"(a[1]), "r"(a[2]), "r"(a[3]), "r"(b0), "r"(b1));
}
__device__ __forceinline__ void cpa16(uint32_t dst, const void* src) {
    asm volatile("cp.async.cg.shared.global [%0], [%1], 16;" :: "r"(dst), "l"(src));
}
#define CPA_COMMIT() asm volatile("cp.async.commit_group;" ::: "memory")
#define CPA_WAIT1()  asm volatile("cp.async.wait_group 1;" ::: "memory")
#define CPA_WAIT0()  asm volatile("cp.async.wait_group 0;" ::: "memory")

__device__ __forceinline__ uint32_t pack_h2(float a, float b) {
    __half2 h;
    h.x = __float2half_rn(a);
    h.y = __float2half_rn(b);
    return *(uint32_t*)&h;
}

// ---------------- GroupNorm stage 1 ----------------
__global__ void gnstat1_kernel(const float* __restrict__ x) {
    const int bg = blockIdx.y;
    const int chunk = blockIdx.x;
    const float* xp = x + (size_t)bg * (CPG * NN) + chunk * 8192;
    float s = 0.f, ss = 0.f;
    for (int i = threadIdx.x; i < 2048; i += 256) {
        float4 v = ((const float4*)xp)[i];
        s += v.x + v.y + v.z + v.w;
        ss += v.x * v.x + v.y * v.y + v.z * v.z + v.w * v.w;
    }
    __shared__ float rs[256], rq[256];
    rs[threadIdx.x] = s; rq[threadIdx.x] = ss;
    __syncthreads();
    for (int st = 128; st > 0; st >>= 1) {
        if (threadIdx.x < st) { rs[threadIdx.x] += rs[threadIdx.x + st]; rq[threadIdx.x] += rq[threadIdx.x + st]; }
        __syncthreads();
    }
    if (threadIdx.x == 0) {
        g_part[(bg * 16 + chunk) * 2 + 0] = rs[0];
        g_part[(bg * 16 + chunk) * 2 + 1] = rq[0];
    }
}

// ---------------- GroupNorm stage 2 ----------------
__global__ void gnstat2_kernel() {
    const int i = threadIdx.x;
    float s = 0.f, ss = 0.f;
    #pragma unroll
    for (int j = 0; j < 16; j++) {
        s += g_part[(i * 16 + j) * 2 + 0];
        ss += g_part[(i * 16 + j) * 2 + 1];
    }
    const float Mf = (float)(CPG * NN);
    const float mean = s / Mf;
    const float var = ss / Mf - mean * mean;
    g_mean[i] = mean;
    g_inv[i] = rsqrtf(var + EPSV);
}

// ---------------- all weight converts + bias concat ----------------
__global__ void wsplitall_kernel(const float* __restrict__ Wq, const float* __restrict__ Wk,
                                 const float* __restrict__ Wv, const float* __restrict__ Wo,
                                 const float* __restrict__ bq, const float* __restrict__ bk) {
    const int i = blockIdx.x * blockDim.x + threadIdx.x;
    if (i < CC * CC) {
        g_wqk[i] = __float2half_rn(Wq[i]);
        g_wqk[CC * CC + i] = __float2half_rn(Wk[i]);
        g_wv[i] = __float2half_rn(Wv[i]);
        g_wo[i] = __float2half_rn(Wo[i]);
        if (i < CC) g_bqk[i] = bq[i];
        else if (i < 2 * CC) g_bqk[i] = bk[i - CC];
    }
}

// ---------------- fused GN-apply + transpose + fp16 ----------------
__global__ void tconv_kernel(const float* __restrict__ x,
                             const float* __restrict__ sc,
                             const float* __restrict__ bi,
                             __half* __restrict__ dst) {
    __shared__ float t[32][33];
    const int b = blockIdx.z;
    const int n0 = blockIdx.x * 32;
    const int c0 = blockIdx.y * 32;
    const int tx = threadIdx.x, ty = threadIdx.y;  // (32, 8)
    const int bg = b * NG + blockIdx.y;
    const float mean = g_mean[bg];
    const float inv = g_inv[bg];
    const float* s = x + (size_t)b * CC * NN;
    #pragma unroll
    for (int k = 0; k < 4; k++)
        t[ty + 8 * k][tx] = s[(size_t)(c0 + ty + 8 * k) * NN + n0 + tx];
    __syncthreads();
    const int c = c0 + tx;
    const float a = inv * sc[c];
    const float d = bi[c] - mean * a;
    const size_t base = (size_t)b * NN * CC;
    #pragma unroll
    for (int k = 0; k < 4; k++) {
        const int n = n0 + ty + 8 * k;
        dst[base + (size_t)n * CC + c] = __float2half_rn(t[tx][ty + 8 * k] * a + d);
    }
}

// ============================================================================
// 1-pass fp16 GEMM: Out[i][j] = scale * sum_k A[i][k]*B[j][k]
// OUTMODE: 0 = fp32; 1 = fp16
// BIASMODE: 0 none; 1 bias[row]; 2 bias[col]
// ============================================================================
template<int OUTMODE, int BIASMODE, bool DO_RES>
__global__ __launch_bounds__(256, 1)
void gemm1h_kernel(const __half* __restrict__ Ah, const __half* __restrict__ Bh,
                   size_t ldA, size_t ldB, size_t strA, size_t strB,
                   float* __restrict__ OutF, __half* __restrict__ Oh,
                   size_t ldOut, size_t strOut,
                   const float* __restrict__ bias, const float* __restrict__ res,
                   int K, float scale) {
    extern __shared__ char smem[];
    const uint32_t sb = smem_u32(smem);
    const int tid = threadIdx.x;
    const int lane = tid & 31, wid = tid >> 5;
    const int warpM = wid & 3, warpN = wid >> 2;
    const int bz = blockIdx.z;
    const int N0 = blockIdx.x * 128;
    const int M0 = blockIdx.y * 128;

    const __half* pA = Ah + (size_t)bz * strA + (size_t)M0 * ldA;
    const __half* pB = Bh + (size_t)bz * strB + (size_t)N0 * ldB;

    const int ga = lane >> 3;
    const int arow = ((ga & 1) << 3) + (lane & 7);
    const int akoff = (ga >> 1) << 3;
    const int brow = ((ga >> 1) << 3) + (lane & 7);
    const int bkoff = (ga & 1) << 3;

    float acc[2][8][4];
    #pragma unroll
    for (int i = 0; i < 2; i++)
        #pragma unroll
        for (int j = 0; j < 8; j++)
            #pragma unroll
            for (int k = 0; k < 4; k++) acc[i][j][k] = 0.f;

    const int nch = K >> 5;

    #define ISSUE_COPY2(bufi, kc) do {                                             \
        _Pragma("unroll")                                                          \
        for (int i_ = 0; i_ < 4; i_++) {                                           \
            int idx_ = tid + i_ * 256;                                             \
            int mat_ = idx_ >> 9;                                                  \
            int r_ = (idx_ >> 2) & 127;                                            \
            int seg_ = idx_ & 3;                                                   \
            const __half* src_ = (mat_ ? pB + (size_t)r_ * ldB : pA + (size_t)r_ * ldA) \
                                 + (kc) + seg_ * 8;                                \
            uint32_t dst_ = sb + (bufi) * BUF2 + mat_ * MATB + (r_ * GROW + seg_ * 8) * 2; \
            cpa16(dst_, src_);                                                     \
        }                                                                          \
        CPA_COMMIT();                                                              \
    } while (0)

    ISSUE_COPY2(0, 0);

    for (int c = 0; c < nch; c++) {
        if (c + 1 < nch) {
            ISSUE_COPY2((c + 1) & 1, (c + 1) << 5);
            CPA_WAIT1();
        } else {
            CPA_WAIT0();
        }
        __syncthreads();

        const uint32_t bufb = sb + (c & 1) * BUF2;
        #pragma unroll
        for (int ks = 0; ks < 32; ks += 16) {
            uint32_t ah[2][4];
            #pragma unroll
            for (int mt = 0; mt < 2; mt++) {
                uint32_t off = (uint32_t)(((warpM * 32 + mt * 16 + arow) * GROW + ks + akoff) * 2);
                ldm4(ah[mt], bufb + off);
            }
            uint32_t bh[4][4];
            #pragma unroll
            for (int ng = 0; ng < 4; ng++) {
                uint32_t off = (uint32_t)(((warpN * 64 + ng * 16 + brow) * GROW + ks + bkoff) * 2);
                ldm4(bh[ng], bufb + MATB + off);
            }
            #pragma unroll
            for (int mt = 0; mt < 2; mt++)
                #pragma unroll
                for (int ng = 0; ng < 4; ng++)
                    #pragma unroll
                    for (int h = 0; h < 2; h++)
                        mma16816h(acc[mt][ng * 2 + h], ah[mt], bh[ng][h * 2], bh[ng][h * 2 + 1]);
        }
        __syncthreads();
    }

    #pragma unroll
    for (int mt = 0; mt < 2; mt++)
        #pragma unroll
        for (int nt = 0; nt < 8; nt++) {
            const int row0 = M0 + warpM * 32 + mt * 16 + (lane >> 2);
            const int col = N0 + warpN * 64 + nt * 8 + ((lane & 3) << 1);
            #pragma unroll
            for (int rr = 0; rr < 2; rr++) {
                const int r = row0 + rr * 8;
                float v0 = acc[mt][nt][rr * 2 + 0] * scale;
                float v1 = acc[mt][nt][rr * 2 + 1] * scale;
                if (BIASMODE == 1) { const float bb = bias[r]; v0 += bb; v1 += bb; }
                if (BIASMODE == 2) { v0 += bias[col]; v1 += bias[col + 1]; }
                const size_t off = (size_t)bz * strOut + (size_t)r * ldOut + col;
                if (DO_RES) { v0 += res[off]; v1 += res[off + 1]; }
                if (OUTMODE == 0) {
                    float2 o; o.x = v0; o.y = v1;
                    *(float2*)&OutF[off] = o;
                } else {
                    __half2 hp;
                    hp.x = __float2half_rn(v0);
                    hp.y = __float2half_rn(v1);
                    *(__half2*)&Oh[off] = hp;
                }
            }
        }
}

// ============================================================================
// Flash attention, split-K, max-free softmax.
// grid: (NN/128, BB, 2). z = kv half (2048 keys each, 32 iters of 64).
// Per iter: S = Q.K^T; per 16-key chunk: exp (scale folded), li accumulate,
// pack P fp16, O += P.V. Partial O (unnormalized fp32) + partial l written out.
// ============================================================================
__global__ __launch_bounds__(256, 1)
void flash_kernel(const __half* __restrict__ QK, const __half* __restrict__ Vh,
                  float* __restrict__ Opart, float* __restrict__ Lpart) {
    extern __shared__ char smem[];
    const uint32_t sb = smem_u32(smem);
    const int tid = threadIdx.x;
    const int lane = tid & 31, wid = tid >> 5;
    const int b = blockIdx.y;
    const int n0 = blockIdx.x * 128;
    const int z = blockIdx.z;
    const int mbase = z * 2048;

    const __half* qh = QK + (size_t)b * NN * 512;
    const __half* kh = qh + 256;
    const __half* vh = Vh + (size_t)b * CC * NN;

    // Q load (once): rows have stride 512 in gmem
    for (int i = tid; i < 128 * 32; i += 256) {
        const int r = i >> 5, seg = i & 31;
        cpa16(sb + FQ0 + r * 528 + seg * 16, qh + (size_t)(n0 + r) * 512 + seg * 8);
    }
    CPA_COMMIT();

    const uint32_t fkb[2] = { sb + FK0, sb + FK1 };
    const uint32_t fvb[2] = { sb + FV0, sb + FV1 };

    #define LOAD_KV64(bufi, mm0) do {                                              \
        for (int i = tid; i < 2048; i += 256) {                                    \
            const int r_ = i >> 5, seg_ = i & 31;                                  \
            cpa16(fkb[bufi] + r_ * 528 + seg_ * 16,                                \
                  kh + (size_t)((mm0) + r_) * 512 + seg_ * 8);                     \
        }                                                                          \
        for (int i = tid; i < 2048; i += 256) {                                    \
            const int r_ = i >> 3, seg_ = i & 7;                                   \
            cpa16(fvb[bufi] + r_ * 144 + seg_ * 16,                                \
                  vh + (size_t)r_ * NN + (mm0) + seg_ * 8);                        \
        }                                                                          \
        CPA_COMMIT();                                                              \
    } while (0)

    LOAD_KV64(0, mbase);

    const int ga = lane >> 3;
    const int arow = ((ga & 1) << 3) + (lane & 7);
    const int akoff = (ga >> 1) << 3;
    const int brow = ((ga >> 1) << 3) + (lane & 7);
    const int bkoff = (ga & 1) << 3;

    float o[32][4];
    #pragma unroll
    for (int i = 0; i < 32; i++)
        #pragma unroll
        for (int j = 0; j < 4; j++) o[i][j] = 0.f;
    float li0 = 0.f, li1 = 0.f;

    const uint32_t qbase = sb + FQ0 + (uint32_t)((wid * 16 + arow) * FQ_STRIDE + akoff) * 2;

    for (int it = 0; it < 32; it++) {
        const int buf = it & 1;
        if (it + 1 < 32) {
            LOAD_KV64((it + 1) & 1, mbase + (it + 1) * 64);
            CPA_WAIT1();
        } else {
            CPA_WAIT0();
        }
        __syncthreads();

        // ---- S = Q . K^T : 16 rows x 64 keys per warp (raw scores) ----
        float s[8][4];
        #pragma unroll
        for (int t = 0; t < 8; t++)
            #pragma unroll
            for (int e = 0; e < 4; e++) s[t][e] = 0.f;

        #pragma unroll
        for (int ks = 0; ks < 256; ks += 16) {
            uint32_t qf[4];
            ldm4(qf, qbase + ks * 2);
            uint32_t kf[4][4];
            #pragma unroll
            for (int g = 0; g < 4; g++)
                ldm4(kf[g], fkb[buf] + (uint32_t)((g * 16 + brow) * FQ_STRIDE + ks + bkoff) * 2);
            #pragma unroll
            for (int g = 0; g < 4; g++)
                #pragma unroll
                for (int h = 0; h < 2; h++)
                    mma16816h(s[g * 2 + h], qf, kf[g][h * 2], kf[g][h * 2 + 1]);
        }

        // ---- per 16-key chunk: exp (scale folded, max-free), li, P pack, PV ----
        #pragma unroll
        for (int kt = 0; kt < 4; kt++) {
            const int t0 = kt * 2, t1 = t0 + 1;
            const float e00 = __expf(s[t0][0] * ATTN_SCALE);
            const float e01 = __expf(s[t0][1] * ATTN_SCALE);
            const float e02 = __expf(s[t0][2] * ATTN_SCALE);
            const float e03 = __expf(s[t0][3] * ATTN_SCALE);
            const float e10 = __expf(s[t1][0] * ATTN_SCALE);
            const float e11 = __expf(s[t1][1] * ATTN_SCALE);
            const float e12 = __expf(s[t1][2] * ATTN_SCALE);
            const float e13 = __expf(s[t1][3] * ATTN_SCALE);
            li0 += e00 + e01 + e10 + e11;
            li1 += e02 + e03 + e12 + e13;
            uint32_t pah[4];
            pah[0] = pack_h2(e00, e01);
            pah[1] = pack_h2(e02, e03);
            pah[2] = pack_h2(e10, e11);
            pah[3] = pack_h2(e12, e13);
            #pragma unroll
            for (int cg = 0; cg < 16; cg++) {
                uint32_t vf[4];
                ldm4(vf, fvb[buf] + (uint32_t)((cg * 16 + brow) * FV_STRIDE + bkoff) * 2 + kt * 32);
                #pragma unroll
                for (int h = 0; h < 2; h++)
                    mma16816h(o[cg * 2 + h], pah, vf[h * 2], vf[h * 2 + 1]);
            }
        }
        __syncthreads();
    }

    // quad-reduce l, write partials
    li0 += __shfl_xor_sync(0xffffffffu, li0, 1);
    li0 += __shfl_xor_sync(0xffffffffu, li0, 2);
    li1 += __shfl_xor_sync(0xffffffffu, li1, 1);
    li1 += __shfl_xor_sync(0xffffffffu, li1, 2);

    const int r0 = n0 + wid * 16 + (lane >> 2);
    float* Ob = Opart + ((size_t)z * BB + b) * NN * CC;
    #pragma unroll
    for (int ct = 0; ct < 32; ct++) {
        const int col = ct * 8 + ((lane & 3) << 1);
        float2 a0, a1;
        a0.x = o[ct][0]; a0.y = o[ct][1];
        a1.x = o[ct][2]; a1.y = o[ct][3];
        *(float2*)&Ob[(size_t)r0 * CC + col] = a0;
        *(float2*)&Ob[(size_t)(r0 + 8) * CC + col] = a1;
    }
    if ((lane & 3) == 0) {
        Lpart[((size_t)z * BB + b) * NN + r0] = li0;
        Lpart[((size_t)z * BB + b) * NN + r0 + 8] = li1;
    }
}

// ---------------- split-K combine: Ot = (O0+O1)/(l0+l1), fp16 ----------------
__global__ void combine_kernel(const float* __restrict__ O, const float* __restrict__ L,
                               __half* __restrict__ Ot) {
    const size_t PAIRS = (size_t)BB * NN * CC / 2;
    const size_t HALFO = (size_t)BB * NN * CC;
    const size_t HALFL = (size_t)BB * NN;
    for (size_t i = (size_t)blockIdx.x * blockDim.x + threadIdx.x; i < PAIRS;
         i += (size_t)gridDim.x * blockDim.x) {
        const size_t row = i >> 7;  // / (CC/2)
        const float2 a = ((const float2*)O)[i];
        const float2 b = ((const float2*)(O + HALFO))[i];
        const float inv = 1.f / (L[row] + L[HALFL + row]);
        __half2 h;
        h.x = __float2half_rn((a.x + b.x) * inv);
        h.y = __float2half_rn((a.y + b.y) * inv);
        ((__half2*)Ot)[i] = h;
    }
}

// ---------------- launch ----------------
extern "C" void kernel_launch(void* const* d_in, const int* in_sizes, int n_in,
                              void* d_out, int out_size) {
    const float* input = (const float*)d_in[0];
    const float* gns   = (const float*)d_in[1];
    const float* gnb   = (const float*)d_in[2];
    const float* Wq    = (const float*)d_in[3];
    const float* bq    = (const float*)d_in[4];
    const float* Wk    = (const float*)d_in[5];
    const float* bk    = (const float*)d_in[6];
    const float* Wv    = (const float*)d_in[7];
    const float* bv    = (const float*)d_in[8];
    const float* Wo    = (const float*)d_in[9];
    const float* bo    = (const float*)d_in[10];
    float* out = (float*)d_out;

    __half *hth, *wqk, *wv, *wo, *qk16, *v16, *ot16;
    float *bqk, *opart, *lpart;
    cudaGetSymbolAddress((void**)&hth, g_ht);
    cudaGetSymbolAddress((void**)&wqk, g_wqk);
    cudaGetSymbolAddress((void**)&wv, g_wv);
    cudaGetSymbolAddress((void**)&wo, g_wo);
    cudaGetSymbolAddress((void**)&bqk, g_bqk);
    cudaGetSymbolAddress((void**)&qk16, g_qk16);
    cudaGetSymbolAddress((void**)&v16, g_v16);
    cudaGetSymbolAddress((void**)&opart, g_opart);
    cudaGetSymbolAddress((void**)&lpart, g_lpart);
    cudaGetSymbolAddress((void**)&ot16, g_ot16);

    cudaFuncSetAttribute(gemm1h_kernel<1, 2, false>, cudaFuncAttributeMaxDynamicSharedMemorySize, GEMM_SMEM);
    cudaFuncSetAttribute(gemm1h_kernel<1, 1, false>, cudaFuncAttributeMaxDynamicSharedMemorySize, GEMM_SMEM);
    cudaFuncSetAttribute(gemm1h_kernel<0, 1, true>, cudaFuncAttributeMaxDynamicSharedMemorySize, GEMM_SMEM);
    cudaFuncSetAttribute(flash_kernel, cudaFuncAttributeMaxDynamicSharedMemorySize, FLASH_SMEM);

    // 1) GroupNorm stats + all weight converts (one kernel)
    gnstat1_kernel<<<dim3(16, 32), 256>>>(input);
    wsplitall_kernel<<<256, 256>>>(Wq, Wk, Wv, Wo, bq, bk);
    gnstat2_kernel<<<1, 32>>>();

    // 2) fused GN-apply + transpose -> fp16
    dim3 gt(NN / 32, CC / 32, BB);
    tconv_kernel<<<gt, dim3(32, 8)>>>(input, gns, gnb, hth);

    // 3) QK merged projection: qk[b][n][512] = hT . [Wq;Wk]^T + [bq;bk]
    dim3 gqk(2 * CC / 128, NN / 128, BB);
    gemm1h_kernel<1, 2, false><<<gqk, 256, GEMM_SMEM>>>(
        hth, wqk,
        CC, CC, (size_t)NN * CC, 0,
        nullptr, qk16, 2 * CC, (size_t)NN * 2 * CC, bqk, nullptr, CC, 1.0f);
    //    V projection: v[b][o][m]
    dim3 gv(NN / 128, CC / 128, BB);
    gemm1h_kernel<1, 1, false><<<gv, 256, GEMM_SMEM>>>(
        wv, hth,
        CC, CC, 0, (size_t)NN * CC,
        nullptr, v16, NN, (size_t)CC * NN, bv, nullptr, CC, 1.0f);

    // 4) flash attention, split-K over 2 kv halves -> partials
    dim3 gfl(NN / 128, BB, 2);
    flash_kernel<<<gfl, 256, FLASH_SMEM>>>(qk16, v16, opart, lpart);

    //    combine partials -> Ot fp16
    combine_kernel<<<4096, 256>>>(opart, lpart, ot16);

    // 5) final: out = Wo . Ot^T + bo + residual (fp32 out)
    dim3 gf(NN / 128, CC / 128, BB);
    gemm1h_kernel<0, 1, true><<<gf, 256, GEMM_SMEM>>>(
        wo, ot16,
        CC, CC, 0, (size_t)NN * CC,
        out, nullptr, NN, (size_t)CC * NN, bo, input, CC, 1.0f);
}

// round 13
// speedup vs baseline: 8.8728x; 1.0405x over previous
#include <cuda_runtime.h>
#include <cuda_fp16.h>
#include <math_constants.h>
#include <cstdint>

// Problem constants
#define BB 4
#define CC 256
#define NN 4096
#define NG 8
#define CPG 32
#define EPSV 1e-5f
#define ATTN_SCALE 0.0625f  // 1/sqrt(256), folded into Wq/bq

// 1-pass gemm smem geometry (2 tiles, double buffered)
#define GROW 40
#define MATB (128 * GROW * 2)     // 10240
#define BUF2 (2 * MATB)           // 20480
#define GEMM_SMEM (2 * BUF2)      // 40960

// flash smem geometry
#define FQ_STRIDE 264             // 528B rows (256 fp16 + pad)
#define FV_STRIDE 72              // 144B rows (64 fp16 + pad)
#define FQ0 0
#define FK0 67584                 // 128*528
#define FK1 (FK0 + 33792)         // 64*528
#define FV0 (FK1 + 33792)         // 135168
#define FV1 (FV0 + 36864)         // 256*144
#define FLASH_SMEM (FV1 + 36864)  // 208896

// ---------------- static scratch ----------------
__device__ __align__(16) float g_part[512 * 2];              // GN partial sums
__device__ float g_mean[BB * NG];
__device__ float g_inv[BB * NG];
__device__ __align__(16) __half g_ht[BB * NN * CC];          // h^T [b][n][c] fp16
__device__ __align__(16) __half g_wqk[2 * CC * CC];          // concat(Wq*scale, Wk)
__device__ __align__(16) __half g_wv[CC * CC];
__device__ __align__(16) __half g_wo[CC * CC];
__device__ __align__(16) float g_bqk[2 * CC];                // concat(bq*scale, bk)
__device__ __align__(16) __half g_qk16[BB * NN * 2 * CC];    // qk^T [b][n][512]
__device__ __align__(16) __half g_v16[BB * CC * NN];         // v [b][o][m]
__device__ __align__(16) __half g_ot16[BB * NN * CC];        // Ot [b][n][c]

// ================= PTX helpers =================
__device__ __forceinline__ uint32_t smem_u32(const void* p) {
    uint32_t a;
    asm("{ .reg .u64 t; cvta.to.shared.u64 t, %1; cvt.u32.u64 %0, t; }" : "=r"(a) : "l"(p));
    return a;
}
__device__ __forceinline__ void ldm4(uint32_t r[4], uint32_t addr) {
    asm volatile("ldmatrix.sync.aligned.m8n8.x4.shared.b16 {%0,%1,%2,%3}, [%4];"
                 : "=r"(r[0]), "=r"(r[1]), "=r"(r[2]), "=r"(r[3]) : "r"(addr));
}
__device__ __forceinline__ void mma16816h(float c[4], const uint32_t a[4],
                                          uint32_t b0, uint32_t b1) {
    asm volatile("mma.sync.aligned.m16n8k16.row.col.f32.f16.f16.f32 "
                 "{%0,%1,%2,%3}, {%4,%5,%6,%7}, {%8,%9}, {%0,%1,%2,%3};"
                 : "+f"(c[0]), "+f"(c[1]), "+f"(c[2]), "+f"(c[3])
                 : "r"(a[0]), "r"(a[1]), "r"(a[2]), "r"(a[3]), "r"(b0), "r"(b1));
}
__device__ __forceinline__ void cpa16(uint32_t dst, const void* src) {
    asm volatile("cp.async.cg.shared.global [%0], [%1], 16;" :: "r"(dst), "l"(src));
}
#define CPA_COMMIT() asm volatile("cp.async.commit_group;" ::: "memory")
#define CPA_WAIT1()  asm volatile("cp.async.wait_group 1;" ::: "memory")
#define CPA_WAIT0()  asm volatile("cp.async.wait_group 0;" ::: "memory")

__device__ __forceinline__ uint32_t pack_h2(float a, float b) {
    __half2 h;
    h.x = __float2half_rn(a);
    h.y = __float2half_rn(b);
    return *(uint32_t*)&h;
}

// ---------------- GroupNorm stage 1 ----------------
__global__ void gnstat1_kernel(const float* __restrict__ x) {
    const int bg = blockIdx.y;
    const int chunk = blockIdx.x;
    const float* xp = x + (size_t)bg * (CPG * NN) + chunk * 8192;
    float s = 0.f, ss = 0.f;
    for (int i = threadIdx.x; i < 2048; i += 256) {
        float4 v = ((const float4*)xp)[i];
        s += v.x + v.y + v.z + v.w;
        ss += v.x * v.x + v.y * v.y + v.z * v.z + v.w * v.w;
    }
    __shared__ float rs[256], rq[256];
    rs[threadIdx.x] = s; rq[threadIdx.x] = ss;
    __syncthreads();
    for (int st = 128; st > 0; st >>= 1) {
        if (threadIdx.x < st) { rs[threadIdx.x] += rs[threadIdx.x + st]; rq[threadIdx.x] += rq[threadIdx.x + st]; }
        __syncthreads();
    }
    if (threadIdx.x == 0) {
        g_part[(bg * 16 + chunk) * 2 + 0] = rs[0];
        g_part[(bg * 16 + chunk) * 2 + 1] = rq[0];
    }
}

// ---------------- GroupNorm stage 2 ----------------
__global__ void gnstat2_kernel() {
    const int i = threadIdx.x;
    float s = 0.f, ss = 0.f;
    #pragma unroll
    for (int j = 0; j < 16; j++) {
        s += g_part[(i * 16 + j) * 2 + 0];
        ss += g_part[(i * 16 + j) * 2 + 1];
    }
    const float Mf = (float)(CPG * NN);
    const float mean = s / Mf;
    const float var = ss / Mf - mean * mean;
    g_mean[i] = mean;
    g_inv[i] = rsqrtf(var + EPSV);
}

// ---------------- all weight converts + bias concat (scale folded into Q) ----------------
__global__ void wsplitall_kernel(const float* __restrict__ Wq, const float* __restrict__ Wk,
                                 const float* __restrict__ Wv, const float* __restrict__ Wo,
                                 const float* __restrict__ bq, const float* __restrict__ bk) {
    const int i = blockIdx.x * blockDim.x + threadIdx.x;
    if (i < CC * CC) {
        g_wqk[i] = __float2half_rn(Wq[i] * ATTN_SCALE);
        g_wqk[CC * CC + i] = __float2half_rn(Wk[i]);
        g_wv[i] = __float2half_rn(Wv[i]);
        g_wo[i] = __float2half_rn(Wo[i]);
        if (i < CC) g_bqk[i] = bq[i] * ATTN_SCALE;
        else if (i < 2 * CC) g_bqk[i] = bk[i - CC];
    }
}

// ---------------- fused GN-apply + transpose + fp16 ----------------
__global__ void tconv_kernel(const float* __restrict__ x,
                             const float* __restrict__ sc,
                             const float* __restrict__ bi,
                             __half* __restrict__ dst) {
    __shared__ float t[32][33];
    const int b = blockIdx.z;
    const int n0 = blockIdx.x * 32;
    const int c0 = blockIdx.y * 32;
    const int tx = threadIdx.x, ty = threadIdx.y;  // (32, 8)
    const int bg = b * NG + blockIdx.y;
    const float mean = g_mean[bg];
    const float inv = g_inv[bg];
    const float* s = x + (size_t)b * CC * NN;
    #pragma unroll
    for (int k = 0; k < 4; k++)
        t[ty + 8 * k][tx] = s[(size_t)(c0 + ty + 8 * k) * NN + n0 + tx];
    __syncthreads();
    const int c = c0 + tx;
    const float a = inv * sc[c];
    const float d = bi[c] - mean * a;
    const size_t base = (size_t)b * NN * CC;
    #pragma unroll
    for (int k = 0; k < 4; k++) {
        const int n = n0 + ty + 8 * k;
        dst[base + (size_t)n * CC + c] = __float2half_rn(t[tx][ty + 8 * k] * a + d);
    }
}

// ============================================================================
// 1-pass fp16 GEMM: Out[i][j] = scale * sum_k A[i][k]*B[j][k]
// OUTMODE: 0 = fp32; 1 = fp16
// BIASMODE: 0 none; 1 bias[row]; 2 bias[col]
// ============================================================================
template<int OUTMODE, int BIASMODE, bool DO_RES>
__global__ __launch_bounds__(256, 1)
void gemm1h_kernel(const __half* __restrict__ Ah, const __half* __restrict__ Bh,
                   size_t ldA, size_t ldB, size_t strA, size_t strB,
                   float* __restrict__ OutF, __half* __restrict__ Oh,
                   size_t ldOut, size_t strOut,
                   const float* __restrict__ bias, const float* __restrict__ res,
                   int K, float scale) {
    extern __shared__ char smem[];
    const uint32_t sb = smem_u32(smem);
    const int tid = threadIdx.x;
    const int lane = tid & 31, wid = tid >> 5;
    const int warpM = wid & 3, warpN = wid >> 2;
    const int bz = blockIdx.z;
    const int N0 = blockIdx.x * 128;
    const int M0 = blockIdx.y * 128;

    const __half* pA = Ah + (size_t)bz * strA + (size_t)M0 * ldA;
    const __half* pB = Bh + (size_t)bz * strB + (size_t)N0 * ldB;

    const int ga = lane >> 3;
    const int arow = ((ga & 1) << 3) + (lane & 7);
    const int akoff = (ga >> 1) << 3;
    const int brow = ((ga >> 1) << 3) + (lane & 7);
    const int bkoff = (ga & 1) << 3;

    float acc[2][8][4];
    #pragma unroll
    for (int i = 0; i < 2; i++)
        #pragma unroll
        for (int j = 0; j < 8; j++)
            #pragma unroll
            for (int k = 0; k < 4; k++) acc[i][j][k] = 0.f;

    const int nch = K >> 5;

    #define ISSUE_COPY2(bufi, kc) do {                                             \
        _Pragma("unroll")                                                          \
        for (int i_ = 0; i_ < 4; i_++) {                                           \
            int idx_ = tid + i_ * 256;                                             \
            int mat_ = idx_ >> 9;                                                  \
            int r_ = (idx_ >> 2) & 127;                                            \
            int seg_ = idx_ & 3;                                                   \
            const __half* src_ = (mat_ ? pB + (size_t)r_ * ldB : pA + (size_t)r_ * ldA) \
                                 + (kc) + seg_ * 8;                                \
            uint32_t dst_ = sb + (bufi) * BUF2 + mat_ * MATB + (r_ * GROW + seg_ * 8) * 2; \
            cpa16(dst_, src_);                                                     \
        }                                                                          \
        CPA_COMMIT();                                                              \
    } while (0)

    ISSUE_COPY2(0, 0);

    for (int c = 0; c < nch; c++) {
        if (c + 1 < nch) {
            ISSUE_COPY2((c + 1) & 1, (c + 1) << 5);
            CPA_WAIT1();
        } else {
            CPA_WAIT0();
        }
        __syncthreads();

        const uint32_t bufb = sb + (c & 1) * BUF2;
        #pragma unroll
        for (int ks = 0; ks < 32; ks += 16) {
            uint32_t ah[2][4];
            #pragma unroll
            for (int mt = 0; mt < 2; mt++) {
                uint32_t off = (uint32_t)(((warpM * 32 + mt * 16 + arow) * GROW + ks + akoff) * 2);
                ldm4(ah[mt], bufb + off);
            }
            uint32_t bh[4][4];
            #pragma unroll
            for (int ng = 0; ng < 4; ng++) {
                uint32_t off = (uint32_t)(((warpN * 64 + ng * 16 + brow) * GROW + ks + bkoff) * 2);
                ldm4(bh[ng], bufb + MATB + off);
            }
            #pragma unroll
            for (int mt = 0; mt < 2; mt++)
                #pragma unroll
                for (int ng = 0; ng < 4; ng++)
                    #pragma unroll
                    for (int h = 0; h < 2; h++)
                        mma16816h(acc[mt][ng * 2 + h], ah[mt], bh[ng][h * 2], bh[ng][h * 2 + 1]);
        }
        __syncthreads();
    }

    #pragma unroll
    for (int mt = 0; mt < 2; mt++)
        #pragma unroll
        for (int nt = 0; nt < 8; nt++) {
            const int row0 = M0 + warpM * 32 + mt * 16 + (lane >> 2);
            const int col = N0 + warpN * 64 + nt * 8 + ((lane & 3) << 1);
            #pragma unroll
            for (int rr = 0; rr < 2; rr++) {
                const int r = row0 + rr * 8;
                float v0 = acc[mt][nt][rr * 2 + 0] * scale;
                float v1 = acc[mt][nt][rr * 2 + 1] * scale;
                if (BIASMODE == 1) { const float bb = bias[r]; v0 += bb; v1 += bb; }
                if (BIASMODE == 2) { v0 += bias[col]; v1 += bias[col + 1]; }
                const size_t off = (size_t)bz * strOut + (size_t)r * ldOut + col;
                if (DO_RES) { v0 += res[off]; v1 += res[off + 1]; }
                if (OUTMODE == 0) {
                    float2 o; o.x = v0; o.y = v1;
                    *(float2*)&OutF[off] = o;
                } else {
                    __half2 hp;
                    hp.x = __float2half_rn(v0);
                    hp.y = __float2half_rn(v1);
                    *(__half2*)&Oh[off] = hp;
                }
            }
        }
}

// ============================================================================
// Flash attention, max-free softmax, no split-K.
// grid: (NN/128, BB). 64 iters of 64 keys.
// S = Q.K^T (scale pre-folded into Q); per 16-key chunk: exp, li, pack, PV.
// Normalizes and writes Ot fp16 directly.
// ============================================================================
__global__ __launch_bounds__(256, 1)
void flash_kernel(const __half* __restrict__ QK, const __half* __restrict__ Vh,
                  __half* __restrict__ Ot) {
    extern __shared__ char smem[];
    const uint32_t sb = smem_u32(smem);
    const int tid = threadIdx.x;
    const int lane = tid & 31, wid = tid >> 5;
    const int b = blockIdx.y;
    const int n0 = blockIdx.x * 128;

    const __half* qh = QK + (size_t)b * NN * 512;
    const __half* kh = qh + 256;
    const __half* vh = Vh + (size_t)b * CC * NN;
    const size_t boN = (size_t)b * NN * CC;

    // Q load (once): rows have stride 512 in gmem
    for (int i = tid; i < 128 * 32; i += 256) {
        const int r = i >> 5, seg = i & 31;
        cpa16(sb + FQ0 + r * 528 + seg * 16, qh + (size_t)(n0 + r) * 512 + seg * 8);
    }
    CPA_COMMIT();

    const uint32_t fkb[2] = { sb + FK0, sb + FK1 };
    const uint32_t fvb[2] = { sb + FV0, sb + FV1 };

    #define LOAD_KV64(bufi, mm0) do {                                              \
        for (int i = tid; i < 2048; i += 256) {                                    \
            const int r_ = i >> 5, seg_ = i & 31;                                  \
            cpa16(fkb[bufi] + r_ * 528 + seg_ * 16,                                \
                  kh + (size_t)((mm0) + r_) * 512 + seg_ * 8);                     \
        }                                                                          \
        for (int i = tid; i < 2048; i += 256) {                                    \
            const int r_ = i >> 3, seg_ = i & 7;                                   \
            cpa16(fvb[bufi] + r_ * 144 + seg_ * 16,                                \
                  vh + (size_t)r_ * NN + (mm0) + seg_ * 8);                        \
        }                                                                          \
        CPA_COMMIT();                                                              \
    } while (0)

    LOAD_KV64(0, 0);

    const int ga = lane >> 3;
    const int arow = ((ga & 1) << 3) + (lane & 7);
    const int akoff = (ga >> 1) << 3;
    const int brow = ((ga >> 1) << 3) + (lane & 7);
    const int bkoff = (ga & 1) << 3;

    float o[32][4];
    #pragma unroll
    for (int i = 0; i < 32; i++)
        #pragma unroll
        for (int j = 0; j < 4; j++) o[i][j] = 0.f;
    float li0 = 0.f, li1 = 0.f;

    const uint32_t qbase = sb + FQ0 + (uint32_t)((wid * 16 + arow) * FQ_STRIDE + akoff) * 2;

    for (int it = 0; it < 64; it++) {
        const int buf = it & 1;
        if (it + 1 < 64) {
            LOAD_KV64((it + 1) & 1, (it + 1) * 64);
            CPA_WAIT1();
        } else {
            CPA_WAIT0();
        }
        __syncthreads();

        // ---- S = Q . K^T : 16 rows x 64 keys per warp (scale pre-folded) ----
        float s[8][4];
        #pragma unroll
        for (int t = 0; t < 8; t++)
            #pragma unroll
            for (int e = 0; e < 4; e++) s[t][e] = 0.f;

        #pragma unroll
        for (int ks = 0; ks < 256; ks += 16) {
            uint32_t qf[4];
            ldm4(qf, qbase + ks * 2);
            uint32_t kf[4][4];
            #pragma unroll
            for (int g = 0; g < 4; g++)
                ldm4(kf[g], fkb[buf] + (uint32_t)((g * 16 + brow) * FQ_STRIDE + ks + bkoff) * 2);
            #pragma unroll
            for (int g = 0; g < 4; g++)
                #pragma unroll
                for (int h = 0; h < 2; h++)
                    mma16816h(s[g * 2 + h], qf, kf[g][h * 2], kf[g][h * 2 + 1]);
        }

        // ---- per 16-key chunk: exp (max-free), li, P pack, PV ----
        #pragma unroll
        for (int kt = 0; kt < 4; kt++) {
            const int t0 = kt * 2, t1 = t0 + 1;
            const float e00 = __expf(s[t0][0]);
            const float e01 = __expf(s[t0][1]);
            const float e02 = __expf(s[t0][2]);
            const float e03 = __expf(s[t0][3]);
            const float e10 = __expf(s[t1][0]);
            const float e11 = __expf(s[t1][1]);
            const float e12 = __expf(s[t1][2]);
            const float e13 = __expf(s[t1][3]);
            li0 += e00 + e01 + e10 + e11;
            li1 += e02 + e03 + e12 + e13;
            uint32_t pah[4];
            pah[0] = pack_h2(e00, e01);
            pah[1] = pack_h2(e02, e03);
            pah[2] = pack_h2(e10, e11);
            pah[3] = pack_h2(e12, e13);
            #pragma unroll
            for (int cg = 0; cg < 16; cg++) {
                uint32_t vf[4];
                ldm4(vf, fvb[buf] + (uint32_t)((cg * 16 + brow) * FV_STRIDE + bkoff) * 2 + kt * 32);
                #pragma unroll
                for (int h = 0; h < 2; h++)
                    mma16816h(o[cg * 2 + h], pah, vf[h * 2], vf[h * 2 + 1]);
            }
        }
        __syncthreads();
    }

    // quad-reduce l, normalize, write Ot fp16
    li0 += __shfl_xor_sync(0xffffffffu, li0, 1);
    li0 += __shfl_xor_sync(0xffffffffu, li0, 2);
    li1 += __shfl_xor_sync(0xffffffffu, li1, 1);
    li1 += __shfl_xor_sync(0xffffffffu, li1, 2);
    const float inv0 = 1.f / li0;
    const float inv1 = 1.f / li1;

    const int r0 = n0 + wid * 16 + (lane >> 2);
    #pragma unroll
    for (int ct = 0; ct < 32; ct++) {
        const int col = ct * 8 + ((lane & 3) << 1);
        __half2 a0, a1;
        a0.x = __float2half_rn(o[ct][0] * inv0);
        a0.y = __float2half_rn(o[ct][1] * inv0);
        a1.x = __float2half_rn(o[ct][2] * inv1);
        a1.y = __float2half_rn(o[ct][3] * inv1);
        *(__half2*)&Ot[boN + (size_t)r0 * CC + col] = a0;
        *(__half2*)&Ot[boN + (size_t)(r0 + 8) * CC + col] = a1;
    }
}

// ---------------- launch ----------------
extern "C" void kernel_launch(void* const* d_in, const int* in_sizes, int n_in,
                              void* d_out, int out_size) {
    const float* input = (const float*)d_in[0];
    const float* gns   = (const float*)d_in[1];
    const float* gnb   = (const float*)d_in[2];
    const float* Wq    = (const float*)d_in[3];
    const float* bq    = (const float*)d_in[4];
    const float* Wk    = (const float*)d_in[5];
    const float* bk    = (const float*)d_in[6];
    const float* Wv    = (const float*)d_in[7];
    const float* bv    = (const float*)d_in[8];
    const float* Wo    = (const float*)d_in[9];
    const float* bo    = (const float*)d_in[10];
    float* out = (float*)d_out;

    __half *hth, *wqk, *wv, *wo, *qk16, *v16, *ot16;
    float* bqk;
    cudaGetSymbolAddress((void**)&hth, g_ht);
    cudaGetSymbolAddress((void**)&wqk, g_wqk);
    cudaGetSymbolAddress((void**)&wv, g_wv);
    cudaGetSymbolAddress((void**)&wo, g_wo);
    cudaGetSymbolAddress((void**)&bqk, g_bqk);
    cudaGetSymbolAddress((void**)&qk16, g_qk16);
    cudaGetSymbolAddress((void**)&v16, g_v16);
    cudaGetSymbolAddress((void**)&ot16, g_ot16);

    cudaFuncSetAttribute(gemm1h_kernel<1, 2, false>, cudaFuncAttributeMaxDynamicSharedMemorySize, GEMM_SMEM);
    cudaFuncSetAttribute(gemm1h_kernel<1, 1, false>, cudaFuncAttributeMaxDynamicSharedMemorySize, GEMM_SMEM);
    cudaFuncSetAttribute(gemm1h_kernel<0, 1, true>, cudaFuncAttributeMaxDynamicSharedMemorySize, GEMM_SMEM);
    cudaFuncSetAttribute(flash_kernel, cudaFuncAttributeMaxDynamicSharedMemorySize, FLASH_SMEM);

    // 1) GroupNorm stats + all weight converts (one kernel)
    gnstat1_kernel<<<dim3(16, 32), 256>>>(input);
    wsplitall_kernel<<<256, 256>>>(Wq, Wk, Wv, Wo, bq, bk);
    gnstat2_kernel<<<1, 32>>>();

    // 2) fused GN-apply + transpose -> fp16
    dim3 gt(NN / 32, CC / 32, BB);
    tconv_kernel<<<gt, dim3(32, 8)>>>(input, gns, gnb, hth);

    // 3) QK merged projection: qk[b][n][512] = hT . [Wq*s;Wk]^T + [bq*s;bk]
    dim3 gqk(2 * CC / 128, NN / 128, BB);
    gemm1h_kernel<1, 2, false><<<gqk, 256, GEMM_SMEM>>>(
        hth, wqk,
        CC, CC, (size_t)NN * CC, 0,
        nullptr, qk16, 2 * CC, (size_t)NN * 2 * CC, bqk, nullptr, CC, 1.0f);
    //    V projection: v[b][o][m]
    dim3 gv(NN / 128, CC / 128, BB);
    gemm1h_kernel<1, 1, false><<<gv, 256, GEMM_SMEM>>>(
        wv, hth,
        CC, CC, 0, (size_t)NN * CC,
        nullptr, v16, NN, (size_t)CC * NN, bv, nullptr, CC, 1.0f);

    // 4) flash attention -> Ot fp16 (normalized in-kernel)
    dim3 gfl(NN / 128, BB);
    flash_kernel<<<gfl, 256, FLASH_SMEM>>>(qk16, v16, ot16);

    // 5) final: out = Wo . Ot^T + bo + residual (fp32 out)
    dim3 gf(NN / 128, CC / 128, BB);
    gemm1h_kernel<0, 1, true><<<gf, 256, GEMM_SMEM>>>(
        wo, ot16,
        CC, CC, 0, (size_t)NN * CC,
        out, nullptr, NN, (size_t)CC * NN, bo, input, CC, 1.0f);
}

// round 14
// speedup vs baseline: 9.3741x; 1.0565x over previous
#include <cuda_runtime.h>
#include <cuda_fp16.h>
#include <math_constants.h>
#include <cstdint>

// Problem constants
#define BB 4
#define CC 256
#define NN 4096
#define NG 8
#define CPG 32
#define EPSV 1e-5f
#define ATTN_SCALE 0.0625f  // 1/sqrt(256), folded into Wq/bq

// 1-pass gemm smem geometry (2 tiles, double buffered)
#define GROW 40
#define MATB (128 * GROW * 2)     // 10240
#define BUF2 (2 * MATB)           // 20480
#define GEMM_SMEM (2 * BUF2)      // 40960

// flash smem geometry
#define FQ_STRIDE 264             // 528B rows (256 fp16 + pad)
#define FV_STRIDE 72              // 144B rows (64 fp16 + pad)
#define FQ0 0
#define FK0 67584                 // 128*528
#define FK1 (FK0 + 33792)         // 64*528
#define FV0 (FK1 + 33792)         // 135168
#define FV1 (FV0 + 36864)         // 256*144
#define FLASH_SMEM (FV1 + 36864)  // 208896

// ---------------- static scratch ----------------
__device__ __align__(16) float g_part[512 * 2];              // GN partial sums
__device__ float g_mean[BB * NG];
__device__ float g_inv[BB * NG];
__device__ __align__(16) __half g_ht[BB * NN * CC];          // h^T [b][n][c] fp16
__device__ __align__(16) __half g_wqk[2 * CC * CC];          // concat(Wq*scale, Wk)
__device__ __align__(16) __half g_wv[CC * CC];
__device__ __align__(16) __half g_wo[CC * CC];
__device__ __align__(16) float g_bqk[2 * CC];                // concat(bq*scale, bk)
__device__ __align__(16) __half g_qk16[BB * NN * 2 * CC];    // qk^T [b][n][512]
__device__ __align__(16) __half g_v16[BB * CC * NN];         // v [b][o][m]
__device__ __align__(16) __half g_ot16[BB * NN * CC];        // Ot [b][n][c]

// ================= PTX helpers =================
__device__ __forceinline__ uint32_t smem_u32(const void* p) {
    uint32_t a;
    asm("{ .reg .u64 t; cvta.to.shared.u64 t, %1; cvt.u32.u64 %0, t; }" : "=r"(a) : "l"(p));
    return a;
}
__device__ __forceinline__ void ldm4(uint32_t r[4], uint32_t addr) {
    asm volatile("ldmatrix.sync.aligned.m8n8.x4.shared.b16 {%0,%1,%2,%3}, [%4];"
                 : "=r"(r[0]), "=r"(r[1]), "=r"(r[2]), "=r"(r[3]) : "r"(addr));
}
__device__ __forceinline__ void mma16816h(float c[4], const uint32_t a[4],
                                          uint32_t b0, uint32_t b1) {
    asm volatile("mma.sync.aligned.m16n8k16.row.col.f32.f16.f16.f32 "
                 "{%0,%1,%2,%3}, {%4,%5,%6,%7}, {%8,%9}, {%0,%1,%2,%3};"
                 : "+f"(c[0]), "+f"(c[1]), "+f"(c[2]), "+f"(c[3])
                 : "r"(a[0]), "r"(a[1]), "r"(a[2]), "r"(a[3]), "r"(b0), "r"(b1));
}
__device__ __forceinline__ void cpa16(uint32_t dst, const void* src) {
    asm volatile("cp.async.cg.shared.global [%0], [%1], 16;" :: "r"(dst), "l"(src));
}
#define CPA_COMMIT() asm volatile("cp.async.commit_group;" ::: "memory")
#define CPA_WAIT0()  asm volatile("cp.async.wait_group 0;" ::: "memory")
#define CPA_WAIT1()  asm volatile("cp.async.wait_group 1;" ::: "memory")

__device__ __forceinline__ uint32_t pack_h2(float a, float b) {
    __half2 h;
    h.x = __float2half_rn(a);
    h.y = __float2half_rn(b);
    return *(uint32_t*)&h;
}

// ---------------- GroupNorm stage 1 ----------------
__global__ void gnstat1_kernel(const float* __restrict__ x) {
    const int bg = blockIdx.y;
    const int chunk = blockIdx.x;
    const float* xp = x + (size_t)bg * (CPG * NN) + chunk * 8192;
    float s = 0.f, ss = 0.f;
    for (int i = threadIdx.x; i < 2048; i += 256) {
        float4 v = ((const float4*)xp)[i];
        s += v.x + v.y + v.z + v.w;
        ss += v.x * v.x + v.y * v.y + v.z * v.z + v.w * v.w;
    }
    __shared__ float rs[256], rq[256];
    rs[threadIdx.x] = s; rq[threadIdx.x] = ss;
    __syncthreads();
    for (int st = 128; st > 0; st >>= 1) {
        if (threadIdx.x < st) { rs[threadIdx.x] += rs[threadIdx.x + st]; rq[threadIdx.x] += rq[threadIdx.x + st]; }
        __syncthreads();
    }
    if (threadIdx.x == 0) {
        g_part[(bg * 16 + chunk) * 2 + 0] = rs[0];
        g_part[(bg * 16 + chunk) * 2 + 1] = rq[0];
    }
}

// ---------------- GroupNorm stage 2 ----------------
__global__ void gnstat2_kernel() {
    const int i = threadIdx.x;
    float s = 0.f, ss = 0.f;
    #pragma unroll
    for (int j = 0; j < 16; j++) {
        s += g_part[(i * 16 + j) * 2 + 0];
        ss += g_part[(i * 16 + j) * 2 + 1];
    }
    const float Mf = (float)(CPG * NN);
    const float mean = s / Mf;
    const float var = ss / Mf - mean * mean;
    g_mean[i] = mean;
    g_inv[i] = rsqrtf(var + EPSV);
}

// ---------------- all weight converts + bias concat (scale folded into Q) ----------------
__global__ void wsplitall_kernel(const float* __restrict__ Wq, const float* __restrict__ Wk,
                                 const float* __restrict__ Wv, const float* __restrict__ Wo,
                                 const float* __restrict__ bq, const float* __restrict__ bk) {
    const int i = blockIdx.x * blockDim.x + threadIdx.x;
    if (i < CC * CC) {
        g_wqk[i] = __float2half_rn(Wq[i] * ATTN_SCALE);
        g_wqk[CC * CC + i] = __float2half_rn(Wk[i]);
        g_wv[i] = __float2half_rn(Wv[i]);
        g_wo[i] = __float2half_rn(Wo[i]);
        if (i < CC) g_bqk[i] = bq[i] * ATTN_SCALE;
        else if (i < 2 * CC) g_bqk[i] = bk[i - CC];
    }
}

// ---------------- fused GN-apply + transpose + fp16 ----------------
__global__ void tconv_kernel(const float* __restrict__ x,
                             const float* __restrict__ sc,
                             const float* __restrict__ bi,
                             __half* __restrict__ dst) {
    __shared__ float t[32][33];
    const int b = blockIdx.z;
    const int n0 = blockIdx.x * 32;
    const int c0 = blockIdx.y * 32;
    const int tx = threadIdx.x, ty = threadIdx.y;  // (32, 8)
    const int bg = b * NG + blockIdx.y;
    const float mean = g_mean[bg];
    const float inv = g_inv[bg];
    const float* s = x + (size_t)b * CC * NN;
    #pragma unroll
    for (int k = 0; k < 4; k++)
        t[ty + 8 * k][tx] = s[(size_t)(c0 + ty + 8 * k) * NN + n0 + tx];
    __syncthreads();
    const int c = c0 + tx;
    const float a = inv * sc[c];
    const float d = bi[c] - mean * a;
    const size_t base = (size_t)b * NN * CC;
    #pragma unroll
    for (int k = 0; k < 4; k++) {
        const int n = n0 + ty + 8 * k;
        dst[base + (size_t)n * CC + c] = __float2half_rn(t[tx][ty + 8 * k] * a + d);
    }
}

// ============================================================================
// 1-pass fp16 GEMM (unchanged from R13)
// ============================================================================
template<int OUTMODE, int BIASMODE, bool DO_RES>
__global__ __launch_bounds__(256, 1)
void gemm1h_kernel(const __half* __restrict__ Ah, const __half* __restrict__ Bh,
                   size_t ldA, size_t ldB, size_t strA, size_t strB,
                   float* __restrict__ OutF, __half* __restrict__ Oh,
                   size_t ldOut, size_t strOut,
                   const float* __restrict__ bias, const float* __restrict__ res,
                   int K, float scale) {
    extern __shared__ char smem[];
    const uint32_t sb = smem_u32(smem);
    const int tid = threadIdx.x;
    const int lane = tid & 31, wid = tid >> 5;
    const int warpM = wid & 3, warpN = wid >> 2;
    const int bz = blockIdx.z;
    const int N0 = blockIdx.x * 128;
    const int M0 = blockIdx.y * 128;

    const __half* pA = Ah + (size_t)bz * strA + (size_t)M0 * ldA;
    const __half* pB = Bh + (size_t)bz * strB + (size_t)N0 * ldB;

    const int ga = lane >> 3;
    const int arow = ((ga & 1) << 3) + (lane & 7);
    const int akoff = (ga >> 1) << 3;
    const int brow = ((ga >> 1) << 3) + (lane & 7);
    const int bkoff = (ga & 1) << 3;

    float acc[2][8][4];
    #pragma unroll
    for (int i = 0; i < 2; i++)
        #pragma unroll
        for (int j = 0; j < 8; j++)
            #pragma unroll
            for (int k = 0; k < 4; k++) acc[i][j][k] = 0.f;

    const int nch = K >> 5;

    #define ISSUE_COPY2(bufi, kc) do {                                             \
        _Pragma("unroll")                                                          \
        for (int i_ = 0; i_ < 4; i_++) {                                           \
            int idx_ = tid + i_ * 256;                                             \
            int mat_ = idx_ >> 9;                                                  \
            int r_ = (idx_ >> 2) & 127;                                            \
            int seg_ = idx_ & 3;                                                   \
            const __half* src_ = (mat_ ? pB + (size_t)r_ * ldB : pA + (size_t)r_ * ldA) \
                                 + (kc) + seg_ * 8;                                \
            uint32_t dst_ = sb + (bufi) * BUF2 + mat_ * MATB + (r_ * GROW + seg_ * 8) * 2; \
            cpa16(dst_, src_);                                                     \
        }                                                                          \
        CPA_COMMIT();                                                              \
    } while (0)

    ISSUE_COPY2(0, 0);

    for (int c = 0; c < nch; c++) {
        if (c + 1 < nch) {
            ISSUE_COPY2((c + 1) & 1, (c + 1) << 5);
            CPA_WAIT1();
        } else {
            CPA_WAIT0();
        }
        __syncthreads();

        const uint32_t bufb = sb + (c & 1) * BUF2;
        #pragma unroll
        for (int ks = 0; ks < 32; ks += 16) {
            uint32_t ah[2][4];
            #pragma unroll
            for (int mt = 0; mt < 2; mt++) {
                uint32_t off = (uint32_t)(((warpM * 32 + mt * 16 + arow) * GROW + ks + akoff) * 2);
                ldm4(ah[mt], bufb + off);
            }
            uint32_t bh[4][4];
            #pragma unroll
            for (int ng = 0; ng < 4; ng++) {
                uint32_t off = (uint32_t)(((warpN * 64 + ng * 16 + brow) * GROW + ks + bkoff) * 2);
                ldm4(bh[ng], bufb + MATB + off);
            }
            #pragma unroll
            for (int mt = 0; mt < 2; mt++)
                #pragma unroll
                for (int ng = 0; ng < 4; ng++)
                    #pragma unroll
                    for (int h = 0; h < 2; h++)
                        mma16816h(acc[mt][ng * 2 + h], ah[mt], bh[ng][h * 2], bh[ng][h * 2 + 1]);
        }
        __syncthreads();
    }

    #pragma unroll
    for (int mt = 0; mt < 2; mt++)
        #pragma unroll
        for (int nt = 0; nt < 8; nt++) {
            const int row0 = M0 + warpM * 32 + mt * 16 + (lane >> 2);
            const int col = N0 + warpN * 64 + nt * 8 + ((lane & 3) << 1);
            #pragma unroll
            for (int rr = 0; rr < 2; rr++) {
                const int r = row0 + rr * 8;
                float v0 = acc[mt][nt][rr * 2 + 0] * scale;
                float v1 = acc[mt][nt][rr * 2 + 1] * scale;
                if (BIASMODE == 1) { const float bb = bias[r]; v0 += bb; v1 += bb; }
                if (BIASMODE == 2) { v0 += bias[col]; v1 += bias[col + 1]; }
                const size_t off = (size_t)bz * strOut + (size_t)r * ldOut + col;
                if (DO_RES) { v0 += res[off]; v1 += res[off + 1]; }
                if (OUTMODE == 0) {
                    float2 o; o.x = v0; o.y = v1;
                    *(float2*)&OutF[off] = o;
                } else {
                    __half2 hp;
                    hp.x = __float2half_rn(v0);
                    hp.y = __float2half_rn(v1);
                    *(__half2*)&Oh[off] = hp;
                }
            }
        }
}

// ============================================================================
// Flash attention, software-pipelined S:
//   body(it): [exp/pack + PV(it)] interleaved with [S(it+1)] per 16-key chunk.
// K consumed one stage before V; both double-buffered. One sync per body.
// Max-free softmax (scale pre-folded into Q).
// ============================================================================
__global__ __launch_bounds__(256, 1)
void flash_kernel(const __half* __restrict__ QK, const __half* __restrict__ Vh,
                  __half* __restrict__ Ot) {
    extern __shared__ char smem[];
    const uint32_t sb = smem_u32(smem);
    const int tid = threadIdx.x;
    const int lane = tid & 31, wid = tid >> 5;
    const int b = blockIdx.y;
    const int n0 = blockIdx.x * 128;

    const __half* qh = QK + (size_t)b * NN * 512;
    const __half* kh = qh + 256;
    const __half* vh = Vh + (size_t)b * CC * NN;
    const size_t boN = (size_t)b * NN * CC;

    const uint32_t fkb[2] = { sb + FK0, sb + FK1 };
    const uint32_t fvb[2] = { sb + FV0, sb + FV1 };

    // K tile load: 64 rows x 256c  (8 cpa16/thread)
    #define LOAD_K(bufi, mm0) do {                                                 \
        for (int i = tid; i < 2048; i += 256) {                                    \
            const int r_ = i >> 5, seg_ = i & 31;                                  \
            cpa16(fkb[bufi] + r_ * 528 + seg_ * 16,                                \
                  kh + (size_t)((mm0) + r_) * 512 + seg_ * 8);                     \
        }                                                                          \
    } while (0)
    // V tile load: 256 rows x 64m  (8 cpa16/thread)
    #define LOAD_V(bufi, mm0) do {                                                 \
        for (int i = tid; i < 2048; i += 256) {                                    \
            const int r_ = i >> 3, seg_ = i & 7;                                   \
            cpa16(fvb[bufi] + r_ * 144 + seg_ * 16,                                \
                  vh + (size_t)r_ * NN + (mm0) + seg_ * 8);                        \
        }                                                                          \
    } while (0)

    // prologue group 0: Q + K(0)
    for (int i = tid; i < 128 * 32; i += 256) {
        const int r = i >> 5, seg = i & 31;
        cpa16(sb + FQ0 + r * 528 + seg * 16, qh + (size_t)(n0 + r) * 512 + seg * 8);
    }
    LOAD_K(0, 0);
    CPA_COMMIT();
    // prologue group 1: K(1) + V(0)
    LOAD_K(1, 64);
    LOAD_V(0, 0);
    CPA_COMMIT();

    const int ga = lane >> 3;
    const int arow = ((ga & 1) << 3) + (lane & 7);
    const int akoff = (ga >> 1) << 3;
    const int brow = ((ga >> 1) << 3) + (lane & 7);
    const int bkoff = (ga & 1) << 3;

    float o[32][4];
    #pragma unroll
    for (int i = 0; i < 32; i++)
        #pragma unroll
        for (int j = 0; j < 4; j++) o[i][j] = 0.f;
    float li0 = 0.f, li1 = 0.f;
    float sa[8][4], sbuf[8][4];

    const uint32_t qbase = sb + FQ0 + (uint32_t)((wid * 16 + arow) * FQ_STRIDE + akoff) * 2;

    CPA_WAIT0();
    __syncthreads();

    // ---- prologue: S(0) into sa (reads Kbuf[0]) ----
    #pragma unroll
    for (int t = 0; t < 8; t++)
        #pragma unroll
        for (int e = 0; e < 4; e++) sa[t][e] = 0.f;
    #pragma unroll
    for (int ks = 0; ks < 256; ks += 16) {
        uint32_t qf[4];
        ldm4(qf, qbase + ks * 2);
        #pragma unroll
        for (int g = 0; g < 4; g++) {
            uint32_t kf[4];
            ldm4(kf, fkb[0] + (uint32_t)((g * 16 + brow) * FQ_STRIDE + ks + bkoff) * 2);
            mma16816h(sa[g * 2 + 0], qf, kf[0], kf[1]);
            mma16816h(sa[g * 2 + 1], qf, kf[2], kf[3]);
        }
    }

    // body: PV(it) from scur + optionally S(it+1) into snxt
    #define FLASH_BODY(scur, snxt, it, DO_S) do {                                  \
        CPA_WAIT0();                                                               \
        __syncthreads();                                                           \
        if ((it) + 2 < 64) LOAD_K((it) & 1, ((it) + 2) * 64);                      \
        if ((it) + 1 < 64) LOAD_V(((it) + 1) & 1, ((it) + 1) * 64);                \
        CPA_COMMIT();                                                              \
        const uint32_t vbase_ = fvb[(it) & 1];                                     \
        const uint32_t kbase_ = fkb[((it) + 1) & 1];                               \
        if (DO_S) {                                                                \
            _Pragma("unroll")                                                      \
            for (int t_ = 0; t_ < 8; t_++)                                         \
                _Pragma("unroll")                                                  \
                for (int e_ = 0; e_ < 4; e_++) snxt[t_][e_] = 0.f;                 \
        }                                                                          \
        _Pragma("unroll")                                                          \
        for (int kt = 0; kt < 4; kt++) {                                           \
            const int t0_ = kt * 2, t1_ = t0_ + 1;                                 \
            const float e00 = __expf(scur[t0_][0]);                                \
            const float e01 = __expf(scur[t0_][1]);                                \
            const float e02 = __expf(scur[t0_][2]);                                \
            const float e03 = __expf(scur[t0_][3]);                                \
            const float e10 = __expf(scur[t1_][0]);                                \
            const float e11 = __expf(scur[t1_][1]);                                \
            const float e12 = __expf(scur[t1_][2]);                                \
            const float e13 = __expf(scur[t1_][3]);                                \
            li0 += e00 + e01 + e10 + e11;                                          \
            li1 += e02 + e03 + e12 + e13;                                          \
            uint32_t pah[4];                                                       \
            pah[0] = pack_h2(e00, e01);                                            \
            pah[1] = pack_h2(e02, e03);                                            \
            pah[2] = pack_h2(e10, e11);                                            \
            pah[3] = pack_h2(e12, e13);                                            \
            _Pragma("unroll")                                                      \
            for (int cg = 0; cg < 16; cg++) {                                      \
                uint32_t vf[4];                                                    \
                ldm4(vf, vbase_ + (uint32_t)((cg * 16 + brow) * FV_STRIDE + bkoff) * 2 + kt * 32); \
                mma16816h(o[cg * 2 + 0], pah, vf[0], vf[1]);                       \
                mma16816h(o[cg * 2 + 1], pah, vf[2], vf[3]);                       \
            }                                                                      \
            if (DO_S) {                                                            \
                _Pragma("unroll")                                                  \
                for (int ks2 = 0; ks2 < 4; ks2++) {                                \
                    const int ks_ = (kt * 4 + ks2) * 16;                           \
                    uint32_t qf[4];                                                \
                    ldm4(qf, qbase + ks_ * 2);                                     \
                    _Pragma("unroll")                                              \
                    for (int g_ = 0; g_ < 4; g_++) {                               \
                        uint32_t kf[4];                                            \
                        ldm4(kf, kbase_ + (uint32_t)((g_ * 16 + brow) * FQ_STRIDE + ks_ + bkoff) * 2); \
                        mma16816h(snxt[g_ * 2 + 0], qf, kf[0], kf[1]);             \
                        mma16816h(snxt[g_ * 2 + 1], qf, kf[2], kf[3]);             \
                    }                                                              \
                }                                                                  \
            }                                                                      \
        }                                                                          \
    } while (0)

    #pragma unroll 1
    for (int it2 = 0; it2 < 62; it2 += 2) {
        FLASH_BODY(sa, sbuf, it2, true);
        FLASH_BODY(sbuf, sa, it2 + 1, true);
    }
    FLASH_BODY(sa, sbuf, 62, true);      // PV(62), S(63) -> sbuf
    FLASH_BODY(sbuf, sa, 63, false);     // PV(63) only

    // quad-reduce l, normalize, write Ot fp16
    li0 += __shfl_xor_sync(0xffffffffu, li0, 1);
    li0 += __shfl_xor_sync(0xffffffffu, li0, 2);
    li1 += __shfl_xor_sync(0xffffffffu, li1, 1);
    li1 += __shfl_xor_sync(0xffffffffu, li1, 2);
    const float inv0 = 1.f / li0;
    const float inv1 = 1.f / li1;

    const int r0 = n0 + wid * 16 + (lane >> 2);
    #pragma unroll
    for (int ct = 0; ct < 32; ct++) {
        const int col = ct * 8 + ((lane & 3) << 1);
        __half2 a0, a1;
        a0.x = __float2half_rn(o[ct][0] * inv0);
        a0.y = __float2half_rn(o[ct][1] * inv0);
        a1.x = __float2half_rn(o[ct][2] * inv1);
        a1.y = __float2half_rn(o[ct][3] * inv1);
        *(__half2*)&Ot[boN + (size_t)r0 * CC + col] = a0;
        *(__half2*)&Ot[boN + (size_t)(r0 + 8) * CC + col] = a1;
    }
}

// ---------------- launch ----------------
extern "C" void kernel_launch(void* const* d_in, const int* in_sizes, int n_in,
                              void* d_out, int out_size) {
    const float* input = (const float*)d_in[0];
    const float* gns   = (const float*)d_in[1];
    const float* gnb   = (const float*)d_in[2];
    const float* Wq    = (const float*)d_in[3];
    const float* bq    = (const float*)d_in[4];
    const float* Wk    = (const float*)d_in[5];
    const float* bk    = (const float*)d_in[6];
    const float* Wv    = (const float*)d_in[7];
    const float* bv    = (const float*)d_in[8];
    const float* Wo    = (const float*)d_in[9];
    const float* bo    = (const float*)d_in[10];
    float* out = (float*)d_out;

    __half *hth, *wqk, *wv, *wo, *qk16, *v16, *ot16;
    float* bqk;
    cudaGetSymbolAddress((void**)&hth, g_ht);
    cudaGetSymbolAddress((void**)&wqk, g_wqk);
    cudaGetSymbolAddress((void**)&wv, g_wv);
    cudaGetSymbolAddress((void**)&wo, g_wo);
    cudaGetSymbolAddress((void**)&bqk, g_bqk);
    cudaGetSymbolAddress((void**)&qk16, g_qk16);
    cudaGetSymbolAddress((void**)&v16, g_v16);
    cudaGetSymbolAddress((void**)&ot16, g_ot16);

    cudaFuncSetAttribute(gemm1h_kernel<1, 2, false>, cudaFuncAttributeMaxDynamicSharedMemorySize, GEMM_SMEM);
    cudaFuncSetAttribute(gemm1h_kernel<1, 1, false>, cudaFuncAttributeMaxDynamicSharedMemorySize, GEMM_SMEM);
    cudaFuncSetAttribute(gemm1h_kernel<0, 1, true>, cudaFuncAttributeMaxDynamicSharedMemorySize, GEMM_SMEM);
    cudaFuncSetAttribute(flash_kernel, cudaFuncAttributeMaxDynamicSharedMemorySize, FLASH_SMEM);

    // 1) GroupNorm stats + all weight converts (one kernel)
    gnstat1_kernel<<<dim3(16, 32), 256>>>(input);
    wsplitall_kernel<<<256, 256>>>(Wq, Wk, Wv, Wo, bq, bk);
    gnstat2_kernel<<<1, 32>>>();

    // 2) fused GN-apply + transpose -> fp16
    dim3 gt(NN / 32, CC / 32, BB);
    tconv_kernel<<<gt, dim3(32, 8)>>>(input, gns, gnb, hth);

    // 3) QK merged projection: qk[b][n][512] = hT . [Wq*s;Wk]^T + [bq*s;bk]
    dim3 gqk(2 * CC / 128, NN / 128, BB);
    gemm1h_kernel<1, 2, false><<<gqk, 256, GEMM_SMEM>>>(
        hth, wqk,
        CC, CC, (size_t)NN * CC, 0,
        nullptr, qk16, 2 * CC, (size_t)NN * 2 * CC, bqk, nullptr, CC, 1.0f);
    //    V projection: v[b][o][m]
    dim3 gv(NN / 128, CC / 128, BB);
    gemm1h_kernel<1, 1, false><<<gv, 256, GEMM_SMEM>>>(
        wv, hth,
        CC, CC, 0, (size_t)NN * CC,
        nullptr, v16, NN, (size_t)CC * NN, bv, nullptr, CC, 1.0f);

    // 4) flash attention (pipelined) -> Ot fp16
    dim3 gfl(NN / 128, BB);
    flash_kernel<<<gfl, 256, FLASH_SMEM>>>(qk16, v16, ot16);

    // 5) final: out = Wo . Ot^T + bo + residual (fp32 out)
    dim3 gf(NN / 128, CC / 128, BB);
    gemm1h_kernel<0, 1, true><<<gf, 256, GEMM_SMEM>>>(
        wo, ot16,
        CC, CC, 0, (size_t)NN * CC,
        out, nullptr, NN, (size_t)CC * NN, bo, input, CC, 1.0f);
}